// round 1
// baseline (speedup 1.0000x reference)
#include <cuda_runtime.h>
#include <math.h>

#define NNODES 50000
#define NEDGES 800000
#define NBATCH 32
#define NV 20
#define NVOC 4000
#define NREL 200
#define NH 128
#define NL 3
#define NOUT 100

// ---------------- device scratch (allocation-free rule: __device__ globals) ----
__device__ float g_Z[(size_t)NBATCH * NV * NVOC];        // alpha logits scratch (one layer)
__device__ float g_Enode[NVOC * NH];
__device__ float g_Erel[NREL * NH];
__device__ float g_wrel[NL * NREL];
__device__ float g_attn[(size_t)NL * NBATCH * NVOC];
__device__ float g_beta[NL * NBATCH * NV];
__device__ float g_x[(size_t)NNODES * NH];
__device__ float g_x2[(size_t)NNODES * NH];
__device__ float g_agg[(size_t)NNODES * NH];
__device__ int   g_deg[NNODES];
__device__ int   g_rowstart[NNODES + 1];
__device__ int   g_cursor[NNODES];
__device__ int   g_elist[NEDGES];
__device__ int   g_part[64];
__device__ int   g_bcnt[NBATCH];
__device__ int   g_bstart[NBATCH + 1];
__device__ float g_xg[NBATCH * NH];
__device__ float g_xnode[NBATCH * NH];

// ---------------- generic NT GEMM: C[M,N] = op(sum_k A[m,k]*B[n,k] + bias[n]) --
// A row-major [M,K] (k contiguous), B row-major [N,K] (k contiguous).
// ADD2: A is (A + A2) elementwise. RELU: relu epilogue. Requires K%16==0, N%4==0.
#define GBM 128
#define GBN 64
#define GBK 16

template <bool RELU, bool ADD2>
__global__ __launch_bounds__(256, 2) void gemm_nt(
    const float* __restrict__ A, const float* __restrict__ A2,
    const float* __restrict__ B, const float* __restrict__ bias,
    float* __restrict__ C, int M, int N, int K)
{
    __shared__ float As[GBK][GBM];
    __shared__ float Bs[GBK][GBN];

    int tid = threadIdx.x;
    int m0 = blockIdx.y * GBM;
    int n0 = blockIdx.x * GBN;
    int ty = tid >> 4;          // 0..15 (rows, x8)
    int tx = tid & 15;          // 0..15 (cols, x4)

    // A tile load mapping: 128 rows x 16 k; 2 float4 per thread
    int arow = tid >> 1;
    int ak   = (tid & 1) * 8;
    // B tile load mapping: 64 rows x 16 k; 1 float4 per thread
    int brow = tid >> 2;
    int bk   = (tid & 3) * 4;

    float acc[8][4];
#pragma unroll
    for (int i = 0; i < 8; i++)
#pragma unroll
        for (int j = 0; j < 4; j++) acc[i][j] = 0.f;

    int agrow = m0 + arow;
    int bgrow = n0 + brow;
    bool aval = agrow < M;
    bool bval = bgrow < N;
    const float* Aptr  = A + (size_t)agrow * K + ak;
    const float* A2ptr = ADD2 ? (A2 + (size_t)agrow * K + ak) : A;
    const float* Bptr  = B + (size_t)bgrow * K + bk;

    for (int k0 = 0; k0 < K; k0 += GBK) {
        float4 a0 = {0, 0, 0, 0}, a1 = {0, 0, 0, 0}, b0 = {0, 0, 0, 0};
        if (aval) {
            a0 = *(const float4*)(Aptr + k0);
            a1 = *(const float4*)(Aptr + k0 + 4);
            if (ADD2) {
                float4 c0 = *(const float4*)(A2ptr + k0);
                float4 c1 = *(const float4*)(A2ptr + k0 + 4);
                a0.x += c0.x; a0.y += c0.y; a0.z += c0.z; a0.w += c0.w;
                a1.x += c1.x; a1.y += c1.y; a1.z += c1.z; a1.w += c1.w;
            }
        }
        if (bval) b0 = *(const float4*)(Bptr + k0);

        __syncthreads();
        As[ak + 0][arow] = a0.x; As[ak + 1][arow] = a0.y;
        As[ak + 2][arow] = a0.z; As[ak + 3][arow] = a0.w;
        As[ak + 4][arow] = a1.x; As[ak + 5][arow] = a1.y;
        As[ak + 6][arow] = a1.z; As[ak + 7][arow] = a1.w;
        Bs[bk + 0][brow] = b0.x; Bs[bk + 1][brow] = b0.y;
        Bs[bk + 2][brow] = b0.z; Bs[bk + 3][brow] = b0.w;
        __syncthreads();

#pragma unroll
        for (int k = 0; k < GBK; k++) {
            float4 av0 = *(const float4*)&As[k][ty * 8];
            float4 av1 = *(const float4*)&As[k][ty * 8 + 4];
            float4 bv  = *(const float4*)&Bs[k][tx * 4];
            float a[8] = {av0.x, av0.y, av0.z, av0.w, av1.x, av1.y, av1.z, av1.w};
            float b[4] = {bv.x, bv.y, bv.z, bv.w};
#pragma unroll
            for (int i = 0; i < 8; i++)
#pragma unroll
                for (int j = 0; j < 4; j++) acc[i][j] = fmaf(a[i], b[j], acc[i][j]);
        }
    }

    int c0 = n0 + tx * 4;
    if (c0 < N) {
        float bb0 = bias[c0], bb1 = bias[c0 + 1], bb2 = bias[c0 + 2], bb3 = bias[c0 + 3];
#pragma unroll
        for (int i = 0; i < 8; i++) {
            int r = m0 + ty * 8 + i;
            if (r < M) {
                float4 o;
                o.x = acc[i][0] + bb0; o.y = acc[i][1] + bb1;
                o.z = acc[i][2] + bb2; o.w = acc[i][3] + bb3;
                if (RELU) {
                    o.x = fmaxf(o.x, 0.f); o.y = fmaxf(o.y, 0.f);
                    o.z = fmaxf(o.z, 0.f); o.w = fmaxf(o.w, 0.f);
                }
                *(float4*)(C + (size_t)r * N + c0) = o;
            }
        }
    }
}

// ---------------- small kernels ------------------------------------------------
__global__ void k_zero_int(int* __restrict__ p, int n) {
    int i = blockIdx.x * blockDim.x + threadIdx.x;
    if (i < n) p[i] = 0;
}

__global__ void k_hist(const int* __restrict__ keys, int* __restrict__ cnt, int n) {
    int i = blockIdx.x * blockDim.x + threadIdx.x;
    if (i < n) atomicAdd(&cnt[keys[i]], 1);
}

__global__ void k_hist_batch(const int* __restrict__ batch, int* __restrict__ bcnt) {
    __shared__ int h[NBATCH];
    if (threadIdx.x < NBATCH) h[threadIdx.x] = 0;
    __syncthreads();
    int i = blockIdx.x * blockDim.x + threadIdx.x;
    if (i < NNODES) atomicAdd(&h[batch[i]], 1);
    __syncthreads();
    if (threadIdx.x < NBATCH) atomicAdd(&bcnt[threadIdx.x], h[threadIdx.x]);
}

__global__ void k_scan_block(const int* __restrict__ in, int* __restrict__ outEx,
                             int* __restrict__ part, int n) {
    __shared__ int s[1024];
    int t = threadIdx.x;
    int i = blockIdx.x * 1024 + t;
    int v = (i < n) ? in[i] : 0;
    s[t] = v;
    __syncthreads();
    for (int off = 1; off < 1024; off <<= 1) {
        int y = (t >= off) ? s[t - off] : 0;
        __syncthreads();
        s[t] += y;
        __syncthreads();
    }
    if (i < n) outEx[i] = s[t] - v;
    if (t == 1023) part[blockIdx.x] = s[1023];
}

__global__ void k_scan_part(int* __restrict__ part, int nb, int* __restrict__ rowstart) {
    if (threadIdx.x == 0 && blockIdx.x == 0) {
        int acc = 0;
        for (int i = 0; i < nb; i++) { int v = part[i]; part[i] = acc; acc += v; }
        rowstart[NNODES] = NEDGES;
    }
}

__global__ void k_scan_add(int* __restrict__ rowstart, const int* __restrict__ part,
                           int* __restrict__ cursor, int n) {
    int i = blockIdx.x * 1024 + threadIdx.x;
    if (i < n) {
        int v = rowstart[i] + part[blockIdx.x];
        rowstart[i] = v;
        cursor[i] = v;
    }
}

__global__ void k_scatter(const int* __restrict__ dst, int* __restrict__ cursor,
                          int* __restrict__ elist, int n) {
    int e = blockIdx.x * blockDim.x + threadIdx.x;
    if (e < n) {
        int d = dst[e];
        int p = atomicAdd(&cursor[d], 1);
        elist[p] = e;
    }
}

__global__ void k_bscan(const int* __restrict__ bcnt, int* __restrict__ bstart) {
    if (threadIdx.x == 0 && blockIdx.x == 0) {
        int acc = 0;
        for (int b = 0; b < NBATCH; b++) { bstart[b] = acc; acc += bcnt[b]; }
        bstart[NBATCH] = acc;
    }
}

// w_rel table: wrel[l][r] = dot(Erel[r], wr_w[l]) + wr_b[l]
__global__ void k_wrel(const float* __restrict__ Erel, const float* __restrict__ wr_w,
                       const float* __restrict__ wr_b, float* __restrict__ wrel) {
    int w = (blockIdx.x * blockDim.x + threadIdx.x) >> 5;
    int lane = threadIdx.x & 31;
    if (w >= NL * NREL) return;
    int l = w / NREL, r = w % NREL;
    float acc = 0.f;
#pragma unroll
    for (int h = lane; h < NH; h += 32) acc += Erel[r * NH + h] * wr_w[l * NH + h];
#pragma unroll
    for (int o = 16; o; o >>= 1) acc += __shfl_down_sync(0xffffffffu, acc, o);
    if (lane == 0) wrel[w] = acc + wr_b[l];
}

__global__ void k_gather(const float* __restrict__ Enode, const int* __restrict__ node_ids,
                         float* __restrict__ x) {
    int t = blockIdx.x * blockDim.x + threadIdx.x;
    if (t >= NNODES * 32) return;
    int i = t >> 5, q = t & 31;
    int nid = node_ids[i];
    *(float4*)(x + (size_t)i * NH + q * 4) =
        *(const float4*)(Enode + (size_t)nid * NH + q * 4);
}

// beta[l][b][v] = tanh(dot(visit[b,v,:], beta_w[l]) + beta_b[l]) * exp(0.03*(V - v))
__global__ void k_beta(const float* __restrict__ vn, const float* __restrict__ beta_w,
                       const float* __restrict__ beta_b, float* __restrict__ betaOut) {
    int w = (blockIdx.x * blockDim.x + threadIdx.x) >> 5;
    int lane = threadIdx.x & 31;
    if (w >= NL * NBATCH * NV) return;
    int l = w / (NBATCH * NV);
    int rem = w % (NBATCH * NV);
    int b = rem / NV, v = rem % NV;
    const float* row = vn + ((size_t)b * NV + v) * NVOC;
    const float* bw = beta_w + l * NVOC;
    float acc = 0.f;
    for (int n = lane; n < NVOC; n += 32) acc += row[n] * bw[n];
#pragma unroll
    for (int o = 16; o; o >>= 1) acc += __shfl_down_sync(0xffffffffu, acc, o);
    if (lane == 0)
        betaOut[w] = tanhf(acc + beta_b[l]) * expf(0.03f * (float)(NV - v));
}

// attn[b][m] = sum_v softmax_v(Z[b,v,m]) * beta[b][v]
__global__ void k_attn(const float* __restrict__ Z, const float* __restrict__ betaL,
                       float* __restrict__ attnL) {
    int m = blockIdx.x * blockDim.x + threadIdx.x;
    int b = blockIdx.y;
    if (m >= NVOC) return;
    float z[NV];
    float mx = -1e30f;
#pragma unroll
    for (int v = 0; v < NV; v++) {
        z[v] = Z[((size_t)(b * NV + v)) * NVOC + m];
        mx = fmaxf(mx, z[v]);
    }
    float s = 0.f, num = 0.f;
#pragma unroll
    for (int v = 0; v < NV; v++) {
        float e = expf(z[v] - mx);
        s += e;
        num += e * betaL[b * NV + v];
    }
    attnL[(size_t)b * NVOC + m] = num / s;
}

// agg[i] = sum_{e: dst[e]==i} relu(x[src[e]]*e_attn + wrel[rid]*Erel[rid])
__global__ void k_aggregate(const float* __restrict__ x, const float* __restrict__ Erel,
                            const float* __restrict__ attnL, const float* __restrict__ wrelL,
                            const int* __restrict__ elist, const int* __restrict__ rowstart,
                            const int* __restrict__ srcArr, const int* __restrict__ ridArr,
                            const int* __restrict__ nodeIds, const int* __restrict__ batchArr,
                            float* __restrict__ agg) {
    int warp = (blockIdx.x * blockDim.x + threadIdx.x) >> 5;
    int lane = threadIdx.x & 31;
    if (warp >= NNODES) return;
    int s0 = rowstart[warp], s1 = rowstart[warp + 1];
    float4 acc = {0.f, 0.f, 0.f, 0.f};
    for (int idx = s0; idx < s1; idx++) {
        int e = elist[idx];
        int s = srcArr[e];
        int r = ridArr[e];
        float ea = attnL[(size_t)batchArr[s] * NVOC + nodeIds[s]];
        float w = wrelL[r];
        float4 xv = *(const float4*)(x + (size_t)s * NH + lane * 4);
        float4 ev = *(const float4*)(Erel + (size_t)r * NH + lane * 4);
        acc.x += fmaxf(fmaf(xv.x, ea, w * ev.x), 0.f);
        acc.y += fmaxf(fmaf(xv.y, ea, w * ev.y), 0.f);
        acc.z += fmaxf(fmaf(xv.z, ea, w * ev.z), 0.f);
        acc.w += fmaxf(fmaf(xv.w, ea, w * ev.w), 0.f);
    }
    *(float4*)(agg + (size_t)warp * NH + lane * 4) = acc;
}

__global__ void k_pool(const float* __restrict__ x, const int* __restrict__ bstart,
                       float* __restrict__ xg) {
    int b = blockIdx.x, h = threadIdx.x;
    int s0 = bstart[b], s1 = bstart[b + 1];
    float acc = 0.f;
    for (int i = s0; i < s1; i++) acc += x[(size_t)i * NH + h];
    int c = s1 - s0;
    float denom = c > 0 ? (float)c : 1.f;
    xg[b * NH + h] = acc / denom;
}

__global__ void k_xnode(const float* __restrict__ ehr, const float* __restrict__ node_emb,
                        const float* __restrict__ lin_w, const float* __restrict__ lin_b,
                        float* __restrict__ xnode) {
    int b = blockIdx.x, h = threadIdx.x;
    __shared__ float t[NH];
    float acc = 0.f, den = 0.f;
    for (int n = 0; n < NVOC; n++) {
        float e = ehr[(size_t)b * NVOC + n];
        den += e;
        acc += e * node_emb[(size_t)n * NH + h];
    }
    t[h] = acc / den;
    __syncthreads();
    float s = 0.f;
    for (int hh = 0; hh < NH; hh++) s += t[hh] * lin_w[h * NH + hh];
    xnode[b * NH + h] = s + lin_b[h];
}

__global__ void k_final(const float* __restrict__ xg, const float* __restrict__ xn,
                        const float* __restrict__ mlp_w, const float* __restrict__ mlp_b,
                        float* __restrict__ out) {
    int b = blockIdx.x, t = threadIdx.x;
    __shared__ float s[2 * NH];
    s[t] = xg[b * NH + t];
    s[NH + t] = xn[b * NH + t];
    __syncthreads();
    if (t < NOUT) {
        float acc = mlp_b[t];
        const float* w = mlp_w + t * (2 * NH);
#pragma unroll 8
        for (int k = 0; k < 2 * NH; k++) acc += s[k] * w[k];
        out[b * NOUT + t] = acc;
    }
}

// ---------------- launch -------------------------------------------------------
extern "C" void kernel_launch(void* const* d_in, const int* in_sizes, int n_in,
                              void* d_out, int out_size) {
    const float* node_emb = (const float*)d_in[0];
    const float* rel_emb  = (const float*)d_in[1];
    const float* lin_w    = (const float*)d_in[2];
    const float* lin_b    = (const float*)d_in[3];
    const float* alpha_w  = (const float*)d_in[4];
    const float* alpha_b  = (const float*)d_in[5];
    const float* beta_w   = (const float*)d_in[6];
    const float* beta_b   = (const float*)d_in[7];
    const float* wr_w     = (const float*)d_in[8];
    const float* wr_b     = (const float*)d_in[9];
    const float* conv_w   = (const float*)d_in[10];
    const float* conv_b   = (const float*)d_in[11];
    const float* mlp_w    = (const float*)d_in[12];
    const float* mlp_b    = (const float*)d_in[13];
    const float* visit    = (const float*)d_in[14];
    const float* ehr      = (const float*)d_in[15];
    const int* node_ids   = (const int*)d_in[16];
    const int* rel_ids    = (const int*)d_in[17];
    const int* eidx       = (const int*)d_in[18];
    const int* batch      = (const int*)d_in[19];
    float* out = (float*)d_out;

    const int* srcArr = eidx;
    const int* dstArr = eidx + NEDGES;

    float *Zp, *Enodep, *Erelp, *wrelp, *attnp, *betap, *xp, *x2p, *aggp, *xgp, *xnodep;
    int *degp, *rowstartp, *cursorp, *elistp, *partp, *bcntp, *bstartp;
    cudaGetSymbolAddress((void**)&Zp, g_Z);
    cudaGetSymbolAddress((void**)&Enodep, g_Enode);
    cudaGetSymbolAddress((void**)&Erelp, g_Erel);
    cudaGetSymbolAddress((void**)&wrelp, g_wrel);
    cudaGetSymbolAddress((void**)&attnp, g_attn);
    cudaGetSymbolAddress((void**)&betap, g_beta);
    cudaGetSymbolAddress((void**)&xp, g_x);
    cudaGetSymbolAddress((void**)&x2p, g_x2);
    cudaGetSymbolAddress((void**)&aggp, g_agg);
    cudaGetSymbolAddress((void**)&xgp, g_xg);
    cudaGetSymbolAddress((void**)&xnodep, g_xnode);
    cudaGetSymbolAddress((void**)&degp, g_deg);
    cudaGetSymbolAddress((void**)&rowstartp, g_rowstart);
    cudaGetSymbolAddress((void**)&cursorp, g_cursor);
    cudaGetSymbolAddress((void**)&elistp, g_elist);
    cudaGetSymbolAddress((void**)&partp, g_part);
    cudaGetSymbolAddress((void**)&bcntp, g_bcnt);
    cudaGetSymbolAddress((void**)&bstartp, g_bstart);

    const int SCAN_BLOCKS = (NNODES + 1023) / 1024;   // 49

    // ---- CSR build (by dst) + batch offsets ----
    k_zero_int<<<(NNODES + 255) / 256, 256>>>(degp, NNODES);
    k_zero_int<<<1, 64>>>(bcntp, NBATCH);
    k_hist<<<(NEDGES + 255) / 256, 256>>>(dstArr, degp, NEDGES);
    k_hist_batch<<<(NNODES + 255) / 256, 256>>>(batch, bcntp);
    k_scan_block<<<SCAN_BLOCKS, 1024>>>(degp, rowstartp, partp, NNODES);
    k_scan_part<<<1, 1>>>(partp, SCAN_BLOCKS, rowstartp);
    k_scan_add<<<SCAN_BLOCKS, 1024>>>(rowstartp, partp, cursorp, NNODES);
    k_scatter<<<(NEDGES + 255) / 256, 256>>>(dstArr, cursorp, elistp, NEDGES);
    k_bscan<<<1, 1>>>(bcntp, bstartp);

    // ---- feature precompute ----
    gemm_nt<false, false><<<dim3((NH + GBN - 1) / GBN, (NVOC + GBM - 1) / GBM), 256>>>(
        node_emb, nullptr, lin_w, lin_b, Enodep, NVOC, NH, NH);
    gemm_nt<false, false><<<dim3((NH + GBN - 1) / GBN, (NREL + GBM - 1) / GBM), 256>>>(
        rel_emb, nullptr, lin_w, lin_b, Erelp, NREL, NH, NH);
    k_wrel<<<(NL * NREL * 32 + 255) / 256, 256>>>(Erelp, wr_w, wr_b, wrelp);
    k_gather<<<(NNODES * 32 + 255) / 256, 256>>>(Enodep, node_ids, xp);
    k_beta<<<(NL * NBATCH * NV * 32 + 255) / 256, 256>>>(visit, beta_w, beta_b, betap);

    // ---- attention (all 3 layers, independent of x) ----
    for (int l = 0; l < NL; l++) {
        gemm_nt<false, false><<<dim3((NVOC + GBN - 1) / GBN, (NBATCH * NV + GBM - 1) / GBM), 256>>>(
            visit, nullptr, alpha_w + (size_t)l * NVOC * NVOC, alpha_b + (size_t)l * NVOC,
            Zp, NBATCH * NV, NVOC, NVOC);
        k_attn<<<dim3((NVOC + 255) / 256, NBATCH), 256>>>(
            Zp, betap + l * NBATCH * NV, attnp + (size_t)l * NBATCH * NVOC);
    }

    // ---- message-passing layers ----
    float* xcur = xp;
    float* xalt = x2p;
    for (int l = 0; l < NL; l++) {
        k_aggregate<<<(NNODES * 32 + 255) / 256, 256>>>(
            xcur, Erelp, attnp + (size_t)l * NBATCH * NVOC, wrelp + l * NREL,
            elistp, rowstartp, srcArr, rel_ids, node_ids, batch, aggp);
        gemm_nt<true, true><<<dim3((NH + GBN - 1) / GBN, (NNODES + GBM - 1) / GBM), 256>>>(
            aggp, xcur, conv_w + (size_t)l * NH * NH, conv_b + (size_t)l * NH,
            xalt, NNODES, NH, NH);
        float* tmp = xcur; xcur = xalt; xalt = tmp;
    }

    // ---- heads ----
    k_pool<<<NBATCH, NH>>>(xcur, bstartp, xgp);
    k_xnode<<<NBATCH, NH>>>(ehr, node_emb, lin_w, lin_b, xnodep);
    k_final<<<NBATCH, NH>>>(xgp, xnodep, mlp_w, mlp_b, out);
}

// round 2
// speedup vs baseline: 2.1984x; 2.1984x over previous
#include <cuda_runtime.h>
#include <math.h>
#include <stdint.h>

#define NNODES 50000
#define NEDGES 800000
#define NBATCH 32
#define NV 20
#define NVOC 4000
#define NREL 200
#define NH 128
#define NL 3
#define NOUT 100

// ---------------- device scratch ----------------
__device__ float g_Z[(size_t)NL * NBATCH * NV * NVOC];   // alpha logits, all layers
__device__ float g_Enode[NVOC * NH];
__device__ float g_Erel[NREL * NH];
__device__ float g_wrel[NL * NREL];
__device__ float g_attn[(size_t)NL * NBATCH * NVOC];
__device__ float g_beta[NL * NBATCH * NV];
__device__ float g_x[(size_t)NNODES * NH];
__device__ float g_x2[(size_t)NNODES * NH];
__device__ float g_agg[(size_t)NNODES * NH];
__device__ int   g_deg[NNODES];
__device__ int   g_rowstart[NNODES + 1];
__device__ int   g_cursor[NNODES];
__device__ int   g_elist[NEDGES];
__device__ int   g_part[64];
__device__ int   g_bcnt[NBATCH];
__device__ int   g_bstart[NBATCH + 1];
__device__ float g_xg[NBATCH * NH];
__device__ float g_xnode[NBATCH * NH];

// ---------------- cp.async helpers ----------------
__device__ __forceinline__ void cp_async16(void* smem_dst, const void* gsrc, int src_size) {
    uint32_t s = (uint32_t)__cvta_generic_to_shared(smem_dst);
    asm volatile("cp.async.ca.shared.global [%0], [%1], 16, %2;\n"
                 :: "r"(s), "l"(gsrc), "r"(src_size));
}
__device__ __forceinline__ void cp_commit() { asm volatile("cp.async.commit_group;\n"); }
template <int W> __device__ __forceinline__ void cp_wait() {
    asm volatile("cp.async.wait_group %0;\n" :: "n"(W));
}

// ---------------- tf32 tensor-core GEMM for alpha logits ----------------
// Z[l][m][n] = sum_k visit[m,k] * alpha_w[l][n,k] + alpha_b[l][n]
// M=640, N=K=4000. Tiles: 128x128x16, 256 thr (8 warps, warp tile 64x32).
#define TBM 128
#define TBN 128
#define TBK 16
#define TPAD 20    // floats per smem row (16 data + 4 pad) -> conflict-free

__global__ __launch_bounds__(256, 2) void alpha_gemm_tf32(
    const float* __restrict__ A,       // visit [M,K]
    const float* __restrict__ Ball,    // alpha_w [L,N,K]
    const float* __restrict__ biasAll, // alpha_b [L,N]
    float* __restrict__ Zall)          // [L,M,N]
{
    const int M = NBATCH * NV, N = NVOC, K = NVOC;
    const int KITERS = K / TBK;        // 250

    int l = blockIdx.z;
    const float* B = Ball + (size_t)l * N * K;
    const float* bias = biasAll + (size_t)l * N;
    float* C = Zall + (size_t)l * M * N;

    __shared__ float As[2][TBM * TPAD];
    __shared__ float Bs[2][TBN * TPAD];

    int tid = threadIdx.x;
    int m0 = blockIdx.y * TBM;
    int n0 = blockIdx.x * TBN;
    int warp = tid >> 5, lane = tid & 31;
    int wm = (warp & 1) * 64;
    int wn = (warp >> 1) * 32;
    int lq = lane >> 2;     // 0..7
    int lr = lane & 3;      // 0..3

    float acc[4][4][4];
#pragma unroll
    for (int i = 0; i < 4; i++)
#pragma unroll
        for (int j = 0; j < 4; j++)
#pragma unroll
            for (int r = 0; r < 4; r++) acc[i][j][r] = 0.f;

#define ISSUE_TILES(stage, k0)                                                        \
    do {                                                                              \
        _Pragma("unroll")                                                             \
        for (int t = tid; t < 512; t += 256) {                                        \
            int row = t >> 2, ch = (t & 3) * 4;                                       \
            cp_async16(&As[stage][row * TPAD + ch],                                   \
                       A + (size_t)(m0 + row) * K + (k0) + ch, 16);                   \
        }                                                                             \
        _Pragma("unroll")                                                             \
        for (int t = tid; t < 512; t += 256) {                                        \
            int row = t >> 2, ch = (t & 3) * 4;                                       \
            int gn = n0 + row;                                                        \
            int ok = gn < N;                                                          \
            cp_async16(&Bs[stage][row * TPAD + ch],                                   \
                       B + (size_t)(ok ? gn : 0) * K + (k0) + ch, ok ? 16 : 0);       \
        }                                                                             \
    } while (0)

    ISSUE_TILES(0, 0);
    cp_commit();

    for (int kt = 0; kt < KITERS; kt++) {
        int st = kt & 1;
        if (kt + 1 < KITERS) {
            ISSUE_TILES(st ^ 1, (kt + 1) * TBK);
            cp_commit();
            cp_wait<1>();
        } else {
            cp_wait<0>();
        }
        __syncthreads();

#pragma unroll
        for (int kk = 0; kk < TBK; kk += 8) {
            uint32_t af[4][4];
            uint32_t bf[4][2];
            const float* as = As[st];
            const float* bs = Bs[st];
#pragma unroll
            for (int mi = 0; mi < 4; mi++) {
                int r = wm + mi * 16 + lq;
                af[mi][0] = __float_as_uint(as[r * TPAD + kk + lr]);
                af[mi][1] = __float_as_uint(as[(r + 8) * TPAD + kk + lr]);
                af[mi][2] = __float_as_uint(as[r * TPAD + kk + 4 + lr]);
                af[mi][3] = __float_as_uint(as[(r + 8) * TPAD + kk + 4 + lr]);
            }
#pragma unroll
            for (int ni = 0; ni < 4; ni++) {
                int c = wn + ni * 8 + lq;
                bf[ni][0] = __float_as_uint(bs[c * TPAD + kk + lr]);
                bf[ni][1] = __float_as_uint(bs[c * TPAD + kk + 4 + lr]);
            }
#pragma unroll
            for (int mi = 0; mi < 4; mi++)
#pragma unroll
                for (int ni = 0; ni < 4; ni++) {
                    asm volatile(
                        "mma.sync.aligned.m16n8k8.row.col.f32.tf32.tf32.f32 "
                        "{%0,%1,%2,%3}, {%4,%5,%6,%7}, {%8,%9}, {%0,%1,%2,%3};\n"
                        : "+f"(acc[mi][ni][0]), "+f"(acc[mi][ni][1]),
                          "+f"(acc[mi][ni][2]), "+f"(acc[mi][ni][3])
                        : "r"(af[mi][0]), "r"(af[mi][1]), "r"(af[mi][2]), "r"(af[mi][3]),
                          "r"(bf[ni][0]), "r"(bf[ni][1]));
                }
        }
        __syncthreads();
    }

    // epilogue: C[r][c] layout per m16n8 accumulator mapping
#pragma unroll
    for (int mi = 0; mi < 4; mi++) {
#pragma unroll
        for (int ni = 0; ni < 4; ni++) {
            int r = m0 + wm + mi * 16 + lq;
            int c = n0 + wn + ni * 8 + lr * 2;
            if (c < N) {
                float2 bb = *(const float2*)(bias + c);
                float2 o0, o1;
                o0.x = acc[mi][ni][0] + bb.x; o0.y = acc[mi][ni][1] + bb.y;
                o1.x = acc[mi][ni][2] + bb.x; o1.y = acc[mi][ni][3] + bb.y;
                *(float2*)(C + (size_t)r * N + c) = o0;
                *(float2*)(C + (size_t)(r + 8) * N + c) = o1;
            }
        }
    }
#undef ISSUE_TILES
}

// ---------------- generic SIMT NT GEMM (small GEMMs / conv layers) ----------
#define GBM 128
#define GBN 64
#define GBK 16

template <bool RELU, bool ADD2>
__global__ __launch_bounds__(256, 2) void gemm_nt(
    const float* __restrict__ A, const float* __restrict__ A2,
    const float* __restrict__ B, const float* __restrict__ bias,
    float* __restrict__ C, int M, int N, int K)
{
    __shared__ float As[GBK][GBM];
    __shared__ float Bs[GBK][GBN];

    int tid = threadIdx.x;
    int m0 = blockIdx.y * GBM;
    int n0 = blockIdx.x * GBN;
    int ty = tid >> 4;
    int tx = tid & 15;

    int arow = tid >> 1;
    int ak   = (tid & 1) * 8;
    int brow = tid >> 2;
    int bk   = (tid & 3) * 4;

    float acc[8][4];
#pragma unroll
    for (int i = 0; i < 8; i++)
#pragma unroll
        for (int j = 0; j < 4; j++) acc[i][j] = 0.f;

    int agrow = m0 + arow;
    int bgrow = n0 + brow;
    bool aval = agrow < M;
    bool bval = bgrow < N;
    const float* Aptr  = A + (size_t)agrow * K + ak;
    const float* A2ptr = ADD2 ? (A2 + (size_t)agrow * K + ak) : A;
    const float* Bptr  = B + (size_t)bgrow * K + bk;

    for (int k0 = 0; k0 < K; k0 += GBK) {
        float4 a0 = {0, 0, 0, 0}, a1 = {0, 0, 0, 0}, b0 = {0, 0, 0, 0};
        if (aval) {
            a0 = *(const float4*)(Aptr + k0);
            a1 = *(const float4*)(Aptr + k0 + 4);
            if (ADD2) {
                float4 c0 = *(const float4*)(A2ptr + k0);
                float4 c1 = *(const float4*)(A2ptr + k0 + 4);
                a0.x += c0.x; a0.y += c0.y; a0.z += c0.z; a0.w += c0.w;
                a1.x += c1.x; a1.y += c1.y; a1.z += c1.z; a1.w += c1.w;
            }
        }
        if (bval) b0 = *(const float4*)(Bptr + k0);

        __syncthreads();
        As[ak + 0][arow] = a0.x; As[ak + 1][arow] = a0.y;
        As[ak + 2][arow] = a0.z; As[ak + 3][arow] = a0.w;
        As[ak + 4][arow] = a1.x; As[ak + 5][arow] = a1.y;
        As[ak + 6][arow] = a1.z; As[ak + 7][arow] = a1.w;
        Bs[bk + 0][brow] = b0.x; Bs[bk + 1][brow] = b0.y;
        Bs[bk + 2][brow] = b0.z; Bs[bk + 3][brow] = b0.w;
        __syncthreads();

#pragma unroll
        for (int k = 0; k < GBK; k++) {
            float4 av0 = *(const float4*)&As[k][ty * 8];
            float4 av1 = *(const float4*)&As[k][ty * 8 + 4];
            float4 bv  = *(const float4*)&Bs[k][tx * 4];
            float a[8] = {av0.x, av0.y, av0.z, av0.w, av1.x, av1.y, av1.z, av1.w};
            float b[4] = {bv.x, bv.y, bv.z, bv.w};
#pragma unroll
            for (int i = 0; i < 8; i++)
#pragma unroll
                for (int j = 0; j < 4; j++) acc[i][j] = fmaf(a[i], b[j], acc[i][j]);
        }
    }

    int c0 = n0 + tx * 4;
    if (c0 < N) {
        float bb0 = bias[c0], bb1 = bias[c0 + 1], bb2 = bias[c0 + 2], bb3 = bias[c0 + 3];
#pragma unroll
        for (int i = 0; i < 8; i++) {
            int r = m0 + ty * 8 + i;
            if (r < M) {
                float4 o;
                o.x = acc[i][0] + bb0; o.y = acc[i][1] + bb1;
                o.z = acc[i][2] + bb2; o.w = acc[i][3] + bb3;
                if (RELU) {
                    o.x = fmaxf(o.x, 0.f); o.y = fmaxf(o.y, 0.f);
                    o.z = fmaxf(o.z, 0.f); o.w = fmaxf(o.w, 0.f);
                }
                *(float4*)(C + (size_t)r * N + c0) = o;
            }
        }
    }
}

// ---------------- small kernels ----------------
__global__ void k_zero_int(int* __restrict__ p, int n) {
    int i = blockIdx.x * blockDim.x + threadIdx.x;
    if (i < n) p[i] = 0;
}

__global__ void k_hist(const int* __restrict__ keys, int* __restrict__ cnt, int n) {
    int i = blockIdx.x * blockDim.x + threadIdx.x;
    if (i < n) atomicAdd(&cnt[keys[i]], 1);
}

__global__ void k_hist_batch(const int* __restrict__ batch, int* __restrict__ bcnt) {
    __shared__ int h[NBATCH];
    if (threadIdx.x < NBATCH) h[threadIdx.x] = 0;
    __syncthreads();
    int i = blockIdx.x * blockDim.x + threadIdx.x;
    if (i < NNODES) atomicAdd(&h[batch[i]], 1);
    __syncthreads();
    if (threadIdx.x < NBATCH) atomicAdd(&bcnt[threadIdx.x], h[threadIdx.x]);
}

__global__ void k_scan_block(const int* __restrict__ in, int* __restrict__ outEx,
                             int* __restrict__ part, int n) {
    __shared__ int s[1024];
    int t = threadIdx.x;
    int i = blockIdx.x * 1024 + t;
    int v = (i < n) ? in[i] : 0;
    s[t] = v;
    __syncthreads();
    for (int off = 1; off < 1024; off <<= 1) {
        int y = (t >= off) ? s[t - off] : 0;
        __syncthreads();
        s[t] += y;
        __syncthreads();
    }
    if (i < n) outEx[i] = s[t] - v;
    if (t == 1023) part[blockIdx.x] = s[1023];
}

__global__ void k_scan_part(int* __restrict__ part, int nb, int* __restrict__ rowstart) {
    if (threadIdx.x == 0 && blockIdx.x == 0) {
        int acc = 0;
        for (int i = 0; i < nb; i++) { int v = part[i]; part[i] = acc; acc += v; }
        rowstart[NNODES] = NEDGES;
    }
}

__global__ void k_scan_add(int* __restrict__ rowstart, const int* __restrict__ part,
                           int* __restrict__ cursor, int n) {
    int i = blockIdx.x * 1024 + threadIdx.x;
    if (i < n) {
        int v = rowstart[i] + part[blockIdx.x];
        rowstart[i] = v;
        cursor[i] = v;
    }
}

__global__ void k_scatter(const int* __restrict__ dst, int* __restrict__ cursor,
                          int* __restrict__ elist, int n) {
    int e = blockIdx.x * blockDim.x + threadIdx.x;
    if (e < n) {
        int d = dst[e];
        int p = atomicAdd(&cursor[d], 1);
        elist[p] = e;
    }
}

__global__ void k_bscan(const int* __restrict__ bcnt, int* __restrict__ bstart) {
    if (threadIdx.x == 0 && blockIdx.x == 0) {
        int acc = 0;
        for (int b = 0; b < NBATCH; b++) { bstart[b] = acc; acc += bcnt[b]; }
        bstart[NBATCH] = acc;
    }
}

__global__ void k_wrel(const float* __restrict__ Erel, const float* __restrict__ wr_w,
                       const float* __restrict__ wr_b, float* __restrict__ wrel) {
    int w = (blockIdx.x * blockDim.x + threadIdx.x) >> 5;
    int lane = threadIdx.x & 31;
    if (w >= NL * NREL) return;
    int l = w / NREL, r = w % NREL;
    float acc = 0.f;
#pragma unroll
    for (int h = lane; h < NH; h += 32) acc += Erel[r * NH + h] * wr_w[l * NH + h];
#pragma unroll
    for (int o = 16; o; o >>= 1) acc += __shfl_down_sync(0xffffffffu, acc, o);
    if (lane == 0) wrel[w] = acc + wr_b[l];
}

__global__ void k_gather(const float* __restrict__ Enode, const int* __restrict__ node_ids,
                         float* __restrict__ x) {
    int t = blockIdx.x * blockDim.x + threadIdx.x;
    if (t >= NNODES * 32) return;
    int i = t >> 5, q = t & 31;
    int nid = node_ids[i];
    *(float4*)(x + (size_t)i * NH + q * 4) =
        *(const float4*)(Enode + (size_t)nid * NH + q * 4);
}

__global__ void k_beta(const float* __restrict__ vn, const float* __restrict__ beta_w,
                       const float* __restrict__ beta_b, float* __restrict__ betaOut) {
    int w = (blockIdx.x * blockDim.x + threadIdx.x) >> 5;
    int lane = threadIdx.x & 31;
    if (w >= NL * NBATCH * NV) return;
    int l = w / (NBATCH * NV);
    int rem = w % (NBATCH * NV);
    int b = rem / NV, v = rem % NV;
    const float* row = vn + ((size_t)b * NV + v) * NVOC;
    const float* bw = beta_w + l * NVOC;
    float acc = 0.f;
    for (int n = lane; n < NVOC; n += 32) acc += row[n] * bw[n];
#pragma unroll
    for (int o = 16; o; o >>= 1) acc += __shfl_down_sync(0xffffffffu, acc, o);
    if (lane == 0)
        betaOut[w] = tanhf(acc + beta_b[l]) * expf(0.03f * (float)(NV - v));
}

// attn[l][b][m] = sum_v softmax_v(Z[l,b,v,m]) * beta[l][b][v]
__global__ void k_attn(const float* __restrict__ Zall, const float* __restrict__ betaAll,
                       float* __restrict__ attnAll) {
    int m = blockIdx.x * blockDim.x + threadIdx.x;
    int b = blockIdx.y;
    int l = blockIdx.z;
    if (m >= NVOC) return;
    const float* Z = Zall + (size_t)l * NBATCH * NV * NVOC;
    const float* betaL = betaAll + l * NBATCH * NV;
    float z[NV];
    float mx = -1e30f;
#pragma unroll
    for (int v = 0; v < NV; v++) {
        z[v] = Z[((size_t)(b * NV + v)) * NVOC + m];
        mx = fmaxf(mx, z[v]);
    }
    float s = 0.f, num = 0.f;
#pragma unroll
    for (int v = 0; v < NV; v++) {
        float e = expf(z[v] - mx);
        s += e;
        num += e * betaL[b * NV + v];
    }
    attnAll[((size_t)l * NBATCH + b) * NVOC + m] = num / s;
}

__global__ void k_aggregate(const float* __restrict__ x, const float* __restrict__ Erel,
                            const float* __restrict__ attnL, const float* __restrict__ wrelL,
                            const int* __restrict__ elist, const int* __restrict__ rowstart,
                            const int* __restrict__ srcArr, const int* __restrict__ ridArr,
                            const int* __restrict__ nodeIds, const int* __restrict__ batchArr,
                            float* __restrict__ agg) {
    int warp = (blockIdx.x * blockDim.x + threadIdx.x) >> 5;
    int lane = threadIdx.x & 31;
    if (warp >= NNODES) return;
    int s0 = rowstart[warp], s1 = rowstart[warp + 1];
    float4 acc = {0.f, 0.f, 0.f, 0.f};
    for (int idx = s0; idx < s1; idx++) {
        int e = elist[idx];
        int s = srcArr[e];
        int r = ridArr[e];
        float ea = attnL[(size_t)batchArr[s] * NVOC + nodeIds[s]];
        float w = wrelL[r];
        float4 xv = *(const float4*)(x + (size_t)s * NH + lane * 4);
        float4 ev = *(const float4*)(Erel + (size_t)r * NH + lane * 4);
        acc.x += fmaxf(fmaf(xv.x, ea, w * ev.x), 0.f);
        acc.y += fmaxf(fmaf(xv.y, ea, w * ev.y), 0.f);
        acc.z += fmaxf(fmaf(xv.z, ea, w * ev.z), 0.f);
        acc.w += fmaxf(fmaf(xv.w, ea, w * ev.w), 0.f);
    }
    *(float4*)(agg + (size_t)warp * NH + lane * 4) = acc;
}

__global__ void k_pool(const float* __restrict__ x, const int* __restrict__ bstart,
                       float* __restrict__ xg) {
    int b = blockIdx.x, h = threadIdx.x;
    int s0 = bstart[b], s1 = bstart[b + 1];
    float acc = 0.f;
    for (int i = s0; i < s1; i++) acc += x[(size_t)i * NH + h];
    int c = s1 - s0;
    float denom = c > 0 ? (float)c : 1.f;
    xg[b * NH + h] = acc / denom;
}

__global__ void k_xnode(const float* __restrict__ ehr, const float* __restrict__ node_emb,
                        const float* __restrict__ lin_w, const float* __restrict__ lin_b,
                        float* __restrict__ xnode) {
    int b = blockIdx.x, h = threadIdx.x;
    __shared__ float t[NH];
    float acc = 0.f, den = 0.f;
    for (int n = 0; n < NVOC; n++) {
        float e = ehr[(size_t)b * NVOC + n];
        den += e;
        acc += e * node_emb[(size_t)n * NH + h];
    }
    t[h] = acc / den;
    __syncthreads();
    float s = 0.f;
    for (int hh = 0; hh < NH; hh++) s += t[hh] * lin_w[h * NH + hh];
    xnode[b * NH + h] = s + lin_b[h];
}

__global__ void k_final(const float* __restrict__ xg, const float* __restrict__ xn,
                        const float* __restrict__ mlp_w, const float* __restrict__ mlp_b,
                        float* __restrict__ out) {
    int b = blockIdx.x, t = threadIdx.x;
    __shared__ float s[2 * NH];
    s[t] = xg[b * NH + t];
    s[NH + t] = xn[b * NH + t];
    __syncthreads();
    if (t < NOUT) {
        float acc = mlp_b[t];
        const float* w = mlp_w + t * (2 * NH);
#pragma unroll 8
        for (int k = 0; k < 2 * NH; k++) acc += s[k] * w[k];
        out[b * NOUT + t] = acc;
    }
}

// ---------------- launch ----------------
extern "C" void kernel_launch(void* const* d_in, const int* in_sizes, int n_in,
                              void* d_out, int out_size) {
    const float* node_emb = (const float*)d_in[0];
    const float* rel_emb  = (const float*)d_in[1];
    const float* lin_w    = (const float*)d_in[2];
    const float* lin_b    = (const float*)d_in[3];
    const float* alpha_w  = (const float*)d_in[4];
    const float* alpha_b  = (const float*)d_in[5];
    const float* beta_w   = (const float*)d_in[6];
    const float* beta_b   = (const float*)d_in[7];
    const float* wr_w     = (const float*)d_in[8];
    const float* wr_b     = (const float*)d_in[9];
    const float* conv_w   = (const float*)d_in[10];
    const float* conv_b   = (const float*)d_in[11];
    const float* mlp_w    = (const float*)d_in[12];
    const float* mlp_b    = (const float*)d_in[13];
    const float* visit    = (const float*)d_in[14];
    const float* ehr      = (const float*)d_in[15];
    const int* node_ids   = (const int*)d_in[16];
    const int* rel_ids    = (const int*)d_in[17];
    const int* eidx       = (const int*)d_in[18];
    const int* batch      = (const int*)d_in[19];
    float* out = (float*)d_out;

    const int* srcArr = eidx;
    const int* dstArr = eidx + NEDGES;

    float *Zp, *Enodep, *Erelp, *wrelp, *attnp, *betap, *xp, *x2p, *aggp, *xgp, *xnodep;
    int *degp, *rowstartp, *cursorp, *elistp, *partp, *bcntp, *bstartp;
    cudaGetSymbolAddress((void**)&Zp, g_Z);
    cudaGetSymbolAddress((void**)&Enodep, g_Enode);
    cudaGetSymbolAddress((void**)&Erelp, g_Erel);
    cudaGetSymbolAddress((void**)&wrelp, g_wrel);
    cudaGetSymbolAddress((void**)&attnp, g_attn);
    cudaGetSymbolAddress((void**)&betap, g_beta);
    cudaGetSymbolAddress((void**)&xp, g_x);
    cudaGetSymbolAddress((void**)&x2p, g_x2);
    cudaGetSymbolAddress((void**)&aggp, g_agg);
    cudaGetSymbolAddress((void**)&xgp, g_xg);
    cudaGetSymbolAddress((void**)&xnodep, g_xnode);
    cudaGetSymbolAddress((void**)&degp, g_deg);
    cudaGetSymbolAddress((void**)&rowstartp, g_rowstart);
    cudaGetSymbolAddress((void**)&cursorp, g_cursor);
    cudaGetSymbolAddress((void**)&elistp, g_elist);
    cudaGetSymbolAddress((void**)&partp, g_part);
    cudaGetSymbolAddress((void**)&bcntp, g_bcnt);
    cudaGetSymbolAddress((void**)&bstartp, g_bstart);

    const int SCAN_BLOCKS = (NNODES + 1023) / 1024;   // 49

    // ---- feature precompute first (puts alpha_gemm_tf32 at launch index 5
    //      so ncu -s 5 -c 1 captures the dominant kernel) ----
    gemm_nt<false, false><<<dim3((NH + GBN - 1) / GBN, (NVOC + GBM - 1) / GBM), 256>>>(
        node_emb, nullptr, lin_w, lin_b, Enodep, NVOC, NH, NH);                       // #0
    gemm_nt<false, false><<<dim3((NH + GBN - 1) / GBN, (NREL + GBM - 1) / GBM), 256>>>(
        rel_emb, nullptr, lin_w, lin_b, Erelp, NREL, NH, NH);                         // #1
    k_wrel<<<(NL * NREL * 32 + 255) / 256, 256>>>(Erelp, wr_w, wr_b, wrelp);          // #2
    k_gather<<<(NNODES * 32 + 255) / 256, 256>>>(Enodep, node_ids, xp);               // #3
    k_beta<<<(NL * NBATCH * NV * 32 + 255) / 256, 256>>>(visit, beta_w, beta_b, betap); // #4

    // ---- alpha logits: all 3 layers, tensor cores ----                             // #5
    alpha_gemm_tf32<<<dim3((NVOC + TBN - 1) / TBN, (NBATCH * NV) / TBM, NL), 256>>>(
        visit, alpha_w, alpha_b, Zp);
    k_attn<<<dim3((NVOC + 255) / 256, NBATCH, NL), 256>>>(Zp, betap, attnp);

    // ---- CSR build (by dst) + batch offsets ----
    k_zero_int<<<(NNODES + 255) / 256, 256>>>(degp, NNODES);
    k_zero_int<<<1, 64>>>(bcntp, NBATCH);
    k_hist<<<(NEDGES + 255) / 256, 256>>>(dstArr, degp, NEDGES);
    k_hist_batch<<<(NNODES + 255) / 256, 256>>>(batch, bcntp);
    k_scan_block<<<SCAN_BLOCKS, 1024>>>(degp, rowstartp, partp, NNODES);
    k_scan_part<<<1, 1>>>(partp, SCAN_BLOCKS, rowstartp);
    k_scan_add<<<SCAN_BLOCKS, 1024>>>(rowstartp, partp, cursorp, NNODES);
    k_scatter<<<(NEDGES + 255) / 256, 256>>>(dstArr, cursorp, elistp, NEDGES);
    k_bscan<<<1, 1>>>(bcntp, bstartp);

    // ---- message-passing layers ----
    float* xcur = xp;
    float* xalt = x2p;
    for (int l = 0; l < NL; l++) {
        k_aggregate<<<(NNODES * 32 + 255) / 256, 256>>>(
            xcur, Erelp, attnp + (size_t)l * NBATCH * NVOC, wrelp + l * NREL,
            elistp, rowstartp, srcArr, rel_ids, node_ids, batch, aggp);
        gemm_nt<true, true><<<dim3((NH + GBN - 1) / GBN, (NNODES + GBM - 1) / GBM), 256>>>(
            aggp, xcur, conv_w + (size_t)l * NH * NH, conv_b + (size_t)l * NH,
            xalt, NNODES, NH, NH);
        float* tmp = xcur; xcur = xalt; xalt = tmp;
    }

    // ---- heads ----
    k_pool<<<NBATCH, NH>>>(xcur, bstartp, xgp);
    k_xnode<<<NBATCH, NH>>>(ehr, node_emb, lin_w, lin_b, xnodep);
    k_final<<<NBATCH, NH>>>(xgp, xnodep, mlp_w, mlp_b, out);
}

// round 4
// speedup vs baseline: 2.7816x; 1.2653x over previous
#include <cuda_runtime.h>
#include <math.h>
#include <stdint.h>

#define NNODES 50000
#define NEDGES 800000
#define NBATCH 32
#define NV 20
#define NVOC 4000
#define NREL 200
#define NH 128
#define NL 3
#define NOUT 100

// ---------------- device scratch ----------------
__device__ float g_Z[(size_t)NL * NBATCH * NV * NVOC];
__device__ float g_Enode[NVOC * NH];
__device__ float g_Erel[NREL * NH];
__device__ float g_wrel[NL * NREL];
__device__ float g_attn[(size_t)NL * NBATCH * NVOC];
__device__ float g_beta[NL * NBATCH * NV];
__device__ float g_x[(size_t)NNODES * NH];
__device__ float g_x2[(size_t)NNODES * NH];
__device__ float g_agg[(size_t)NNODES * NH];
__device__ int   g_deg[NNODES];
__device__ int   g_rowstart[NNODES + 1];
__device__ int   g_cursor[NNODES];
__device__ int   g_elist[NEDGES];
__device__ int   g_part[64];
__device__ int   g_bcnt[NBATCH];
__device__ int   g_bstart[NBATCH + 1];
__device__ float g_xg[NBATCH * NH];
__device__ float g_xacc[NBATCH * NH];
__device__ float g_den[NBATCH];
__device__ float g_xnode[NBATCH * NH];

// ---------------- cp.async helpers ----------------
__device__ __forceinline__ void cp_async16(void* smem_dst, const void* gsrc, int src_size) {
    uint32_t s = (uint32_t)__cvta_generic_to_shared(smem_dst);
    asm volatile("cp.async.ca.shared.global [%0], [%1], 16, %2;\n"
                 :: "r"(s), "l"(gsrc), "r"(src_size));
}
__device__ __forceinline__ void cp_commit() { asm volatile("cp.async.commit_group;\n"); }
template <int W> __device__ __forceinline__ void cp_wait() {
    asm volatile("cp.async.wait_group %0;\n" :: "n"(W));
}

__device__ __forceinline__ void split_tf32(float v, uint32_t& hi, uint32_t& lo) {
    uint32_t h;
    asm("cvt.rna.tf32.f32 %0, %1;" : "=r"(h) : "f"(v));
    float l = v - __uint_as_float(h);
    uint32_t lt;
    asm("cvt.rna.tf32.f32 %0, %1;" : "=r"(lt) : "f"(l));
    hi = h; lo = lt;
}

// ---------------- tf32 tensor-core GEMM for alpha logits (proven R2) --------
// Z[l][m][n] = sum_k visit[m,k]*alpha_w[l][n,k] + alpha_b[l][n]; M=640,N=K=4000
#define TBM 128
#define TBN 128
#define TBK 16
#define TPAD 20

__global__ __launch_bounds__(256, 2) void alpha_gemm_tf32(
    const float* __restrict__ A,
    const float* __restrict__ Ball,
    const float* __restrict__ biasAll,
    float* __restrict__ Zall)
{
    const int M = NBATCH * NV, N = NVOC, K = NVOC;
    const int KITERS = K / TBK;

    int l = blockIdx.z;
    const float* B = Ball + (size_t)l * N * K;
    const float* bias = biasAll + (size_t)l * N;
    float* C = Zall + (size_t)l * M * N;

    __shared__ float As[2][TBM * TPAD];
    __shared__ float Bs[2][TBN * TPAD];

    int tid = threadIdx.x;
    int m0 = blockIdx.y * TBM;
    int n0 = blockIdx.x * TBN;
    int warp = tid >> 5, lane = tid & 31;
    int wm = (warp & 1) * 64;
    int wn = (warp >> 1) * 32;
    int lq = lane >> 2;
    int lr = lane & 3;

    float acc[4][4][4];
#pragma unroll
    for (int i = 0; i < 4; i++)
#pragma unroll
        for (int j = 0; j < 4; j++)
#pragma unroll
            for (int r = 0; r < 4; r++) acc[i][j][r] = 0.f;

#define ISSUE_TILES(stage, k0)                                                        \
    do {                                                                              \
        _Pragma("unroll")                                                             \
        for (int t = tid; t < 512; t += 256) {                                        \
            int row = t >> 2, ch = (t & 3) * 4;                                       \
            cp_async16(&As[stage][row * TPAD + ch],                                   \
                       A + (size_t)(m0 + row) * K + (k0) + ch, 16);                   \
        }                                                                             \
        _Pragma("unroll")                                                             \
        for (int t = tid; t < 512; t += 256) {                                        \
            int row = t >> 2, ch = (t & 3) * 4;                                       \
            int gn = n0 + row;                                                        \
            int ok = gn < N;                                                          \
            cp_async16(&Bs[stage][row * TPAD + ch],                                   \
                       B + (size_t)(ok ? gn : 0) * K + (k0) + ch, ok ? 16 : 0);       \
        }                                                                             \
    } while (0)

    ISSUE_TILES(0, 0);
    cp_commit();

    for (int kt = 0; kt < KITERS; kt++) {
        int st = kt & 1;
        if (kt + 1 < KITERS) {
            ISSUE_TILES(st ^ 1, (kt + 1) * TBK);
            cp_commit();
            cp_wait<1>();
        } else {
            cp_wait<0>();
        }
        __syncthreads();

#pragma unroll
        for (int kk = 0; kk < TBK; kk += 8) {
            uint32_t af[4][4];
            uint32_t bf[4][2];
            const float* as = As[st];
            const float* bs = Bs[st];
#pragma unroll
            for (int mi = 0; mi < 4; mi++) {
                int r = wm + mi * 16 + lq;
                af[mi][0] = __float_as_uint(as[r * TPAD + kk + lr]);
                af[mi][1] = __float_as_uint(as[(r + 8) * TPAD + kk + lr]);
                af[mi][2] = __float_as_uint(as[r * TPAD + kk + 4 + lr]);
                af[mi][3] = __float_as_uint(as[(r + 8) * TPAD + kk + 4 + lr]);
            }
#pragma unroll
            for (int ni = 0; ni < 4; ni++) {
                int c = wn + ni * 8 + lq;
                bf[ni][0] = __float_as_uint(bs[c * TPAD + kk + lr]);
                bf[ni][1] = __float_as_uint(bs[c * TPAD + kk + 4 + lr]);
            }
#pragma unroll
            for (int mi = 0; mi < 4; mi++)
#pragma unroll
                for (int ni = 0; ni < 4; ni++) {
                    asm volatile(
                        "mma.sync.aligned.m16n8k8.row.col.f32.tf32.tf32.f32 "
                        "{%0,%1,%2,%3}, {%4,%5,%6,%7}, {%8,%9}, {%0,%1,%2,%3};\n"
                        : "+f"(acc[mi][ni][0]), "+f"(acc[mi][ni][1]),
                          "+f"(acc[mi][ni][2]), "+f"(acc[mi][ni][3])
                        : "r"(af[mi][0]), "r"(af[mi][1]), "r"(af[mi][2]), "r"(af[mi][3]),
                          "r"(bf[ni][0]), "r"(bf[ni][1]));
                }
        }
        __syncthreads();
    }

#pragma unroll
    for (int mi = 0; mi < 4; mi++) {
#pragma unroll
        for (int ni = 0; ni < 4; ni++) {
            int r = m0 + wm + mi * 16 + lq;
            int c = n0 + wn + ni * 8 + lr * 2;
            if (c < N) {
                float2 bb = *(const float2*)(bias + c);
                float2 o0, o1;
                o0.x = acc[mi][ni][0] + bb.x; o0.y = acc[mi][ni][1] + bb.y;
                o1.x = acc[mi][ni][2] + bb.x; o1.y = acc[mi][ni][3] + bb.y;
                *(float2*)(C + (size_t)r * N + c) = o0;
                *(float2*)(C + (size_t)(r + 8) * N + c) = o1;
            }
        }
    }
#undef ISSUE_TILES
}

// ---------------- 3xTF32 compensated mma GEMM: K=128, N=128 -----------------
// C[M,128] = op((A (+A2)) @ B[128,128]^T + bias), fp32-equivalent precision.
#define CPW 36

template <bool RELU, bool ADD2>
__global__ __launch_bounds__(256) void gemm128_3xtf32(
    const float* __restrict__ A, const float* __restrict__ A2,
    const float* __restrict__ B, const float* __restrict__ bias,
    float* __restrict__ C, int M)
{
    __shared__ float As[128 * CPW];
    __shared__ float Bs[128 * CPW];

    int tid = threadIdx.x;
    int m0 = blockIdx.x * 128;
    int warp = tid >> 5, lane = tid & 31;
    int wm = (warp & 1) * 64;
    int wn = (warp >> 1) * 32;
    int lq = lane >> 2;
    int lr = lane & 3;

    float acc[4][4][4];
#pragma unroll
    for (int i = 0; i < 4; i++)
#pragma unroll
        for (int j = 0; j < 4; j++)
#pragma unroll
            for (int r = 0; r < 4; r++) acc[i][j][r] = 0.f;

    for (int k0 = 0; k0 < NH; k0 += 32) {
        __syncthreads();
#pragma unroll
        for (int t = tid; t < 1024; t += 256) {
            int row = t >> 3, seg = (t & 7) * 4;
            int gm = m0 + row;
            float4 v = {0, 0, 0, 0};
            if (gm < M) {
                v = *(const float4*)(A + (size_t)gm * NH + k0 + seg);
                if (ADD2) {
                    float4 w = *(const float4*)(A2 + (size_t)gm * NH + k0 + seg);
                    v.x += w.x; v.y += w.y; v.z += w.z; v.w += w.w;
                }
            }
            *(float4*)&As[row * CPW + seg] = v;
            *(float4*)&Bs[row * CPW + seg] = *(const float4*)(B + (size_t)row * NH + k0 + seg);
        }
        __syncthreads();

#pragma unroll
        for (int kk = 0; kk < 32; kk += 8) {
            uint32_t ah[4][4], al[4][4];
            uint32_t bh[4][2], bl[4][2];
#pragma unroll
            for (int mi = 0; mi < 4; mi++) {
                int base = (wm + mi * 16 + lq) * CPW + kk + lr;
                split_tf32(As[base],               ah[mi][0], al[mi][0]);
                split_tf32(As[base + 8 * CPW],     ah[mi][1], al[mi][1]);
                split_tf32(As[base + 4],           ah[mi][2], al[mi][2]);
                split_tf32(As[base + 8 * CPW + 4], ah[mi][3], al[mi][3]);
            }
#pragma unroll
            for (int ni = 0; ni < 4; ni++) {
                int base = (wn + ni * 8 + lq) * CPW + kk + lr;
                split_tf32(Bs[base],     bh[ni][0], bl[ni][0]);
                split_tf32(Bs[base + 4], bh[ni][1], bl[ni][1]);
            }
#define MMA_TF32(Aop, Bop)                                                            \
    asm volatile(                                                                     \
        "mma.sync.aligned.m16n8k8.row.col.f32.tf32.tf32.f32 "                         \
        "{%0,%1,%2,%3}, {%4,%5,%6,%7}, {%8,%9}, {%0,%1,%2,%3};\n"                     \
        : "+f"(acc[mi][ni][0]), "+f"(acc[mi][ni][1]),                                 \
          "+f"(acc[mi][ni][2]), "+f"(acc[mi][ni][3])                                  \
        : "r"(Aop[mi][0]), "r"(Aop[mi][1]), "r"(Aop[mi][2]), "r"(Aop[mi][3]),         \
          "r"(Bop[ni][0]), "r"(Bop[ni][1]))
#pragma unroll
            for (int mi = 0; mi < 4; mi++)
#pragma unroll
                for (int ni = 0; ni < 4; ni++) {
                    MMA_TF32(ah, bh);
                    MMA_TF32(ah, bl);
                    MMA_TF32(al, bh);
                }
#undef MMA_TF32
        }
    }

#pragma unroll
    for (int mi = 0; mi < 4; mi++) {
#pragma unroll
        for (int ni = 0; ni < 4; ni++) {
            int r = m0 + wm + mi * 16 + lq;
            int c = wn + ni * 8 + lr * 2;
            float2 bb = *(const float2*)(bias + c);
            float2 o0, o1;
            o0.x = acc[mi][ni][0] + bb.x; o0.y = acc[mi][ni][1] + bb.y;
            o1.x = acc[mi][ni][2] + bb.x; o1.y = acc[mi][ni][3] + bb.y;
            if (RELU) {
                o0.x = fmaxf(o0.x, 0.f); o0.y = fmaxf(o0.y, 0.f);
                o1.x = fmaxf(o1.x, 0.f); o1.y = fmaxf(o1.y, 0.f);
            }
            if (r < M)     *(float2*)(C + (size_t)r * NH + c) = o0;
            if (r + 8 < M) *(float2*)(C + (size_t)(r + 8) * NH + c) = o1;
        }
    }
}

// ---------------- small kernels ----------------
__global__ void k_zero_int(int* __restrict__ p, int n) {
    int i = blockIdx.x * blockDim.x + threadIdx.x;
    if (i < n) p[i] = 0;
}
__global__ void k_zero_float(float* __restrict__ p, int n) {
    int i = blockIdx.x * blockDim.x + threadIdx.x;
    if (i < n) p[i] = 0.f;
}

__global__ void k_hist(const int* __restrict__ keys, int* __restrict__ cnt, int n) {
    int i = blockIdx.x * blockDim.x + threadIdx.x;
    if (i < n) atomicAdd(&cnt[keys[i]], 1);
}

__global__ void k_hist_batch(const int* __restrict__ batch, int* __restrict__ bcnt) {
    __shared__ int h[NBATCH];
    if (threadIdx.x < NBATCH) h[threadIdx.x] = 0;
    __syncthreads();
    int i = blockIdx.x * blockDim.x + threadIdx.x;
    if (i < NNODES) atomicAdd(&h[batch[i]], 1);
    __syncthreads();
    if (threadIdx.x < NBATCH) atomicAdd(&bcnt[threadIdx.x], h[threadIdx.x]);
}

__global__ void k_scan_block(const int* __restrict__ in, int* __restrict__ outEx,
                             int* __restrict__ part, int n) {
    __shared__ int s[1024];
    int t = threadIdx.x;
    int i = blockIdx.x * 1024 + t;
    int v = (i < n) ? in[i] : 0;
    s[t] = v;
    __syncthreads();
    for (int off = 1; off < 1024; off <<= 1) {
        int y = (t >= off) ? s[t - off] : 0;
        __syncthreads();
        s[t] += y;
        __syncthreads();
    }
    if (i < n) outEx[i] = s[t] - v;
    if (t == 1023) part[blockIdx.x] = s[1023];
}

__global__ void k_scan_part(int* __restrict__ part, int nb, int* __restrict__ rowstart) {
    if (threadIdx.x == 0 && blockIdx.x == 0) {
        int acc = 0;
        for (int i = 0; i < nb; i++) { int v = part[i]; part[i] = acc; acc += v; }
        rowstart[NNODES] = NEDGES;
    }
}

__global__ void k_scan_add(int* __restrict__ rowstart, const int* __restrict__ part,
                           int* __restrict__ cursor, int n) {
    int i = blockIdx.x * 1024 + threadIdx.x;
    if (i < n) {
        int v = rowstart[i] + part[blockIdx.x];
        rowstart[i] = v;
        cursor[i] = v;
    }
}

__global__ void k_scatter(const int* __restrict__ dst, int* __restrict__ cursor,
                          int* __restrict__ elist, int n) {
    int e = blockIdx.x * blockDim.x + threadIdx.x;
    if (e < n) {
        int d = dst[e];
        int p = atomicAdd(&cursor[d], 1);
        elist[p] = e;
    }
}

__global__ void k_bscan(const int* __restrict__ bcnt, int* __restrict__ bstart) {
    if (threadIdx.x == 0 && blockIdx.x == 0) {
        int acc = 0;
        for (int b = 0; b < NBATCH; b++) { bstart[b] = acc; acc += bcnt[b]; }
        bstart[NBATCH] = acc;
    }
}

__global__ void k_wrel(const float* __restrict__ Erel, const float* __restrict__ wr_w,
                       const float* __restrict__ wr_b, float* __restrict__ wrel) {
    int w = (blockIdx.x * blockDim.x + threadIdx.x) >> 5;
    int lane = threadIdx.x & 31;
    if (w >= NL * NREL) return;
    int l = w / NREL, r = w % NREL;
    float acc = 0.f;
#pragma unroll
    for (int h = lane; h < NH; h += 32) acc += Erel[r * NH + h] * wr_w[l * NH + h];
#pragma unroll
    for (int o = 16; o; o >>= 1) acc += __shfl_down_sync(0xffffffffu, acc, o);
    if (lane == 0) wrel[w] = acc + wr_b[l];
}

__global__ void k_gather(const float* __restrict__ Enode, const int* __restrict__ node_ids,
                         float* __restrict__ x) {
    int t = blockIdx.x * blockDim.x + threadIdx.x;
    if (t >= NNODES * 32) return;
    int i = t >> 5, q = t & 31;
    int nid = node_ids[i];
    *(float4*)(x + (size_t)i * NH + q * 4) =
        *(const float4*)(Enode + (size_t)nid * NH + q * 4);
}

__global__ void k_beta(const float* __restrict__ vn, const float* __restrict__ beta_w,
                       const float* __restrict__ beta_b, float* __restrict__ betaOut) {
    int w = (blockIdx.x * blockDim.x + threadIdx.x) >> 5;
    int lane = threadIdx.x & 31;
    if (w >= NL * NBATCH * NV) return;
    int l = w / (NBATCH * NV);
    int rem = w % (NBATCH * NV);
    int b = rem / NV, v = rem % NV;
    const float* row = vn + ((size_t)b * NV + v) * NVOC;
    const float* bw = beta_w + l * NVOC;
    float acc = 0.f;
    for (int n = lane; n < NVOC; n += 32) acc += row[n] * bw[n];
#pragma unroll
    for (int o = 16; o; o >>= 1) acc += __shfl_down_sync(0xffffffffu, acc, o);
    if (lane == 0)
        betaOut[w] = tanhf(acc + beta_b[l]) * expf(0.03f * (float)(NV - v));
}

__global__ void k_attn(const float* __restrict__ Zall, const float* __restrict__ betaAll,
                       float* __restrict__ attnAll) {
    int m = blockIdx.x * blockDim.x + threadIdx.x;
    int b = blockIdx.y;
    int l = blockIdx.z;
    if (m >= NVOC) return;
    const float* Z = Zall + (size_t)l * NBATCH * NV * NVOC;
    const float* betaL = betaAll + l * NBATCH * NV;
    float z[NV];
    float mx = -1e30f;
#pragma unroll
    for (int v = 0; v < NV; v++) {
        z[v] = Z[((size_t)(b * NV + v)) * NVOC + m];
        mx = fmaxf(mx, z[v]);
    }
    float s = 0.f, num = 0.f;
#pragma unroll
    for (int v = 0; v < NV; v++) {
        float e = expf(z[v] - mx);
        s += e;
        num += e * betaL[b * NV + v];
    }
    attnAll[((size_t)l * NBATCH + b) * NVOC + m] = num / s;
}

__global__ void k_aggregate(const float* __restrict__ x, const float* __restrict__ Erel,
                            const float* __restrict__ attnL, const float* __restrict__ wrelL,
                            const int* __restrict__ elist, const int* __restrict__ rowstart,
                            const int* __restrict__ srcArr, const int* __restrict__ ridArr,
                            const int* __restrict__ nodeIds, const int* __restrict__ batchArr,
                            float* __restrict__ agg) {
    int warp = (blockIdx.x * blockDim.x + threadIdx.x) >> 5;
    int lane = threadIdx.x & 31;
    if (warp >= NNODES) return;
    int s0 = rowstart[warp], s1 = rowstart[warp + 1];
    float4 acc = {0.f, 0.f, 0.f, 0.f};
    for (int idx = s0; idx < s1; idx++) {
        int e = elist[idx];
        int s = srcArr[e];
        int r = ridArr[e];
        float ea = attnL[(size_t)batchArr[s] * NVOC + nodeIds[s]];
        float w = wrelL[r];
        float4 xv = *(const float4*)(x + (size_t)s * NH + lane * 4);
        float4 ev = *(const float4*)(Erel + (size_t)r * NH + lane * 4);
        acc.x += fmaxf(fmaf(xv.x, ea, w * ev.x), 0.f);
        acc.y += fmaxf(fmaf(xv.y, ea, w * ev.y), 0.f);
        acc.z += fmaxf(fmaf(xv.z, ea, w * ev.z), 0.f);
        acc.w += fmaxf(fmaf(xv.w, ea, w * ev.w), 0.f);
    }
    *(float4*)(agg + (size_t)warp * NH + lane * 4) = acc;
}

// pool split 8 ways per batch with atomics, then normalize
__global__ void k_pool_partial(const float* __restrict__ x, const int* __restrict__ bstart,
                               float* __restrict__ xg) {
    int b = blockIdx.y, chunk = blockIdx.x, h = threadIdx.x;
    int s0 = bstart[b], s1 = bstart[b + 1];
    int len = s1 - s0;
    int r0 = s0 + (int)((long long)len * chunk / 8);
    int r1 = s0 + (int)((long long)len * (chunk + 1) / 8);
    float acc = 0.f;
    for (int i = r0; i < r1; i++) acc += x[(size_t)i * NH + h];
    atomicAdd(&xg[b * NH + h], acc);
}

__global__ void k_pool_finish(float* __restrict__ xg, const int* __restrict__ bcnt) {
    int b = blockIdx.x, h = threadIdx.x;
    float c = (float)bcnt[b];
    xg[b * NH + h] /= fmaxf(c, 1.f);
}

// xnode: den[b] = sum_n ehr[b][n]; xacc[b][h] = sum_n ehr[b][n]*node_emb[n][h]
__global__ void k_ehrsum(const float* __restrict__ ehr, float* __restrict__ den) {
    int b = blockIdx.x, t = threadIdx.x;
    __shared__ float s[256];
    float acc = 0.f;
    for (int n = t; n < NVOC; n += 256) acc += ehr[(size_t)b * NVOC + n];
    s[t] = acc;
    __syncthreads();
    for (int o = 128; o; o >>= 1) {
        if (t < o) s[t] += s[t + o];
        __syncthreads();
    }
    if (t == 0) den[b] = s[0];
}

__global__ void k_xnode_partial(const float* __restrict__ ehr,
                                const float* __restrict__ node_emb,
                                float* __restrict__ xacc) {
    int b = blockIdx.y, slice = blockIdx.x, h = threadIdx.x;
    int n0 = slice * (NVOC / 16), n1 = n0 + (NVOC / 16);
    float acc = 0.f;
    for (int n = n0; n < n1; n++)
        acc += ehr[(size_t)b * NVOC + n] * node_emb[(size_t)n * NH + h];
    atomicAdd(&xacc[b * NH + h], acc);
}

__global__ void k_xnode_finish(const float* __restrict__ xacc, const float* __restrict__ den,
                               const float* __restrict__ lin_w, const float* __restrict__ lin_b,
                               float* __restrict__ xnode) {
    int b = blockIdx.x, h = threadIdx.x;
    __shared__ float t[NH];
    t[h] = xacc[b * NH + h] / den[b];
    __syncthreads();
    float s = 0.f;
#pragma unroll 8
    for (int hh = 0; hh < NH; hh++) s += t[hh] * lin_w[h * NH + hh];
    xnode[b * NH + h] = s + lin_b[h];
}

__global__ void k_final(const float* __restrict__ xg, const float* __restrict__ xn,
                        const float* __restrict__ mlp_w, const float* __restrict__ mlp_b,
                        float* __restrict__ out) {
    int b = blockIdx.x, t = threadIdx.x;
    __shared__ float s[2 * NH];
    s[t] = xg[b * NH + t];
    s[NH + t] = xn[b * NH + t];
    __syncthreads();
    if (t < NOUT) {
        float acc = mlp_b[t];
        const float* w = mlp_w + t * (2 * NH);
#pragma unroll 8
        for (int k = 0; k < 2 * NH; k++) acc += s[k] * w[k];
        out[b * NOUT + t] = acc;
    }
}

// ---------------- launch ----------------
extern "C" void kernel_launch(void* const* d_in, const int* in_sizes, int n_in,
                              void* d_out, int out_size) {
    const float* node_emb = (const float*)d_in[0];
    const float* rel_emb  = (const float*)d_in[1];
    const float* lin_w    = (const float*)d_in[2];
    const float* lin_b    = (const float*)d_in[3];
    const float* alpha_w  = (const float*)d_in[4];
    const float* alpha_b  = (const float*)d_in[5];
    const float* beta_w   = (const float*)d_in[6];
    const float* beta_b   = (const float*)d_in[7];
    const float* wr_w     = (const float*)d_in[8];
    const float* wr_b     = (const float*)d_in[9];
    const float* conv_w   = (const float*)d_in[10];
    const float* conv_b   = (const float*)d_in[11];
    const float* mlp_w    = (const float*)d_in[12];
    const float* mlp_b    = (const float*)d_in[13];
    const float* visit    = (const float*)d_in[14];
    const float* ehr      = (const float*)d_in[15];
    const int* node_ids   = (const int*)d_in[16];
    const int* rel_ids    = (const int*)d_in[17];
    const int* eidx       = (const int*)d_in[18];
    const int* batch      = (const int*)d_in[19];
    float* out = (float*)d_out;

    const int* srcArr = eidx;
    const int* dstArr = eidx + NEDGES;

    float *Zp, *Enodep, *Erelp, *wrelp, *attnp, *betap, *xp, *x2p, *aggp;
    float *xgp, *xaccp, *denp, *xnodep;
    int *degp, *rowstartp, *cursorp, *elistp, *partp, *bcntp, *bstartp;
    cudaGetSymbolAddress((void**)&Zp, g_Z);
    cudaGetSymbolAddress((void**)&Enodep, g_Enode);
    cudaGetSymbolAddress((void**)&Erelp, g_Erel);
    cudaGetSymbolAddress((void**)&wrelp, g_wrel);
    cudaGetSymbolAddress((void**)&attnp, g_attn);
    cudaGetSymbolAddress((void**)&betap, g_beta);
    cudaGetSymbolAddress((void**)&xp, g_x);
    cudaGetSymbolAddress((void**)&x2p, g_x2);
    cudaGetSymbolAddress((void**)&aggp, g_agg);
    cudaGetSymbolAddress((void**)&xgp, g_xg);
    cudaGetSymbolAddress((void**)&xaccp, g_xacc);
    cudaGetSymbolAddress((void**)&denp, g_den);
    cudaGetSymbolAddress((void**)&xnodep, g_xnode);
    cudaGetSymbolAddress((void**)&degp, g_deg);
    cudaGetSymbolAddress((void**)&rowstartp, g_rowstart);
    cudaGetSymbolAddress((void**)&cursorp, g_cursor);
    cudaGetSymbolAddress((void**)&elistp, g_elist);
    cudaGetSymbolAddress((void**)&partp, g_part);
    cudaGetSymbolAddress((void**)&bcntp, g_bcnt);
    cudaGetSymbolAddress((void**)&bstartp, g_bstart);

    const int SCAN_BLOCKS = (NNODES + 1023) / 1024;

    // #0 Enode, #1 Erel, #2 wrel
    gemm128_3xtf32<false, false><<<(NVOC + 127) / 128, 256>>>(
        node_emb, nullptr, lin_w, lin_b, Enodep, NVOC);
    gemm128_3xtf32<false, false><<<(NREL + 127) / 128, 256>>>(
        rel_emb, nullptr, lin_w, lin_b, Erelp, NREL);
    k_wrel<<<(NL * NREL * 32 + 255) / 256, 256>>>(Erelp, wr_w, wr_b, wrelp);

    // #3 alpha logits (ncu capture target)
    alpha_gemm_tf32<<<dim3((NVOC + TBN - 1) / TBN, (NBATCH * NV) / TBM, NL), 256>>>(
        visit, alpha_w, alpha_b, Zp);

    k_gather<<<(NNODES * 32 + 255) / 256, 256>>>(Enodep, node_ids, xp);
    k_beta<<<(NL * NBATCH * NV * 32 + 255) / 256, 256>>>(visit, beta_w, beta_b, betap);
    k_attn<<<dim3((NVOC + 255) / 256, NBATCH, NL), 256>>>(Zp, betap, attnp);

    // CSR build + batch offsets
    k_zero_int<<<(NNODES + 255) / 256, 256>>>(degp, NNODES);
    k_zero_int<<<1, 64>>>(bcntp, NBATCH);
    k_hist<<<(NEDGES + 255) / 256, 256>>>(dstArr, degp, NEDGES);
    k_hist_batch<<<(NNODES + 255) / 256, 256>>>(batch, bcntp);
    k_scan_block<<<SCAN_BLOCKS, 1024>>>(degp, rowstartp, partp, NNODES);
    k_scan_part<<<1, 1>>>(partp, SCAN_BLOCKS, rowstartp);
    k_scan_add<<<SCAN_BLOCKS, 1024>>>(rowstartp, partp, cursorp, NNODES);
    k_scatter<<<(NEDGES + 255) / 256, 256>>>(dstArr, cursorp, elistp, NEDGES);
    k_bscan<<<1, 1>>>(bcntp, bstartp);

    // message-passing layers
    float* xcur = xp;
    float* xalt = x2p;
    for (int l = 0; l < NL; l++) {
        k_aggregate<<<(NNODES * 32 + 255) / 256, 256>>>(
            xcur, Erelp, attnp + (size_t)l * NBATCH * NVOC, wrelp + l * NREL,
            elistp, rowstartp, srcArr, rel_ids, node_ids, batch, aggp);
        gemm128_3xtf32<true, true><<<(NNODES + 127) / 128, 256>>>(
            aggp, xcur, conv_w + (size_t)l * NH * NH, conv_b + (size_t)l * NH,
            xalt, NNODES);
        float* tmp = xcur; xcur = xalt; xalt = tmp;
    }

    // heads
    k_zero_float<<<(NBATCH * NH + 255) / 256, 256>>>(xgp, NBATCH * NH);
    k_zero_float<<<(NBATCH * NH + 255) / 256, 256>>>(xaccp, NBATCH * NH);
    k_pool_partial<<<dim3(8, NBATCH), NH>>>(xcur, bstartp, xgp);
    k_pool_finish<<<NBATCH, NH>>>(xgp, bcntp);
    k_ehrsum<<<NBATCH, 256>>>(ehr, denp);
    k_xnode_partial<<<dim3(16, NBATCH), NH>>>(ehr, node_emb, xaccp);
    k_xnode_finish<<<NBATCH, NH>>>(xaccp, denp, lin_w, lin_b, xnodep);
    k_final<<<NBATCH, NH>>>(xgp, xnodep, mlp_w, mlp_b, out);
}

// round 5
// speedup vs baseline: 2.8168x; 1.0126x over previous
#include <cuda_runtime.h>
#include <math.h>
#include <stdint.h>

#define NNODES 50000
#define NEDGES 800000
#define NBATCH 32
#define NV 20
#define NVOC 4000
#define NREL 200
#define NH 128
#define NL 3
#define NOUT 100

// ---------------- device scratch ----------------
__device__ float g_Z[(size_t)NL * NBATCH * NV * NVOC];
__device__ float g_Enode[NVOC * NH];
__device__ float g_Erel[NREL * NH];
__device__ float g_wrel[NL * NREL];
__device__ float g_attn[(size_t)NL * NBATCH * NVOC];
__device__ float g_beta[NL * NBATCH * NV];
__device__ float g_x[(size_t)NNODES * NH];
__device__ float g_x2[(size_t)NNODES * NH];
__device__ float g_agg[(size_t)NNODES * NH];
__device__ int   g_deg[NNODES];
__device__ int   g_rowstart[NNODES + 1];
__device__ int   g_cursor[NNODES];
__device__ int   g_elist[NEDGES];
__device__ int   g_part[64];
__device__ int   g_bcnt[NBATCH];
__device__ int   g_bstart[NBATCH + 1];
__device__ float g_xg[NBATCH * NH];
__device__ float g_xacc[NBATCH * NH];
__device__ float g_den[NBATCH];
__device__ float g_xnode[NBATCH * NH];

// ---------------- helpers ----------------
__device__ __forceinline__ void cp_async16(void* smem_dst, const void* gsrc, int src_size) {
    uint32_t s = (uint32_t)__cvta_generic_to_shared(smem_dst);
    asm volatile("cp.async.ca.shared.global [%0], [%1], 16, %2;\n"
                 :: "r"(s), "l"(gsrc), "r"(src_size));
}
__device__ __forceinline__ void cp_commit() { asm volatile("cp.async.commit_group;\n"); }
template <int W> __device__ __forceinline__ void cp_wait() {
    asm volatile("cp.async.wait_group %0;\n" :: "n"(W));
}
__device__ __forceinline__ uint32_t smem_u32(const void* p) {
    return (uint32_t)__cvta_generic_to_shared(p);
}
__device__ __forceinline__ void ldsm_x4(uint32_t& r0, uint32_t& r1, uint32_t& r2,
                                        uint32_t& r3, uint32_t addr) {
    asm volatile("ldmatrix.sync.aligned.m8n8.x4.shared.b16 {%0,%1,%2,%3}, [%4];"
                 : "=r"(r0), "=r"(r1), "=r"(r2), "=r"(r3) : "r"(addr));
}
__device__ __forceinline__ void split_tf32(float v, uint32_t& hi, uint32_t& lo) {
    uint32_t h;
    asm("cvt.rna.tf32.f32 %0, %1;" : "=r"(h) : "f"(v));
    float l = v - __uint_as_float(h);
    uint32_t lt;
    asm("cvt.rna.tf32.f32 %0, %1;" : "=r"(lt) : "f"(l));
    hi = h; lo = lt;
}

// ---------------- tf32 tensor-core GEMM for alpha logits ----------------
// Z[l][m][n] = sum_k visit[m,k]*alpha_w[l][n,k] + alpha_b[l][n]; M=640,N=K=4000
// ldmatrix-based fragment loads; TPAD=20 -> conflict-free LDSM phases.
#define TBM 128
#define TBN 128
#define TBK 16
#define TPAD 20

__global__ __launch_bounds__(256, 2) void alpha_gemm_tf32(
    const float* __restrict__ A,
    const float* __restrict__ Ball,
    const float* __restrict__ biasAll,
    float* __restrict__ Zall)
{
    const int M = NBATCH * NV, N = NVOC, K = NVOC;
    const int KITERS = K / TBK;

    int l = blockIdx.z;
    const float* B = Ball + (size_t)l * N * K;
    const float* bias = biasAll + (size_t)l * N;
    float* C = Zall + (size_t)l * M * N;

    __shared__ float As[2][TBM * TPAD];
    __shared__ float Bs[2][TBN * TPAD];

    int tid = threadIdx.x;
    int m0 = blockIdx.y * TBM;
    int n0 = blockIdx.x * TBN;
    int warp = tid >> 5, lane = tid & 31;
    int wm = (warp & 1) * 64;
    int wn = (warp >> 1) * 32;
    int lq = lane >> 2;
    int lr = lane & 3;
    int tile = lane >> 3, trow = lane & 7;

    float acc[4][4][4];
#pragma unroll
    for (int i = 0; i < 4; i++)
#pragma unroll
        for (int j = 0; j < 4; j++)
#pragma unroll
            for (int r = 0; r < 4; r++) acc[i][j][r] = 0.f;

#define ISSUE_TILES(stage, k0)                                                        \
    do {                                                                              \
        _Pragma("unroll")                                                             \
        for (int t = tid; t < 512; t += 256) {                                        \
            int row = t >> 2, ch = (t & 3) * 4;                                       \
            cp_async16(&As[stage][row * TPAD + ch],                                   \
                       A + (size_t)(m0 + row) * K + (k0) + ch, 16);                   \
        }                                                                             \
        _Pragma("unroll")                                                             \
        for (int t = tid; t < 512; t += 256) {                                        \
            int row = t >> 2, ch = (t & 3) * 4;                                       \
            int gn = n0 + row;                                                        \
            int ok = gn < N;                                                          \
            cp_async16(&Bs[stage][row * TPAD + ch],                                   \
                       B + (size_t)(ok ? gn : 0) * K + (k0) + ch, ok ? 16 : 0);       \
        }                                                                             \
    } while (0)

    ISSUE_TILES(0, 0);
    cp_commit();

    // LDSM address components (see fragment-map derivation):
    //  A x4 per mi: threads 0-7 (rows lo,k lo), 8-15 (rows hi,k lo),
    //               16-23 (rows lo,k hi), 24-31 (rows hi,k hi)
    int aRow = wm + ((tile & 1) << 3) + trow;
    int aKof = (tile >> 1) << 2;
    //  B x4 per ni-pair: r0=(ni,klo) r1=(ni,khi) r2=(ni+1,klo) r3=(ni+1,khi)
    int bCol = wn + ((tile >> 1) << 3) + trow;
    int bKof = (tile & 1) << 2;

    for (int kt = 0; kt < KITERS; kt++) {
        int st = kt & 1;
        if (kt + 1 < KITERS) {
            ISSUE_TILES(st ^ 1, (kt + 1) * TBK);
            cp_commit();
            cp_wait<1>();
        } else {
            cp_wait<0>();
        }
        __syncthreads();

        const float* as = As[st];
        const float* bs = Bs[st];
        uint32_t abase = smem_u32(&as[aRow * TPAD + aKof]);
        uint32_t bbase = smem_u32(&bs[bCol * TPAD + bKof]);

#pragma unroll
        for (int kk = 0; kk < TBK; kk += 8) {
            uint32_t af[4][4];
            uint32_t bf[4][2];
#pragma unroll
            for (int mi = 0; mi < 4; mi++)
                ldsm_x4(af[mi][0], af[mi][1], af[mi][2], af[mi][3],
                        abase + (kk + mi * 16 * TPAD) * 4);
#pragma unroll
            for (int np = 0; np < 2; np++)
                ldsm_x4(bf[2 * np][0], bf[2 * np][1], bf[2 * np + 1][0], bf[2 * np + 1][1],
                        bbase + (kk + np * 16 * TPAD) * 4);
#pragma unroll
            for (int mi = 0; mi < 4; mi++)
#pragma unroll
                for (int ni = 0; ni < 4; ni++) {
                    asm volatile(
                        "mma.sync.aligned.m16n8k8.row.col.f32.tf32.tf32.f32 "
                        "{%0,%1,%2,%3}, {%4,%5,%6,%7}, {%8,%9}, {%0,%1,%2,%3};\n"
                        : "+f"(acc[mi][ni][0]), "+f"(acc[mi][ni][1]),
                          "+f"(acc[mi][ni][2]), "+f"(acc[mi][ni][3])
                        : "r"(af[mi][0]), "r"(af[mi][1]), "r"(af[mi][2]), "r"(af[mi][3]),
                          "r"(bf[ni][0]), "r"(bf[ni][1]));
                }
        }
        __syncthreads();
    }

#pragma unroll
    for (int mi = 0; mi < 4; mi++) {
#pragma unroll
        for (int ni = 0; ni < 4; ni++) {
            int r = m0 + wm + mi * 16 + lq;
            int c = n0 + wn + ni * 8 + lr * 2;
            if (c < N) {
                float2 bb = *(const float2*)(bias + c);
                float2 o0, o1;
                o0.x = acc[mi][ni][0] + bb.x; o0.y = acc[mi][ni][1] + bb.y;
                o1.x = acc[mi][ni][2] + bb.x; o1.y = acc[mi][ni][3] + bb.y;
                *(float2*)(C + (size_t)r * N + c) = o0;
                *(float2*)(C + (size_t)(r + 8) * N + c) = o1;
            }
        }
    }
#undef ISSUE_TILES
}

// ---------------- 3xTF32 compensated mma GEMM: K=128, N=128 -----------------
#define CPW 36

template <bool RELU, bool ADD2>
__global__ __launch_bounds__(256) void gemm128_3xtf32(
    const float* __restrict__ A, const float* __restrict__ A2,
    const float* __restrict__ B, const float* __restrict__ bias,
    float* __restrict__ C, int M)
{
    __shared__ float As[128 * CPW];
    __shared__ float Bs[128 * CPW];

    int tid = threadIdx.x;
    int m0 = blockIdx.x * 128;
    int warp = tid >> 5, lane = tid & 31;
    int wm = (warp & 1) * 64;
    int wn = (warp >> 1) * 32;
    int lq = lane >> 2;
    int lr = lane & 3;

    float acc[4][4][4];
#pragma unroll
    for (int i = 0; i < 4; i++)
#pragma unroll
        for (int j = 0; j < 4; j++)
#pragma unroll
            for (int r = 0; r < 4; r++) acc[i][j][r] = 0.f;

    for (int k0 = 0; k0 < NH; k0 += 32) {
        __syncthreads();
#pragma unroll
        for (int t = tid; t < 1024; t += 256) {
            int row = t >> 3, seg = (t & 7) * 4;
            int gm = m0 + row;
            float4 v = {0, 0, 0, 0};
            if (gm < M) {
                v = *(const float4*)(A + (size_t)gm * NH + k0 + seg);
                if (ADD2) {
                    float4 w = *(const float4*)(A2 + (size_t)gm * NH + k0 + seg);
                    v.x += w.x; v.y += w.y; v.z += w.z; v.w += w.w;
                }
            }
            *(float4*)&As[row * CPW + seg] = v;
            *(float4*)&Bs[row * CPW + seg] = *(const float4*)(B + (size_t)row * NH + k0 + seg);
        }
        __syncthreads();

#pragma unroll
        for (int kk = 0; kk < 32; kk += 8) {
            uint32_t ah[4][4], al[4][4];
            uint32_t bh[4][2], bl[4][2];
#pragma unroll
            for (int mi = 0; mi < 4; mi++) {
                int base = (wm + mi * 16 + lq) * CPW + kk + lr;
                split_tf32(As[base],               ah[mi][0], al[mi][0]);
                split_tf32(As[base + 8 * CPW],     ah[mi][1], al[mi][1]);
                split_tf32(As[base + 4],           ah[mi][2], al[mi][2]);
                split_tf32(As[base + 8 * CPW + 4], ah[mi][3], al[mi][3]);
            }
#pragma unroll
            for (int ni = 0; ni < 4; ni++) {
                int base = (wn + ni * 8 + lq) * CPW + kk + lr;
                split_tf32(Bs[base],     bh[ni][0], bl[ni][0]);
                split_tf32(Bs[base + 4], bh[ni][1], bl[ni][1]);
            }
#define MMA_TF32(Aop, Bop)                                                            \
    asm volatile(                                                                     \
        "mma.sync.aligned.m16n8k8.row.col.f32.tf32.tf32.f32 "                         \
        "{%0,%1,%2,%3}, {%4,%5,%6,%7}, {%8,%9}, {%0,%1,%2,%3};\n"                     \
        : "+f"(acc[mi][ni][0]), "+f"(acc[mi][ni][1]),                                 \
          "+f"(acc[mi][ni][2]), "+f"(acc[mi][ni][3])                                  \
        : "r"(Aop[mi][0]), "r"(Aop[mi][1]), "r"(Aop[mi][2]), "r"(Aop[mi][3]),         \
          "r"(Bop[ni][0]), "r"(Bop[ni][1]))
#pragma unroll
            for (int mi = 0; mi < 4; mi++)
#pragma unroll
                for (int ni = 0; ni < 4; ni++) {
                    MMA_TF32(ah, bh);
                    MMA_TF32(ah, bl);
                    MMA_TF32(al, bh);
                }
#undef MMA_TF32
        }
    }

#pragma unroll
    for (int mi = 0; mi < 4; mi++) {
#pragma unroll
        for (int ni = 0; ni < 4; ni++) {
            int r = m0 + wm + mi * 16 + lq;
            int c = wn + ni * 8 + lr * 2;
            float2 bb = *(const float2*)(bias + c);
            float2 o0, o1;
            o0.x = acc[mi][ni][0] + bb.x; o0.y = acc[mi][ni][1] + bb.y;
            o1.x = acc[mi][ni][2] + bb.x; o1.y = acc[mi][ni][3] + bb.y;
            if (RELU) {
                o0.x = fmaxf(o0.x, 0.f); o0.y = fmaxf(o0.y, 0.f);
                o1.x = fmaxf(o1.x, 0.f); o1.y = fmaxf(o1.y, 0.f);
            }
            if (r < M)     *(float2*)(C + (size_t)r * NH + c) = o0;
            if (r + 8 < M) *(float2*)(C + (size_t)(r + 8) * NH + c) = o1;
        }
    }
}

// ---------------- small kernels ----------------
__global__ void k_zero_int(int* __restrict__ p, int n) {
    int i = blockIdx.x * blockDim.x + threadIdx.x;
    if (i < n) p[i] = 0;
}
__global__ void k_zero_float(float* __restrict__ p, int n) {
    int i = blockIdx.x * blockDim.x + threadIdx.x;
    if (i < n) p[i] = 0.f;
}

__global__ void k_hist(const int* __restrict__ keys, int* __restrict__ cnt, int n) {
    int i = blockIdx.x * blockDim.x + threadIdx.x;
    if (i < n) atomicAdd(&cnt[keys[i]], 1);
}

__global__ void k_hist_batch(const int* __restrict__ batch, int* __restrict__ bcnt) {
    __shared__ int h[NBATCH];
    if (threadIdx.x < NBATCH) h[threadIdx.x] = 0;
    __syncthreads();
    int i = blockIdx.x * blockDim.x + threadIdx.x;
    if (i < NNODES) atomicAdd(&h[batch[i]], 1);
    __syncthreads();
    if (threadIdx.x < NBATCH) atomicAdd(&bcnt[threadIdx.x], h[threadIdx.x]);
}

__global__ void k_scan_block(const int* __restrict__ in, int* __restrict__ outEx,
                             int* __restrict__ part, int n) {
    __shared__ int s[1024];
    int t = threadIdx.x;
    int i = blockIdx.x * 1024 + t;
    int v = (i < n) ? in[i] : 0;
    s[t] = v;
    __syncthreads();
    for (int off = 1; off < 1024; off <<= 1) {
        int y = (t >= off) ? s[t - off] : 0;
        __syncthreads();
        s[t] += y;
        __syncthreads();
    }
    if (i < n) outEx[i] = s[t] - v;
    if (t == 1023) part[blockIdx.x] = s[1023];
}

__global__ void k_scan_part(int* __restrict__ part, int nb, int* __restrict__ rowstart) {
    if (threadIdx.x == 0 && blockIdx.x == 0) {
        int acc = 0;
        for (int i = 0; i < nb; i++) { int v = part[i]; part[i] = acc; acc += v; }
        rowstart[NNODES] = NEDGES;
    }
}

__global__ void k_scan_add(int* __restrict__ rowstart, const int* __restrict__ part,
                           int* __restrict__ cursor, int n) {
    int i = blockIdx.x * 1024 + threadIdx.x;
    if (i < n) {
        int v = rowstart[i] + part[blockIdx.x];
        rowstart[i] = v;
        cursor[i] = v;
    }
}

__global__ void k_scatter(const int* __restrict__ dst, int* __restrict__ cursor,
                          int* __restrict__ elist, int n) {
    int e = blockIdx.x * blockDim.x + threadIdx.x;
    if (e < n) {
        int d = dst[e];
        int p = atomicAdd(&cursor[d], 1);
        elist[p] = e;
    }
}

__global__ void k_bscan(const int* __restrict__ bcnt, int* __restrict__ bstart) {
    if (threadIdx.x == 0 && blockIdx.x == 0) {
        int acc = 0;
        for (int b = 0; b < NBATCH; b++) { bstart[b] = acc; acc += bcnt[b]; }
        bstart[NBATCH] = acc;
    }
}

__global__ void k_wrel(const float* __restrict__ Erel, const float* __restrict__ wr_w,
                       const float* __restrict__ wr_b, float* __restrict__ wrel) {
    int w = (blockIdx.x * blockDim.x + threadIdx.x) >> 5;
    int lane = threadIdx.x & 31;
    if (w >= NL * NREL) return;
    int l = w / NREL, r = w % NREL;
    float acc = 0.f;
#pragma unroll
    for (int h = lane; h < NH; h += 32) acc += Erel[r * NH + h] * wr_w[l * NH + h];
#pragma unroll
    for (int o = 16; o; o >>= 1) acc += __shfl_down_sync(0xffffffffu, acc, o);
    if (lane == 0) wrel[w] = acc + wr_b[l];
}

__global__ void k_gather(const float* __restrict__ Enode, const int* __restrict__ node_ids,
                         float* __restrict__ x) {
    int t = blockIdx.x * blockDim.x + threadIdx.x;
    if (t >= NNODES * 32) return;
    int i = t >> 5, q = t & 31;
    int nid = node_ids[i];
    *(float4*)(x + (size_t)i * NH + q * 4) =
        *(const float4*)(Enode + (size_t)nid * NH + q * 4);
}

__global__ void k_beta(const float* __restrict__ vn, const float* __restrict__ beta_w,
                       const float* __restrict__ beta_b, float* __restrict__ betaOut) {
    int w = (blockIdx.x * blockDim.x + threadIdx.x) >> 5;
    int lane = threadIdx.x & 31;
    if (w >= NL * NBATCH * NV) return;
    int l = w / (NBATCH * NV);
    int rem = w % (NBATCH * NV);
    int b = rem / NV, v = rem % NV;
    const float* row = vn + ((size_t)b * NV + v) * NVOC;
    const float* bw = beta_w + l * NVOC;
    float acc = 0.f;
    for (int n = lane; n < NVOC; n += 32) acc += row[n] * bw[n];
#pragma unroll
    for (int o = 16; o; o >>= 1) acc += __shfl_down_sync(0xffffffffu, acc, o);
    if (lane == 0)
        betaOut[w] = tanhf(acc + beta_b[l]) * expf(0.03f * (float)(NV - v));
}

__global__ void k_attn(const float* __restrict__ Zall, const float* __restrict__ betaAll,
                       float* __restrict__ attnAll) {
    int m = blockIdx.x * blockDim.x + threadIdx.x;
    int b = blockIdx.y;
    int l = blockIdx.z;
    if (m >= NVOC) return;
    const float* Z = Zall + (size_t)l * NBATCH * NV * NVOC;
    const float* betaL = betaAll + l * NBATCH * NV;
    float z[NV];
    float mx = -1e30f;
#pragma unroll
    for (int v = 0; v < NV; v++) {
        z[v] = Z[((size_t)(b * NV + v)) * NVOC + m];
        mx = fmaxf(mx, z[v]);
    }
    float s = 0.f, num = 0.f;
#pragma unroll
    for (int v = 0; v < NV; v++) {
        float e = expf(z[v] - mx);
        s += e;
        num += e * betaL[b * NV + v];
    }
    attnAll[((size_t)l * NBATCH + b) * NVOC + m] = num / s;
}

// persistent aggregate: (wrel*Erel) cached in smem, lane-parallel edge meta
#define AGG_BLOCKS 296
#define AGG_SMEM (NREL * NH * 4)

__global__ __launch_bounds__(256) void k_aggregate_smem(
    const float* __restrict__ x, const float* __restrict__ Erel,
    const float* __restrict__ attnL, const float* __restrict__ wrelL,
    const int* __restrict__ elist, const int* __restrict__ rowstart,
    const int* __restrict__ srcArr, const int* __restrict__ ridArr,
    const int* __restrict__ nodeIds, const int* __restrict__ batchArr,
    float* __restrict__ agg)
{
    extern __shared__ float sE[];   // NREL*NH premultiplied by wrel
    int tid = threadIdx.x;
    int warp = tid >> 5, lane = tid & 31;

    for (int i = tid; i < NREL * (NH / 4); i += 256) {
        int r = i >> 5;
        float w = wrelL[r];
        float4 v = ((const float4*)Erel)[i];
        v.x *= w; v.y *= w; v.z *= w; v.w *= w;
        ((float4*)sE)[i] = v;
    }
    __syncthreads();

    int gw = blockIdx.x * 8 + warp;
    int nw = gridDim.x * 8;
    for (int node = gw; node < NNODES; node += nw) {
        int s0 = rowstart[node], s1 = rowstart[node + 1];
        float4 acc = {0.f, 0.f, 0.f, 0.f};
        for (int base = s0; base < s1; base += 32) {
            int m = s1 - base; if (m > 32) m = 32;
            int sidx = 0, rid = 0;
            float ea = 0.f;
            if (lane < m) {
                int e = elist[base + lane];
                sidx = srcArr[e];
                rid = ridArr[e];
                ea = attnL[(size_t)batchArr[sidx] * NVOC + nodeIds[sidx]];
            }
#pragma unroll 4
            for (int j = 0; j < m; j++) {
                int sj = __shfl_sync(0xffffffffu, sidx, j);
                int rj = __shfl_sync(0xffffffffu, rid, j);
                float eaj = __shfl_sync(0xffffffffu, ea, j);
                float4 xv = *(const float4*)(x + (size_t)sj * NH + lane * 4);
                float4 ev = *(const float4*)(sE + rj * NH + lane * 4);
                acc.x += fmaxf(fmaf(xv.x, eaj, ev.x), 0.f);
                acc.y += fmaxf(fmaf(xv.y, eaj, ev.y), 0.f);
                acc.z += fmaxf(fmaf(xv.z, eaj, ev.z), 0.f);
                acc.w += fmaxf(fmaf(xv.w, eaj, ev.w), 0.f);
            }
        }
        *(float4*)(agg + (size_t)node * NH + lane * 4) = acc;
    }
}

__global__ void k_pool_partial(const float* __restrict__ x, const int* __restrict__ bstart,
                               float* __restrict__ xg) {
    int b = blockIdx.y, chunk = blockIdx.x, h = threadIdx.x;
    int s0 = bstart[b], s1 = bstart[b + 1];
    int len = s1 - s0;
    int r0 = s0 + (int)((long long)len * chunk / 8);
    int r1 = s0 + (int)((long long)len * (chunk + 1) / 8);
    float acc = 0.f;
    for (int i = r0; i < r1; i++) acc += x[(size_t)i * NH + h];
    atomicAdd(&xg[b * NH + h], acc);
}

__global__ void k_pool_finish(float* __restrict__ xg, const int* __restrict__ bcnt) {
    int b = blockIdx.x, h = threadIdx.x;
    float c = (float)bcnt[b];
    xg[b * NH + h] /= fmaxf(c, 1.f);
}

__global__ void k_ehrsum(const float* __restrict__ ehr, float* __restrict__ den) {
    int b = blockIdx.x, t = threadIdx.x;
    __shared__ float s[256];
    float acc = 0.f;
    for (int n = t; n < NVOC; n += 256) acc += ehr[(size_t)b * NVOC + n];
    s[t] = acc;
    __syncthreads();
    for (int o = 128; o; o >>= 1) {
        if (t < o) s[t] += s[t + o];
        __syncthreads();
    }
    if (t == 0) den[b] = s[0];
}

__global__ void k_xnode_partial(const float* __restrict__ ehr,
                                const float* __restrict__ node_emb,
                                float* __restrict__ xacc) {
    int b = blockIdx.y, slice = blockIdx.x, h = threadIdx.x;
    int n0 = slice * (NVOC / 16), n1 = n0 + (NVOC / 16);
    float acc = 0.f;
    for (int n = n0; n < n1; n++)
        acc += ehr[(size_t)b * NVOC + n] * node_emb[(size_t)n * NH + h];
    atomicAdd(&xacc[b * NH + h], acc);
}

__global__ void k_xnode_finish(const float* __restrict__ xacc, const float* __restrict__ den,
                               const float* __restrict__ lin_w, const float* __restrict__ lin_b,
                               float* __restrict__ xnode) {
    int b = blockIdx.x, h = threadIdx.x;
    __shared__ float t[NH];
    t[h] = xacc[b * NH + h] / den[b];
    __syncthreads();
    float s = 0.f;
#pragma unroll 8
    for (int hh = 0; hh < NH; hh++) s += t[hh] * lin_w[h * NH + hh];
    xnode[b * NH + h] = s + lin_b[h];
}

__global__ void k_final(const float* __restrict__ xg, const float* __restrict__ xn,
                        const float* __restrict__ mlp_w, const float* __restrict__ mlp_b,
                        float* __restrict__ out) {
    int b = blockIdx.x, t = threadIdx.x;
    __shared__ float s[2 * NH];
    s[t] = xg[b * NH + t];
    s[NH + t] = xn[b * NH + t];
    __syncthreads();
    if (t < NOUT) {
        float acc = mlp_b[t];
        const float* w = mlp_w + t * (2 * NH);
#pragma unroll 8
        for (int k = 0; k < 2 * NH; k++) acc += s[k] * w[k];
        out[b * NOUT + t] = acc;
    }
}

// ---------------- launch ----------------
extern "C" void kernel_launch(void* const* d_in, const int* in_sizes, int n_in,
                              void* d_out, int out_size) {
    const float* node_emb = (const float*)d_in[0];
    const float* rel_emb  = (const float*)d_in[1];
    const float* lin_w    = (const float*)d_in[2];
    const float* lin_b    = (const float*)d_in[3];
    const float* alpha_w  = (const float*)d_in[4];
    const float* alpha_b  = (const float*)d_in[5];
    const float* beta_w   = (const float*)d_in[6];
    const float* beta_b   = (const float*)d_in[7];
    const float* wr_w     = (const float*)d_in[8];
    const float* wr_b     = (const float*)d_in[9];
    const float* conv_w   = (const float*)d_in[10];
    const float* conv_b   = (const float*)d_in[11];
    const float* mlp_w    = (const float*)d_in[12];
    const float* mlp_b    = (const float*)d_in[13];
    const float* visit    = (const float*)d_in[14];
    const float* ehr      = (const float*)d_in[15];
    const int* node_ids   = (const int*)d_in[16];
    const int* rel_ids    = (const int*)d_in[17];
    const int* eidx       = (const int*)d_in[18];
    const int* batch      = (const int*)d_in[19];
    float* out = (float*)d_out;

    const int* srcArr = eidx;
    const int* dstArr = eidx + NEDGES;

    float *Zp, *Enodep, *Erelp, *wrelp, *attnp, *betap, *xp, *x2p, *aggp;
    float *xgp, *xaccp, *denp, *xnodep;
    int *degp, *rowstartp, *cursorp, *elistp, *partp, *bcntp, *bstartp;
    cudaGetSymbolAddress((void**)&Zp, g_Z);
    cudaGetSymbolAddress((void**)&Enodep, g_Enode);
    cudaGetSymbolAddress((void**)&Erelp, g_Erel);
    cudaGetSymbolAddress((void**)&wrelp, g_wrel);
    cudaGetSymbolAddress((void**)&attnp, g_attn);
    cudaGetSymbolAddress((void**)&betap, g_beta);
    cudaGetSymbolAddress((void**)&xp, g_x);
    cudaGetSymbolAddress((void**)&x2p, g_x2);
    cudaGetSymbolAddress((void**)&aggp, g_agg);
    cudaGetSymbolAddress((void**)&xgp, g_xg);
    cudaGetSymbolAddress((void**)&xaccp, g_xacc);
    cudaGetSymbolAddress((void**)&denp, g_den);
    cudaGetSymbolAddress((void**)&xnodep, g_xnode);
    cudaGetSymbolAddress((void**)&degp, g_deg);
    cudaGetSymbolAddress((void**)&rowstartp, g_rowstart);
    cudaGetSymbolAddress((void**)&cursorp, g_cursor);
    cudaGetSymbolAddress((void**)&elistp, g_elist);
    cudaGetSymbolAddress((void**)&partp, g_part);
    cudaGetSymbolAddress((void**)&bcntp, g_bcnt);
    cudaGetSymbolAddress((void**)&bstartp, g_bstart);

    cudaFuncSetAttribute(k_aggregate_smem,
                         cudaFuncAttributeMaxDynamicSharedMemorySize, AGG_SMEM);

    const int SCAN_BLOCKS = (NNODES + 1023) / 1024;

    // #0 Enode, #1 Erel, #2 wrel
    gemm128_3xtf32<false, false><<<(NVOC + 127) / 128, 256>>>(
        node_emb, nullptr, lin_w, lin_b, Enodep, NVOC);
    gemm128_3xtf32<false, false><<<(NREL + 127) / 128, 256>>>(
        rel_emb, nullptr, lin_w, lin_b, Erelp, NREL);
    k_wrel<<<(NL * NREL * 32 + 255) / 256, 256>>>(Erelp, wr_w, wr_b, wrelp);

    // #3 alpha logits (ncu capture target)
    alpha_gemm_tf32<<<dim3((NVOC + TBN - 1) / TBN, (NBATCH * NV) / TBM, NL), 256>>>(
        visit, alpha_w, alpha_b, Zp);

    k_gather<<<(NNODES * 32 + 255) / 256, 256>>>(Enodep, node_ids, xp);
    k_beta<<<(NL * NBATCH * NV * 32 + 255) / 256, 256>>>(visit, beta_w, beta_b, betap);
    k_attn<<<dim3((NVOC + 255) / 256, NBATCH, NL), 256>>>(Zp, betap, attnp);

    // CSR build + batch offsets
    k_zero_int<<<(NNODES + 255) / 256, 256>>>(degp, NNODES);
    k_zero_int<<<1, 64>>>(bcntp, NBATCH);
    k_hist<<<(NEDGES + 255) / 256, 256>>>(dstArr, degp, NEDGES);
    k_hist_batch<<<(NNODES + 255) / 256, 256>>>(batch, bcntp);
    k_scan_block<<<SCAN_BLOCKS, 1024>>>(degp, rowstartp, partp, NNODES);
    k_scan_part<<<1, 1>>>(partp, SCAN_BLOCKS, rowstartp);
    k_scan_add<<<SCAN_BLOCKS, 1024>>>(rowstartp, partp, cursorp, NNODES);
    k_scatter<<<(NEDGES + 255) / 256, 256>>>(dstArr, cursorp, elistp, NEDGES);
    k_bscan<<<1, 1>>>(bcntp, bstartp);

    // message-passing layers
    float* xcur = xp;
    float* xalt = x2p;
    for (int l = 0; l < NL; l++) {
        k_aggregate_smem<<<AGG_BLOCKS, 256, AGG_SMEM>>>(
            xcur, Erelp, attnp + (size_t)l * NBATCH * NVOC, wrelp + l * NREL,
            elistp, rowstartp, srcArr, rel_ids, node_ids, batch, aggp);
        gemm128_3xtf32<true, true><<<(NNODES + 127) / 128, 256>>>(
            aggp, xcur, conv_w + (size_t)l * NH * NH, conv_b + (size_t)l * NH,
            xalt, NNODES);
        float* tmp = xcur; xcur = xalt; xalt = tmp;
    }

    // heads
    k_zero_float<<<(NBATCH * NH + 255) / 256, 256>>>(xgp, NBATCH * NH);
    k_zero_float<<<(NBATCH * NH + 255) / 256, 256>>>(xaccp, NBATCH * NH);
    k_pool_partial<<<dim3(8, NBATCH), NH>>>(xcur, bstartp, xgp);
    k_pool_finish<<<NBATCH, NH>>>(xgp, bcntp);
    k_ehrsum<<<NBATCH, 256>>>(ehr, denp);
    k_xnode_partial<<<dim3(16, NBATCH), NH>>>(ehr, node_emb, xaccp);
    k_xnode_finish<<<NBATCH, NH>>>(xaccp, denp, lin_w, lin_b, xnodep);
    k_final<<<NBATCH, NH>>>(xgp, xnodep, mlp_w, mlp_b, out);
}

// round 7
// speedup vs baseline: 3.0399x; 1.0792x over previous
#include <cuda_runtime.h>
#include <math.h>
#include <stdint.h>

#define NNODES 50000
#define NEDGES 800000
#define NBATCH 32
#define NV 20
#define NVOC 4000
#define NREL 200
#define NH 128
#define NL 3
#define NOUT 100

// ---------------- device scratch ----------------
__device__ float g_Z[(size_t)NL * NBATCH * NV * NVOC];
__device__ float g_Enode[NVOC * NH];
__device__ float g_Erel[NREL * NH];
__device__ float g_wrel[NL * NREL];
__device__ float g_attn[(size_t)NL * NBATCH * NVOC];
__device__ float g_beta[NL * NBATCH * NV];
__device__ float g_x[(size_t)NNODES * NH];
__device__ float g_x2[(size_t)NNODES * NH];
__device__ float g_agg[(size_t)NNODES * NH];
__device__ int   g_deg[NNODES];
__device__ int   g_rowstart[NNODES + 1];
__device__ int   g_cursor[NNODES];
__device__ int   g_elist[NEDGES];
__device__ int   g_part[64];
__device__ int   g_bcnt[NBATCH];
__device__ int   g_bstart[NBATCH + 1];
__device__ float g_xg[NBATCH * NH];
__device__ float g_xacc[NBATCH * NH];
__device__ float g_den[NBATCH];
__device__ float g_xnode[NBATCH * NH];

// ---------------- helpers ----------------
__device__ __forceinline__ void cp_async16(void* smem_dst, const void* gsrc, int src_size) {
    uint32_t s = (uint32_t)__cvta_generic_to_shared(smem_dst);
    asm volatile("cp.async.ca.shared.global [%0], [%1], 16, %2;\n"
                 :: "r"(s), "l"(gsrc), "r"(src_size));
}
__device__ __forceinline__ void cp_commit() { asm volatile("cp.async.commit_group;\n"); }
template <int W> __device__ __forceinline__ void cp_wait() {
    asm volatile("cp.async.wait_group %0;\n" :: "n"(W));
}
__device__ __forceinline__ uint32_t smem_u32(const void* p) {
    return (uint32_t)__cvta_generic_to_shared(p);
}
__device__ __forceinline__ void ldsm_x4(uint32_t& r0, uint32_t& r1, uint32_t& r2,
                                        uint32_t& r3, uint32_t addr) {
    asm volatile("ldmatrix.sync.aligned.m8n8.x4.shared.b16 {%0,%1,%2,%3}, [%4];"
                 : "=r"(r0), "=r"(r1), "=r"(r2), "=r"(r3) : "r"(addr));
}
__device__ __forceinline__ void split_tf32(float v, uint32_t& hi, uint32_t& lo) {
    uint32_t h;
    asm("cvt.rna.tf32.f32 %0, %1;" : "=r"(h) : "f"(v));
    float l = v - __uint_as_float(h);
    uint32_t lt;
    asm("cvt.rna.tf32.f32 %0, %1;" : "=r"(lt) : "f"(l));
    hi = h; lo = lt;
}

// ---------------- tf32 tensor-core GEMM for alpha logits ----------------
// Z[l][m][n] = sum_k visit[m,k]*alpha_w[l][n,k] + alpha_b[l][n]; M=640,N=K=4000
// ldmatrix fragment loads + 3-stage cp.async ring (dynamic smem).
#define TBM 128
#define TBN 128
#define TBK 16
#define TPAD 20
#define NSTAGE 3
#define ATILE (TBM * TPAD)
#define ALPHA_SMEM (NSTAGE * ATILE * 2 * 4)

__global__ __launch_bounds__(256, 2) void alpha_gemm_tf32(
    const float* __restrict__ A,
    const float* __restrict__ Ball,
    const float* __restrict__ biasAll,
    float* __restrict__ Zall)
{
    const int M = NBATCH * NV, N = NVOC, K = NVOC;
    const int KITERS = K / TBK;

    int l = blockIdx.z;
    const float* B = Ball + (size_t)l * N * K;
    const float* bias = biasAll + (size_t)l * N;
    float* C = Zall + (size_t)l * M * N;

    extern __shared__ float sh[];
    float* Asb = sh;                       // [NSTAGE][ATILE]
    float* Bsb = sh + NSTAGE * ATILE;      // [NSTAGE][ATILE]

    int tid = threadIdx.x;
    int m0 = blockIdx.y * TBM;
    int n0 = blockIdx.x * TBN;
    int warp = tid >> 5, lane = tid & 31;
    int wm = (warp & 1) * 64;
    int wn = (warp >> 1) * 32;
    int lq = lane >> 2;
    int lr = lane & 3;
    int tile = lane >> 3, trow = lane & 7;

    float acc[4][4][4];
#pragma unroll
    for (int i = 0; i < 4; i++)
#pragma unroll
        for (int j = 0; j < 4; j++)
#pragma unroll
            for (int r = 0; r < 4; r++) acc[i][j][r] = 0.f;

#define ISSUE_TILES(stage, k0)                                                        \
    do {                                                                              \
        float* Asp = Asb + (stage) * ATILE;                                           \
        float* Bsp = Bsb + (stage) * ATILE;                                           \
        _Pragma("unroll")                                                             \
        for (int t = tid; t < 512; t += 256) {                                        \
            int row = t >> 2, ch = (t & 3) * 4;                                       \
            cp_async16(&Asp[row * TPAD + ch],                                         \
                       A + (size_t)(m0 + row) * K + (k0) + ch, 16);                   \
        }                                                                             \
        _Pragma("unroll")                                                             \
        for (int t = tid; t < 512; t += 256) {                                        \
            int row = t >> 2, ch = (t & 3) * 4;                                       \
            int gn = n0 + row;                                                        \
            int ok = gn < N;                                                          \
            cp_async16(&Bsp[row * TPAD + ch],                                         \
                       B + (size_t)(ok ? gn : 0) * K + (k0) + ch, ok ? 16 : 0);       \
        }                                                                             \
    } while (0)

    ISSUE_TILES(0, 0);
    cp_commit();
    ISSUE_TILES(1, TBK);
    cp_commit();

    // LDSM address components:
    int aRow = wm + ((tile & 1) << 3) + trow;
    int aKof = (tile >> 1) << 2;
    int bCol = wn + ((tile >> 1) << 3) + trow;
    int bKof = (tile & 1) << 2;

    int st = 0;
    for (int kt = 0; kt < KITERS; kt++) {
        cp_wait<1>();
        __syncthreads();
        if (kt + 2 < KITERS) {
            int nst = st + 2; if (nst >= NSTAGE) nst -= NSTAGE;
            ISSUE_TILES(nst, (kt + 2) * TBK);
            cp_commit();
        }

        const float* as = Asb + st * ATILE;
        const float* bs = Bsb + st * ATILE;
        uint32_t abase = smem_u32(&as[aRow * TPAD + aKof]);
        uint32_t bbase = smem_u32(&bs[bCol * TPAD + bKof]);

#pragma unroll
        for (int kk = 0; kk < TBK; kk += 8) {
            uint32_t af[4][4];
            uint32_t bf[4][2];
#pragma unroll
            for (int mi = 0; mi < 4; mi++)
                ldsm_x4(af[mi][0], af[mi][1], af[mi][2], af[mi][3],
                        abase + (kk + mi * 16 * TPAD) * 4);
#pragma unroll
            for (int np = 0; np < 2; np++)
                ldsm_x4(bf[2 * np][0], bf[2 * np][1], bf[2 * np + 1][0], bf[2 * np + 1][1],
                        bbase + (kk + np * 16 * TPAD) * 4);
#pragma unroll
            for (int mi = 0; mi < 4; mi++)
#pragma unroll
                for (int ni = 0; ni < 4; ni++) {
                    asm volatile(
                        "mma.sync.aligned.m16n8k8.row.col.f32.tf32.tf32.f32 "
                        "{%0,%1,%2,%3}, {%4,%5,%6,%7}, {%8,%9}, {%0,%1,%2,%3};\n"
                        : "+f"(acc[mi][ni][0]), "+f"(acc[mi][ni][1]),
                          "+f"(acc[mi][ni][2]), "+f"(acc[mi][ni][3])
                        : "r"(af[mi][0]), "r"(af[mi][1]), "r"(af[mi][2]), "r"(af[mi][3]),
                          "r"(bf[ni][0]), "r"(bf[ni][1]));
                }
        }
        if (++st >= NSTAGE) st = 0;
    }

#pragma unroll
    for (int mi = 0; mi < 4; mi++) {
#pragma unroll
        for (int ni = 0; ni < 4; ni++) {
            int r = m0 + wm + mi * 16 + lq;
            int c = n0 + wn + ni * 8 + lr * 2;
            if (c < N) {
                float2 bb = *(const float2*)(bias + c);
                float2 o0, o1;
                o0.x = acc[mi][ni][0] + bb.x; o0.y = acc[mi][ni][1] + bb.y;
                o1.x = acc[mi][ni][2] + bb.x; o1.y = acc[mi][ni][3] + bb.y;
                *(float2*)(C + (size_t)r * N + c) = o0;
                *(float2*)(C + (size_t)(r + 8) * N + c) = o1;
            }
        }
    }
#undef ISSUE_TILES
}

// ---------------- 3xTF32 compensated mma GEMM: K=128, N=128 -----------------
#define CPW 36

template <bool RELU, bool ADD2>
__global__ __launch_bounds__(256) void gemm128_3xtf32(
    const float* __restrict__ A, const float* __restrict__ A2,
    const float* __restrict__ B, const float* __restrict__ bias,
    float* __restrict__ C, int M)
{
    __shared__ float As[128 * CPW];
    __shared__ float Bs[128 * CPW];

    int tid = threadIdx.x;
    int m0 = blockIdx.x * 128;
    int warp = tid >> 5, lane = tid & 31;
    int wm = (warp & 1) * 64;
    int wn = (warp >> 1) * 32;
    int lq = lane >> 2;
    int lr = lane & 3;

    float acc[4][4][4];
#pragma unroll
    for (int i = 0; i < 4; i++)
#pragma unroll
        for (int j = 0; j < 4; j++)
#pragma unroll
            for (int r = 0; r < 4; r++) acc[i][j][r] = 0.f;

    for (int k0 = 0; k0 < NH; k0 += 32) {
        __syncthreads();
#pragma unroll
        for (int t = tid; t < 1024; t += 256) {
            int row = t >> 3, seg = (t & 7) * 4;
            int gm = m0 + row;
            float4 v = {0, 0, 0, 0};
            if (gm < M) {
                v = *(const float4*)(A + (size_t)gm * NH + k0 + seg);
                if (ADD2) {
                    float4 w = *(const float4*)(A2 + (size_t)gm * NH + k0 + seg);
                    v.x += w.x; v.y += w.y; v.z += w.z; v.w += w.w;
                }
            }
            *(float4*)&As[row * CPW + seg] = v;
            *(float4*)&Bs[row * CPW + seg] = *(const float4*)(B + (size_t)row * NH + k0 + seg);
        }
        __syncthreads();

#pragma unroll
        for (int kk = 0; kk < 32; kk += 8) {
            uint32_t ah[4][4], al[4][4];
            uint32_t bh[4][2], bl[4][2];
#pragma unroll
            for (int mi = 0; mi < 4; mi++) {
                int base = (wm + mi * 16 + lq) * CPW + kk + lr;
                split_tf32(As[base],               ah[mi][0], al[mi][0]);
                split_tf32(As[base + 8 * CPW],     ah[mi][1], al[mi][1]);
                split_tf32(As[base + 4],           ah[mi][2], al[mi][2]);
                split_tf32(As[base + 8 * CPW + 4], ah[mi][3], al[mi][3]);
            }
#pragma unroll
            for (int ni = 0; ni < 4; ni++) {
                int base = (wn + ni * 8 + lq) * CPW + kk + lr;
                split_tf32(Bs[base],     bh[ni][0], bl[ni][0]);
                split_tf32(Bs[base + 4], bh[ni][1], bl[ni][1]);
            }
#define MMA_TF32(Aop, Bop)                                                            \
    asm volatile(                                                                     \
        "mma.sync.aligned.m16n8k8.row.col.f32.tf32.tf32.f32 "                         \
        "{%0,%1,%2,%3}, {%4,%5,%6,%7}, {%8,%9}, {%0,%1,%2,%3};\n"                     \
        : "+f"(acc[mi][ni][0]), "+f"(acc[mi][ni][1]),                                 \
          "+f"(acc[mi][ni][2]), "+f"(acc[mi][ni][3])                                  \
        : "r"(Aop[mi][0]), "r"(Aop[mi][1]), "r"(Aop[mi][2]), "r"(Aop[mi][3]),         \
          "r"(Bop[ni][0]), "r"(Bop[ni][1]))
#pragma unroll
            for (int mi = 0; mi < 4; mi++)
#pragma unroll
                for (int ni = 0; ni < 4; ni++) {
                    MMA_TF32(ah, bh);
                    MMA_TF32(ah, bl);
                    MMA_TF32(al, bh);
                }
#undef MMA_TF32
        }
    }

#pragma unroll
    for (int mi = 0; mi < 4; mi++) {
#pragma unroll
        for (int ni = 0; ni < 4; ni++) {
            int r = m0 + wm + mi * 16 + lq;
            int c = wn + ni * 8 + lr * 2;
            float2 bb = *(const float2*)(bias + c);
            float2 o0, o1;
            o0.x = acc[mi][ni][0] + bb.x; o0.y = acc[mi][ni][1] + bb.y;
            o1.x = acc[mi][ni][2] + bb.x; o1.y = acc[mi][ni][3] + bb.y;
            if (RELU) {
                o0.x = fmaxf(o0.x, 0.f); o0.y = fmaxf(o0.y, 0.f);
                o1.x = fmaxf(o1.x, 0.f); o1.y = fmaxf(o1.y, 0.f);
            }
            if (r < M)     *(float2*)(C + (size_t)r * NH + c) = o0;
            if (r + 8 < M) *(float2*)(C + (size_t)(r + 8) * NH + c) = o1;
        }
    }
}

// ---------------- small kernels ----------------
__global__ void k_zero_int(int* __restrict__ p, int n) {
    int i = blockIdx.x * blockDim.x + threadIdx.x;
    if (i < n) p[i] = 0;
}
__global__ void k_zero_float(float* __restrict__ p, int n) {
    int i = blockIdx.x * blockDim.x + threadIdx.x;
    if (i < n) p[i] = 0.f;
}

__global__ void k_hist(const int* __restrict__ keys, int* __restrict__ cnt, int n) {
    int i = blockIdx.x * blockDim.x + threadIdx.x;
    if (i < n) atomicAdd(&cnt[keys[i]], 1);
}

__global__ void k_hist_batch(const int* __restrict__ batch, int* __restrict__ bcnt) {
    __shared__ int h[NBATCH];
    if (threadIdx.x < NBATCH) h[threadIdx.x] = 0;
    __syncthreads();
    int i = blockIdx.x * blockDim.x + threadIdx.x;
    if (i < NNODES) atomicAdd(&h[batch[i]], 1);
    __syncthreads();
    if (threadIdx.x < NBATCH) atomicAdd(&bcnt[threadIdx.x], h[threadIdx.x]);
}

__global__ void k_scan_block(const int* __restrict__ in, int* __restrict__ outEx,
                             int* __restrict__ part, int n) {
    __shared__ int s[1024];
    int t = threadIdx.x;
    int i = blockIdx.x * 1024 + t;
    int v = (i < n) ? in[i] : 0;
    s[t] = v;
    __syncthreads();
    for (int off = 1; off < 1024; off <<= 1) {
        int y = (t >= off) ? s[t - off] : 0;
        __syncthreads();
        s[t] += y;
        __syncthreads();
    }
    if (i < n) outEx[i] = s[t] - v;
    if (t == 1023) part[blockIdx.x] = s[1023];
}

__global__ void k_scan_part(int* __restrict__ part, int nb, int* __restrict__ rowstart) {
    if (threadIdx.x == 0 && blockIdx.x == 0) {
        int acc = 0;
        for (int i = 0; i < nb; i++) { int v = part[i]; part[i] = acc; acc += v; }
        rowstart[NNODES] = NEDGES;
    }
}

__global__ void k_scan_add(int* __restrict__ rowstart, const int* __restrict__ part,
                           int* __restrict__ cursor, int n) {
    int i = blockIdx.x * 1024 + threadIdx.x;
    if (i < n) {
        int v = rowstart[i] + part[blockIdx.x];
        rowstart[i] = v;
        cursor[i] = v;
    }
}

__global__ void k_scatter(const int* __restrict__ dst, int* __restrict__ cursor,
                          int* __restrict__ elist, int n) {
    int e = blockIdx.x * blockDim.x + threadIdx.x;
    if (e < n) {
        int d = dst[e];
        int p = atomicAdd(&cursor[d], 1);
        elist[p] = e;
    }
}

__global__ void k_bscan(const int* __restrict__ bcnt, int* __restrict__ bstart) {
    if (threadIdx.x == 0 && blockIdx.x == 0) {
        int acc = 0;
        for (int b = 0; b < NBATCH; b++) { bstart[b] = acc; acc += bcnt[b]; }
        bstart[NBATCH] = acc;
    }
}

__global__ void k_wrel(const float* __restrict__ Erel, const float* __restrict__ wr_w,
                       const float* __restrict__ wr_b, float* __restrict__ wrel) {
    int w = (blockIdx.x * blockDim.x + threadIdx.x) >> 5;
    int lane = threadIdx.x & 31;
    if (w >= NL * NREL) return;
    int l = w / NREL, r = w % NREL;
    float acc = 0.f;
#pragma unroll
    for (int h = lane; h < NH; h += 32) acc += Erel[r * NH + h] * wr_w[l * NH + h];
#pragma unroll
    for (int o = 16; o; o >>= 1) acc += __shfl_down_sync(0xffffffffu, acc, o);
    if (lane == 0) wrel[w] = acc + wr_b[l];
}

__global__ void k_gather(const float* __restrict__ Enode, const int* __restrict__ node_ids,
                         float* __restrict__ x) {
    int t = blockIdx.x * blockDim.x + threadIdx.x;
    if (t >= NNODES * 32) return;
    int i = t >> 5, q = t & 31;
    int nid = node_ids[i];
    *(float4*)(x + (size_t)i * NH + q * 4) =
        *(const float4*)(Enode + (size_t)nid * NH + q * 4);
}

__global__ void k_beta(const float* __restrict__ vn, const float* __restrict__ beta_w,
                       const float* __restrict__ beta_b, float* __restrict__ betaOut) {
    int w = (blockIdx.x * blockDim.x + threadIdx.x) >> 5;
    int lane = threadIdx.x & 31;
    if (w >= NL * NBATCH * NV) return;
    int l = w / (NBATCH * NV);
    int rem = w % (NBATCH * NV);
    int b = rem / NV, v = rem % NV;
    const float* row = vn + ((size_t)b * NV + v) * NVOC;
    const float* bw = beta_w + l * NVOC;
    float acc = 0.f;
    for (int n = lane; n < NVOC; n += 32) acc += row[n] * bw[n];
#pragma unroll
    for (int o = 16; o; o >>= 1) acc += __shfl_down_sync(0xffffffffu, acc, o);
    if (lane == 0)
        betaOut[w] = tanhf(acc + beta_b[l]) * expf(0.03f * (float)(NV - v));
}

__global__ void k_attn(const float* __restrict__ Zall, const float* __restrict__ betaAll,
                       float* __restrict__ attnAll) {
    int m = blockIdx.x * blockDim.x + threadIdx.x;
    int b = blockIdx.y;
    int l = blockIdx.z;
    if (m >= NVOC) return;
    const float* Z = Zall + (size_t)l * NBATCH * NV * NVOC;
    const float* betaL = betaAll + l * NBATCH * NV;
    float z[NV];
    float mx = -1e30f;
#pragma unroll
    for (int v = 0; v < NV; v++) {
        z[v] = Z[((size_t)(b * NV + v)) * NVOC + m];
        mx = fmaxf(mx, z[v]);
    }
    float s = 0.f, num = 0.f;
#pragma unroll
    for (int v = 0; v < NV; v++) {
        float e = expf(z[v] - mx);
        s += e;
        num += e * betaL[b * NV + v];
    }
    attnAll[((size_t)l * NBATCH + b) * NVOC + m] = num / s;
}

// warp-per-node aggregate (R4 proven version)
__global__ void k_aggregate(const float* __restrict__ x, const float* __restrict__ Erel,
                            const float* __restrict__ attnL, const float* __restrict__ wrelL,
                            const int* __restrict__ elist, const int* __restrict__ rowstart,
                            const int* __restrict__ srcArr, const int* __restrict__ ridArr,
                            const int* __restrict__ nodeIds, const int* __restrict__ batchArr,
                            float* __restrict__ agg) {
    int warp = (blockIdx.x * blockDim.x + threadIdx.x) >> 5;
    int lane = threadIdx.x & 31;
    if (warp >= NNODES) return;
    int s0 = rowstart[warp], s1 = rowstart[warp + 1];
    float4 acc = {0.f, 0.f, 0.f, 0.f};
    for (int idx = s0; idx < s1; idx++) {
        int e = elist[idx];
        int s = srcArr[e];
        int r = ridArr[e];
        float ea = attnL[(size_t)batchArr[s] * NVOC + nodeIds[s]];
        float w = wrelL[r];
        float4 xv = *(const float4*)(x + (size_t)s * NH + lane * 4);
        float4 ev = *(const float4*)(Erel + (size_t)r * NH + lane * 4);
        acc.x += fmaxf(fmaf(xv.x, ea, w * ev.x), 0.f);
        acc.y += fmaxf(fmaf(xv.y, ea, w * ev.y), 0.f);
        acc.z += fmaxf(fmaf(xv.z, ea, w * ev.z), 0.f);
        acc.w += fmaxf(fmaf(xv.w, ea, w * ev.w), 0.f);
    }
    *(float4*)(agg + (size_t)warp * NH + lane * 4) = acc;
}

__global__ void k_pool_partial(const float* __restrict__ x, const int* __restrict__ bstart,
                               float* __restrict__ xg) {
    int b = blockIdx.y, chunk = blockIdx.x, h = threadIdx.x;
    int s0 = bstart[b], s1 = bstart[b + 1];
    int len = s1 - s0;
    int r0 = s0 + (int)((long long)len * chunk / 8);
    int r1 = s0 + (int)((long long)len * (chunk + 1) / 8);
    float acc = 0.f;
    for (int i = r0; i < r1; i++) acc += x[(size_t)i * NH + h];
    atomicAdd(&xg[b * NH + h], acc);
}

__global__ void k_pool_finish(float* __restrict__ xg, const int* __restrict__ bcnt) {
    int b = blockIdx.x, h = threadIdx.x;
    float c = (float)bcnt[b];
    xg[b * NH + h] /= fmaxf(c, 1.f);
}

__global__ void k_ehrsum(const float* __restrict__ ehr, float* __restrict__ den) {
    int b = blockIdx.x, t = threadIdx.x;
    __shared__ float s[256];
    float acc = 0.f;
    for (int n = t; n < NVOC; n += 256) acc += ehr[(size_t)b * NVOC + n];
    s[t] = acc;
    __syncthreads();
    for (int o = 128; o; o >>= 1) {
        if (t < o) s[t] += s[t + o];
        __syncthreads();
    }
    if (t == 0) den[b] = s[0];
}

__global__ void k_xnode_partial(const float* __restrict__ ehr,
                                const float* __restrict__ node_emb,
                                float* __restrict__ xacc) {
    int b = blockIdx.y, slice = blockIdx.x, h = threadIdx.x;
    int n0 = slice * (NVOC / 16), n1 = n0 + (NVOC / 16);
    float acc = 0.f;
    for (int n = n0; n < n1; n++)
        acc += ehr[(size_t)b * NVOC + n] * node_emb[(size_t)n * NH + h];
    atomicAdd(&xacc[b * NH + h], acc);
}

__global__ void k_xnode_finish(const float* __restrict__ xacc, const float* __restrict__ den,
                               const float* __restrict__ lin_w, const float* __restrict__ lin_b,
                               float* __restrict__ xnode) {
    int b = blockIdx.x, h = threadIdx.x;
    __shared__ float t[NH];
    t[h] = xacc[b * NH + h] / den[b];
    __syncthreads();
    float s = 0.f;
#pragma unroll 8
    for (int hh = 0; hh < NH; hh++) s += t[hh] * lin_w[h * NH + hh];
    xnode[b * NH + h] = s + lin_b[h];
}

__global__ void k_final(const float* __restrict__ xg, const float* __restrict__ xn,
                        const float* __restrict__ mlp_w, const float* __restrict__ mlp_b,
                        float* __restrict__ out) {
    int b = blockIdx.x, t = threadIdx.x;
    __shared__ float s[2 * NH];
    s[t] = xg[b * NH + t];
    s[NH + t] = xn[b * NH + t];
    __syncthreads();
    if (t < NOUT) {
        float acc = mlp_b[t];
        const float* w = mlp_w + t * (2 * NH);
#pragma unroll 8
        for (int k = 0; k < 2 * NH; k++) acc += s[k] * w[k];
        out[b * NOUT + t] = acc;
    }
}

// ---------------- launch ----------------
extern "C" void kernel_launch(void* const* d_in, const int* in_sizes, int n_in,
                              void* d_out, int out_size) {
    const float* node_emb = (const float*)d_in[0];
    const float* rel_emb  = (const float*)d_in[1];
    const float* lin_w    = (const float*)d_in[2];
    const float* lin_b    = (const float*)d_in[3];
    const float* alpha_w  = (const float*)d_in[4];
    const float* alpha_b  = (const float*)d_in[5];
    const float* beta_w   = (const float*)d_in[6];
    const float* beta_b   = (const float*)d_in[7];
    const float* wr_w     = (const float*)d_in[8];
    const float* wr_b     = (const float*)d_in[9];
    const float* conv_w   = (const float*)d_in[10];
    const float* conv_b   = (const float*)d_in[11];
    const float* mlp_w    = (const float*)d_in[12];
    const float* mlp_b    = (const float*)d_in[13];
    const float* visit    = (const float*)d_in[14];
    const float* ehr      = (const float*)d_in[15];
    const int* node_ids   = (const int*)d_in[16];
    const int* rel_ids    = (const int*)d_in[17];
    const int* eidx       = (const int*)d_in[18];
    const int* batch      = (const int*)d_in[19];
    float* out = (float*)d_out;

    const int* srcArr = eidx;
    const int* dstArr = eidx + NEDGES;

    float *Zp, *Enodep, *Erelp, *wrelp, *attnp, *betap, *xp, *x2p, *aggp;
    float *xgp, *xaccp, *denp, *xnodep;
    int *degp, *rowstartp, *cursorp, *elistp, *partp, *bcntp, *bstartp;
    cudaGetSymbolAddress((void**)&Zp, g_Z);
    cudaGetSymbolAddress((void**)&Enodep, g_Enode);
    cudaGetSymbolAddress((void**)&Erelp, g_Erel);
    cudaGetSymbolAddress((void**)&wrelp, g_wrel);
    cudaGetSymbolAddress((void**)&attnp, g_attn);
    cudaGetSymbolAddress((void**)&betap, g_beta);
    cudaGetSymbolAddress((void**)&xp, g_x);
    cudaGetSymbolAddress((void**)&x2p, g_x2);
    cudaGetSymbolAddress((void**)&aggp, g_agg);
    cudaGetSymbolAddress((void**)&xgp, g_xg);
    cudaGetSymbolAddress((void**)&xaccp, g_xacc);
    cudaGetSymbolAddress((void**)&denp, g_den);
    cudaGetSymbolAddress((void**)&xnodep, g_xnode);
    cudaGetSymbolAddress((void**)&degp, g_deg);
    cudaGetSymbolAddress((void**)&rowstartp, g_rowstart);
    cudaGetSymbolAddress((void**)&cursorp, g_cursor);
    cudaGetSymbolAddress((void**)&elistp, g_elist);
    cudaGetSymbolAddress((void**)&partp, g_part);
    cudaGetSymbolAddress((void**)&bcntp, g_bcnt);
    cudaGetSymbolAddress((void**)&bstartp, g_bstart);

    cudaFuncSetAttribute(alpha_gemm_tf32,
                         cudaFuncAttributeMaxDynamicSharedMemorySize, ALPHA_SMEM);

    const int SCAN_BLOCKS = (NNODES + 1023) / 1024;

    // #0 Enode, #1 Erel, #2 wrel
    gemm128_3xtf32<false, false><<<(NVOC + 127) / 128, 256>>>(
        node_emb, nullptr, lin_w, lin_b, Enodep, NVOC);
    gemm128_3xtf32<false, false><<<(NREL + 127) / 128, 256>>>(
        rel_emb, nullptr, lin_w, lin_b, Erelp, NREL);
    k_wrel<<<(NL * NREL * 32 + 255) / 256, 256>>>(Erelp, wr_w, wr_b, wrelp);

    // #3 alpha logits (ncu capture target)
    alpha_gemm_tf32<<<dim3((NVOC + TBN - 1) / TBN, (NBATCH * NV) / TBM, NL), 256,
                     ALPHA_SMEM>>>(visit, alpha_w, alpha_b, Zp);

    k_gather<<<(NNODES * 32 + 255) / 256, 256>>>(Enodep, node_ids, xp);
    k_beta<<<(NL * NBATCH * NV * 32 + 255) / 256, 256>>>(visit, beta_w, beta_b, betap);
    k_attn<<<dim3((NVOC + 255) / 256, NBATCH, NL), 256>>>(Zp, betap, attnp);

    // CSR build + batch offsets
    k_zero_int<<<(NNODES + 255) / 256, 256>>>(degp, NNODES);
    k_zero_int<<<1, 64>>>(bcntp, NBATCH);
    k_hist<<<(NEDGES + 255) / 256, 256>>>(dstArr, degp, NEDGES);
    k_hist_batch<<<(NNODES + 255) / 256, 256>>>(batch, bcntp);
    k_scan_block<<<SCAN_BLOCKS, 1024>>>(degp, rowstartp, partp, NNODES);
    k_scan_part<<<1, 1>>>(partp, SCAN_BLOCKS, rowstartp);
    k_scan_add<<<SCAN_BLOCKS, 1024>>>(rowstartp, partp, cursorp, NNODES);
    k_scatter<<<(NEDGES + 255) / 256, 256>>>(dstArr, cursorp, elistp, NEDGES);
    k_bscan<<<1, 1>>>(bcntp, bstartp);

    // message-passing layers
    float* xcur = xp;
    float* xalt = x2p;
    for (int l = 0; l < NL; l++) {
        k_aggregate<<<(NNODES * 32 + 255) / 256, 256>>>(
            xcur, Erelp, attnp + (size_t)l * NBATCH * NVOC, wrelp + l * NREL,
            elistp, rowstartp, srcArr, rel_ids, node_ids, batch, aggp);
        gemm128_3xtf32<true, true><<<(NNODES + 127) / 128, 256>>>(
            aggp, xcur, conv_w + (size_t)l * NH * NH, conv_b + (size_t)l * NH,
            xalt, NNODES);
        float* tmp = xcur; xcur = xalt; xalt = tmp;
    }

    // heads
    k_zero_float<<<(NBATCH * NH + 255) / 256, 256>>>(xgp, NBATCH * NH);
    k_zero_float<<<(NBATCH * NH + 255) / 256, 256>>>(xaccp, NBATCH * NH);
    k_pool_partial<<<dim3(8, NBATCH), NH>>>(xcur, bstartp, xgp);
    k_pool_finish<<<NBATCH, NH>>>(xgp, bcntp);
    k_ehrsum<<<NBATCH, 256>>>(ehr, denp);
    k_xnode_partial<<<dim3(16, NBATCH), NH>>>(ehr, node_emb, xaccp);
    k_xnode_finish<<<NBATCH, NH>>>(xaccp, denp, lin_w, lin_b, xnodep);
    k_final<<<NBATCH, NH>>>(xgp, xnodep, mlp_w, mlp_b, out);
}

// round 10
// speedup vs baseline: 3.2749x; 1.0773x over previous
#include <cuda_runtime.h>
#include <math.h>
#include <stdint.h>

#define NNODES 50000
#define NEDGES 800000
#define NBATCH 32
#define NV 20
#define NVOC 4000
#define NREL 200
#define NH 128
#define NL 3
#define NOUT 100

// ---------------- device scratch ----------------
__device__ float g_Z[(size_t)NL * NBATCH * NV * NVOC];
__device__ float g_Enode[NVOC * NH];
__device__ float g_Erel[NREL * NH];
__device__ float g_wrel[NL * NREL];
__device__ float g_attn[(size_t)NL * NBATCH * NVOC];
__device__ float g_beta[NL * NBATCH * NV];
__device__ float g_x[(size_t)NNODES * NH];
__device__ float g_x2[(size_t)NNODES * NH];
__device__ float g_agg[(size_t)NNODES * NH];
__device__ int   g_deg[NNODES];
__device__ int   g_rowstart[NNODES + 1];
__device__ int   g_cursor[NNODES];
__device__ int   g_elist[NEDGES];
__device__ int   g_part[64];
__device__ int   g_bcnt[NBATCH];
__device__ int   g_bstart[NBATCH + 1];
__device__ float g_xg[NBATCH * NH];
__device__ float g_xacc[NBATCH * NH];
__device__ float g_den[NBATCH];
__device__ float g_xnode[NBATCH * NH];

// ---------------- helpers ----------------
__device__ __forceinline__ void cp_async16(void* smem_dst, const void* gsrc, int src_size) {
    uint32_t s = (uint32_t)__cvta_generic_to_shared(smem_dst);
    asm volatile("cp.async.ca.shared.global [%0], [%1], 16, %2;\n"
                 :: "r"(s), "l"(gsrc), "r"(src_size));
}
__device__ __forceinline__ void cp_commit() { asm volatile("cp.async.commit_group;\n"); }
template <int W> __device__ __forceinline__ void cp_wait() {
    asm volatile("cp.async.wait_group %0;\n" :: "n"(W));
}
__device__ __forceinline__ uint32_t smem_u32(const void* p) {
    return (uint32_t)__cvta_generic_to_shared(p);
}
__device__ __forceinline__ void ldsm_x4(uint32_t& r0, uint32_t& r1, uint32_t& r2,
                                        uint32_t& r3, uint32_t addr) {
    asm volatile("ldmatrix.sync.aligned.m8n8.x4.shared.b16 {%0,%1,%2,%3}, [%4];"
                 : "=r"(r0), "=r"(r1), "=r"(r2), "=r"(r3) : "r"(addr));
}
__device__ __forceinline__ void split_tf32(float v, uint32_t& hi, uint32_t& lo) {
    uint32_t h;
    asm("cvt.rna.tf32.f32 %0, %1;" : "=r"(h) : "f"(v));
    float l = v - __uint_as_float(h);
    uint32_t lt;
    asm("cvt.rna.tf32.f32 %0, %1;" : "=r"(lt) : "f"(l));
    hi = h; lo = lt;
}

// ---------------- tf32 tensor-core GEMM for alpha logits ----------------
// Z[l][m][n] = sum_k visit[m,k]*alpha_w[l][n,k] + alpha_b[l][n]; M=640,N=K=4000
// 4 warps, 64x64 warp tiles (2x2 grid) -> smem traffic 0.1875 B/MAC.
// ldmatrix fragment loads; TPAD=20 -> conflict-free LDSM phases; 2-stage ring.
#define TBM 128
#define TBN 128
#define TBK 16
#define TPAD 20

__global__ __launch_bounds__(128, 2) void alpha_gemm_tf32(
    const float* __restrict__ A,
    const float* __restrict__ Ball,
    const float* __restrict__ biasAll,
    float* __restrict__ Zall)
{
    const int M = NBATCH * NV, N = NVOC, K = NVOC;
    const int KITERS = K / TBK;

    int l = blockIdx.z;
    const float* B = Ball + (size_t)l * N * K;
    const float* bias = biasAll + (size_t)l * N;
    float* C = Zall + (size_t)l * M * N;

    __shared__ float As[2][TBM * TPAD];
    __shared__ float Bs[2][TBN * TPAD];

    int tid = threadIdx.x;
    int m0 = blockIdx.y * TBM;
    int n0 = blockIdx.x * TBN;
    int warp = tid >> 5, lane = tid & 31;
    int wm = (warp & 1) * 64;
    int wn = (warp >> 1) * 64;
    int lq = lane >> 2;
    int lr = lane & 3;
    int tile = lane >> 3, trow = lane & 7;

    float acc[4][8][4];
#pragma unroll
    for (int i = 0; i < 4; i++)
#pragma unroll
        for (int j = 0; j < 8; j++)
#pragma unroll
            for (int r = 0; r < 4; r++) acc[i][j][r] = 0.f;

#define ISSUE_TILES(stage, k0)                                                        \
    do {                                                                              \
        _Pragma("unroll")                                                             \
        for (int t = tid; t < 512; t += 128) {                                        \
            int row = t >> 2, ch = (t & 3) * 4;                                       \
            cp_async16(&As[stage][row * TPAD + ch],                                   \
                       A + (size_t)(m0 + row) * K + (k0) + ch, 16);                   \
        }                                                                             \
        _Pragma("unroll")                                                             \
        for (int t = tid; t < 512; t += 128) {                                        \
            int row = t >> 2, ch = (t & 3) * 4;                                       \
            int gn = n0 + row;                                                        \
            int ok = gn < N;                                                          \
            cp_async16(&Bs[stage][row * TPAD + ch],                                   \
                       B + (size_t)(ok ? gn : 0) * K + (k0) + ch, ok ? 16 : 0);       \
        }                                                                             \
    } while (0)

    ISSUE_TILES(0, 0);
    cp_commit();

    // LDSM address components:
    //  A x4 per mi: threads 0-7 (rows lo,k lo), 8-15 (rows hi,k lo),
    //               16-23 (rows lo,k hi), 24-31 (rows hi,k hi)
    int aRow = wm + ((tile & 1) << 3) + trow;
    int aKof = (tile >> 1) << 2;
    //  B x4 per ni-pair: r0=(ni,klo) r1=(ni,khi) r2=(ni+1,klo) r3=(ni+1,khi)
    int bCol = wn + ((tile >> 1) << 3) + trow;
    int bKof = (tile & 1) << 2;

    for (int kt = 0; kt < KITERS; kt++) {
        int st = kt & 1;
        if (kt + 1 < KITERS) {
            ISSUE_TILES(st ^ 1, (kt + 1) * TBK);
            cp_commit();
            cp_wait<1>();
        } else {
            cp_wait<0>();
        }
        __syncthreads();

        const float* as = As[st];
        const float* bs = Bs[st];
        uint32_t abase = smem_u32(&as[aRow * TPAD + aKof]);
        uint32_t bbase = smem_u32(&bs[bCol * TPAD + bKof]);

#pragma unroll
        for (int kk = 0; kk < TBK; kk += 8) {
            uint32_t af[4][4];
            uint32_t bf[8][2];
#pragma unroll
            for (int mi = 0; mi < 4; mi++)
                ldsm_x4(af[mi][0], af[mi][1], af[mi][2], af[mi][3],
                        abase + (kk + mi * 16 * TPAD) * 4);
#pragma unroll
            for (int np = 0; np < 4; np++)
                ldsm_x4(bf[2 * np][0], bf[2 * np][1], bf[2 * np + 1][0], bf[2 * np + 1][1],
                        bbase + (kk + np * 16 * TPAD) * 4);
#pragma unroll
            for (int mi = 0; mi < 4; mi++)
#pragma unroll
                for (int ni = 0; ni < 8; ni++) {
                    asm volatile(
                        "mma.sync.aligned.m16n8k8.row.col.f32.tf32.tf32.f32 "
                        "{%0,%1,%2,%3}, {%4,%5,%6,%7}, {%8,%9}, {%0,%1,%2,%3};\n"
                        : "+f"(acc[mi][ni][0]), "+f"(acc[mi][ni][1]),
                          "+f"(acc[mi][ni][2]), "+f"(acc[mi][ni][3])
                        : "r"(af[mi][0]), "r"(af[mi][1]), "r"(af[mi][2]), "r"(af[mi][3]),
                          "r"(bf[ni][0]), "r"(bf[ni][1]));
                }
        }
        __syncthreads();
    }

#pragma unroll
    for (int mi = 0; mi < 4; mi++) {
#pragma unroll
        for (int ni = 0; ni < 8; ni++) {
            int r = m0 + wm + mi * 16 + lq;
            int c = n0 + wn + ni * 8 + lr * 2;
            if (c < N) {
                float2 bb = *(const float2*)(bias + c);
                float2 o0, o1;
                o0.x = acc[mi][ni][0] + bb.x; o0.y = acc[mi][ni][1] + bb.y;
                o1.x = acc[mi][ni][2] + bb.x; o1.y = acc[mi][ni][3] + bb.y;
                *(float2*)(C + (size_t)r * N + c) = o0;
                *(float2*)(C + (size_t)(r + 8) * N + c) = o1;
            }
        }
    }
#undef ISSUE_TILES
}

// ---------------- 3xTF32 compensated mma GEMM: K=128, N=128 -----------------
#define CPW 36

template <bool RELU, bool ADD2>
__global__ __launch_bounds__(256) void gemm128_3xtf32(
    const float* __restrict__ A, const float* __restrict__ A2,
    const float* __restrict__ B, const float* __restrict__ bias,
    float* __restrict__ C, int M)
{
    __shared__ float As[128 * CPW];
    __shared__ float Bs[128 * CPW];

    int tid = threadIdx.x;
    int m0 = blockIdx.x * 128;
    int warp = tid >> 5, lane = tid & 31;
    int wm = (warp & 1) * 64;
    int wn = (warp >> 1) * 32;
    int lq = lane >> 2;
    int lr = lane & 3;

    float acc[4][4][4];
#pragma unroll
    for (int i = 0; i < 4; i++)
#pragma unroll
        for (int j = 0; j < 4; j++)
#pragma unroll
            for (int r = 0; r < 4; r++) acc[i][j][r] = 0.f;

    for (int k0 = 0; k0 < NH; k0 += 32) {
        __syncthreads();
#pragma unroll
        for (int t = tid; t < 1024; t += 256) {
            int row = t >> 3, seg = (t & 7) * 4;
            int gm = m0 + row;
            float4 v = {0, 0, 0, 0};
            if (gm < M) {
                v = *(const float4*)(A + (size_t)gm * NH + k0 + seg);
                if (ADD2) {
                    float4 w = *(const float4*)(A2 + (size_t)gm * NH + k0 + seg);
                    v.x += w.x; v.y += w.y; v.z += w.z; v.w += w.w;
                }
            }
            *(float4*)&As[row * CPW + seg] = v;
            *(float4*)&Bs[row * CPW + seg] = *(const float4*)(B + (size_t)row * NH + k0 + seg);
        }
        __syncthreads();

#pragma unroll
        for (int kk = 0; kk < 32; kk += 8) {
            uint32_t ah[4][4], al[4][4];
            uint32_t bh[4][2], bl[4][2];
#pragma unroll
            for (int mi = 0; mi < 4; mi++) {
                int base = (wm + mi * 16 + lq) * CPW + kk + lr;
                split_tf32(As[base],               ah[mi][0], al[mi][0]);
                split_tf32(As[base + 8 * CPW],     ah[mi][1], al[mi][1]);
                split_tf32(As[base + 4],           ah[mi][2], al[mi][2]);
                split_tf32(As[base + 8 * CPW + 4], ah[mi][3], al[mi][3]);
            }
#pragma unroll
            for (int ni = 0; ni < 4; ni++) {
                int base = (wn + ni * 8 + lq) * CPW + kk + lr;
                split_tf32(Bs[base],     bh[ni][0], bl[ni][0]);
                split_tf32(Bs[base + 4], bh[ni][1], bl[ni][1]);
            }
#define MMA_TF32(Aop, Bop)                                                            \
    asm volatile(                                                                     \
        "mma.sync.aligned.m16n8k8.row.col.f32.tf32.tf32.f32 "                         \
        "{%0,%1,%2,%3}, {%4,%5,%6,%7}, {%8,%9}, {%0,%1,%2,%3};\n"                     \
        : "+f"(acc[mi][ni][0]), "+f"(acc[mi][ni][1]),                                 \
          "+f"(acc[mi][ni][2]), "+f"(acc[mi][ni][3])                                  \
        : "r"(Aop[mi][0]), "r"(Aop[mi][1]), "r"(Aop[mi][2]), "r"(Aop[mi][3]),         \
          "r"(Bop[ni][0]), "r"(Bop[ni][1]))
#pragma unroll
            for (int mi = 0; mi < 4; mi++)
#pragma unroll
                for (int ni = 0; ni < 4; ni++) {
                    MMA_TF32(ah, bh);
                    MMA_TF32(ah, bl);
                    MMA_TF32(al, bh);
                }
#undef MMA_TF32
        }
    }

#pragma unroll
    for (int mi = 0; mi < 4; mi++) {
#pragma unroll
        for (int ni = 0; ni < 4; ni++) {
            int r = m0 + wm + mi * 16 + lq;
            int c = wn + ni * 8 + lr * 2;
            float2 bb = *(const float2*)(bias + c);
            float2 o0, o1;
            o0.x = acc[mi][ni][0] + bb.x; o0.y = acc[mi][ni][1] + bb.y;
            o1.x = acc[mi][ni][2] + bb.x; o1.y = acc[mi][ni][3] + bb.y;
            if (RELU) {
                o0.x = fmaxf(o0.x, 0.f); o0.y = fmaxf(o0.y, 0.f);
                o1.x = fmaxf(o1.x, 0.f); o1.y = fmaxf(o1.y, 0.f);
            }
            if (r < M)     *(float2*)(C + (size_t)r * NH + c) = o0;
            if (r + 8 < M) *(float2*)(C + (size_t)(r + 8) * NH + c) = o1;
        }
    }
}

// ---------------- small kernels ----------------
__global__ void k_zero_int(int* __restrict__ p, int n) {
    int i = blockIdx.x * blockDim.x + threadIdx.x;
    if (i < n) p[i] = 0;
}
__global__ void k_zero_float(float* __restrict__ p, int n) {
    int i = blockIdx.x * blockDim.x + threadIdx.x;
    if (i < n) p[i] = 0.f;
}

__global__ void k_hist(const int* __restrict__ keys, int* __restrict__ cnt, int n) {
    int i = blockIdx.x * blockDim.x + threadIdx.x;
    if (i < n) atomicAdd(&cnt[keys[i]], 1);
}

__global__ void k_hist_batch(const int* __restrict__ batch, int* __restrict__ bcnt) {
    __shared__ int h[NBATCH];
    if (threadIdx.x < NBATCH) h[threadIdx.x] = 0;
    __syncthreads();
    int i = blockIdx.x * blockDim.x + threadIdx.x;
    if (i < NNODES) atomicAdd(&h[batch[i]], 1);
    __syncthreads();
    if (threadIdx.x < NBATCH) atomicAdd(&bcnt[threadIdx.x], h[threadIdx.x]);
}

__global__ void k_scan_block(const int* __restrict__ in, int* __restrict__ outEx,
                             int* __restrict__ part, int n) {
    __shared__ int s[1024];
    int t = threadIdx.x;
    int i = blockIdx.x * 1024 + t;
    int v = (i < n) ? in[i] : 0;
    s[t] = v;
    __syncthreads();
    for (int off = 1; off < 1024; off <<= 1) {
        int y = (t >= off) ? s[t - off] : 0;
        __syncthreads();
        s[t] += y;
        __syncthreads();
    }
    if (i < n) outEx[i] = s[t] - v;
    if (t == 1023) part[blockIdx.x] = s[1023];
}

__global__ void k_scan_part(int* __restrict__ part, int nb, int* __restrict__ rowstart) {
    if (threadIdx.x == 0 && blockIdx.x == 0) {
        int acc = 0;
        for (int i = 0; i < nb; i++) { int v = part[i]; part[i] = acc; acc += v; }
        rowstart[NNODES] = NEDGES;
    }
}

__global__ void k_scan_add(int* __restrict__ rowstart, const int* __restrict__ part,
                           int* __restrict__ cursor, int n) {
    int i = blockIdx.x * 1024 + threadIdx.x;
    if (i < n) {
        int v = rowstart[i] + part[blockIdx.x];
        rowstart[i] = v;
        cursor[i] = v;
    }
}

__global__ void k_scatter(const int* __restrict__ dst, int* __restrict__ cursor,
                          int* __restrict__ elist, int n) {
    int e = blockIdx.x * blockDim.x + threadIdx.x;
    if (e < n) {
        int d = dst[e];
        int p = atomicAdd(&cursor[d], 1);
        elist[p] = e;
    }
}

__global__ void k_bscan(const int* __restrict__ bcnt, int* __restrict__ bstart) {
    if (threadIdx.x == 0 && blockIdx.x == 0) {
        int acc = 0;
        for (int b = 0; b < NBATCH; b++) { bstart[b] = acc; acc += bcnt[b]; }
        bstart[NBATCH] = acc;
    }
}

__global__ void k_wrel(const float* __restrict__ Erel, const float* __restrict__ wr_w,
                       const float* __restrict__ wr_b, float* __restrict__ wrel) {
    int w = (blockIdx.x * blockDim.x + threadIdx.x) >> 5;
    int lane = threadIdx.x & 31;
    if (w >= NL * NREL) return;
    int l = w / NREL, r = w % NREL;
    float acc = 0.f;
#pragma unroll
    for (int h = lane; h < NH; h += 32) acc += Erel[r * NH + h] * wr_w[l * NH + h];
#pragma unroll
    for (int o = 16; o; o >>= 1) acc += __shfl_down_sync(0xffffffffu, acc, o);
    if (lane == 0) wrel[w] = acc + wr_b[l];
}

__global__ void k_gather(const float* __restrict__ Enode, const int* __restrict__ node_ids,
                         float* __restrict__ x) {
    int t = blockIdx.x * blockDim.x + threadIdx.x;
    if (t >= NNODES * 32) return;
    int i = t >> 5, q = t & 31;
    int nid = node_ids[i];
    *(float4*)(x + (size_t)i * NH + q * 4) =
        *(const float4*)(Enode + (size_t)nid * NH + q * 4);
}

__global__ void k_beta(const float* __restrict__ vn, const float* __restrict__ beta_w,
                       const float* __restrict__ beta_b, float* __restrict__ betaOut) {
    int w = (blockIdx.x * blockDim.x + threadIdx.x) >> 5;
    int lane = threadIdx.x & 31;
    if (w >= NL * NBATCH * NV) return;
    int l = w / (NBATCH * NV);
    int rem = w % (NBATCH * NV);
    int b = rem / NV, v = rem % NV;
    const float* row = vn + ((size_t)b * NV + v) * NVOC;
    const float* bw = beta_w + l * NVOC;
    float acc = 0.f;
    for (int n = lane; n < NVOC; n += 32) acc += row[n] * bw[n];
#pragma unroll
    for (int o = 16; o; o >>= 1) acc += __shfl_down_sync(0xffffffffu, acc, o);
    if (lane == 0)
        betaOut[w] = tanhf(acc + beta_b[l]) * expf(0.03f * (float)(NV - v));
}

__global__ void k_attn(const float* __restrict__ Zall, const float* __restrict__ betaAll,
                       float* __restrict__ attnAll) {
    int m = blockIdx.x * blockDim.x + threadIdx.x;
    int b = blockIdx.y;
    int l = blockIdx.z;
    if (m >= NVOC) return;
    const float* Z = Zall + (size_t)l * NBATCH * NV * NVOC;
    const float* betaL = betaAll + l * NBATCH * NV;
    float z[NV];
    float mx = -1e30f;
#pragma unroll
    for (int v = 0; v < NV; v++) {
        z[v] = Z[((size_t)(b * NV + v)) * NVOC + m];
        mx = fmaxf(mx, z[v]);
    }
    float s = 0.f, num = 0.f;
#pragma unroll
    for (int v = 0; v < NV; v++) {
        float e = expf(z[v] - mx);
        s += e;
        num += e * betaL[b * NV + v];
    }
    attnAll[((size_t)l * NBATCH + b) * NVOC + m] = num / s;
}

// warp-per-node aggregate (R4 proven version)
__global__ void k_aggregate(const float* __restrict__ x, const float* __restrict__ Erel,
                            const float* __restrict__ attnL, const float* __restrict__ wrelL,
                            const int* __restrict__ elist, const int* __restrict__ rowstart,
                            const int* __restrict__ srcArr, const int* __restrict__ ridArr,
                            const int* __restrict__ nodeIds, const int* __restrict__ batchArr,
                            float* __restrict__ agg) {
    int warp = (blockIdx.x * blockDim.x + threadIdx.x) >> 5;
    int lane = threadIdx.x & 31;
    if (warp >= NNODES) return;
    int s0 = rowstart[warp], s1 = rowstart[warp + 1];
    float4 acc = {0.f, 0.f, 0.f, 0.f};
    for (int idx = s0; idx < s1; idx++) {
        int e = elist[idx];
        int s = srcArr[e];
        int r = ridArr[e];
        float ea = attnL[(size_t)batchArr[s] * NVOC + nodeIds[s]];
        float w = wrelL[r];
        float4 xv = *(const float4*)(x + (size_t)s * NH + lane * 4);
        float4 ev = *(const float4*)(Erel + (size_t)r * NH + lane * 4);
        acc.x += fmaxf(fmaf(xv.x, ea, w * ev.x), 0.f);
        acc.y += fmaxf(fmaf(xv.y, ea, w * ev.y), 0.f);
        acc.z += fmaxf(fmaf(xv.z, ea, w * ev.z), 0.f);
        acc.w += fmaxf(fmaf(xv.w, ea, w * ev.w), 0.f);
    }
    *(float4*)(agg + (size_t)warp * NH + lane * 4) = acc;
}

__global__ void k_pool_partial(const float* __restrict__ x, const int* __restrict__ bstart,
                               float* __restrict__ xg) {
    int b = blockIdx.y, chunk = blockIdx.x, h = threadIdx.x;
    int s0 = bstart[b], s1 = bstart[b + 1];
    int len = s1 - s0;
    int r0 = s0 + (int)((long long)len * chunk / 8);
    int r1 = s0 + (int)((long long)len * (chunk + 1) / 8);
    float acc = 0.f;
    for (int i = r0; i < r1; i++) acc += x[(size_t)i * NH + h];
    atomicAdd(&xg[b * NH + h], acc);
}

__global__ void k_pool_finish(float* __restrict__ xg, const int* __restrict__ bcnt) {
    int b = blockIdx.x, h = threadIdx.x;
    float c = (float)bcnt[b];
    xg[b * NH + h] /= fmaxf(c, 1.f);
}

__global__ void k_ehrsum(const float* __restrict__ ehr, float* __restrict__ den) {
    int b = blockIdx.x, t = threadIdx.x;
    __shared__ float s[256];
    float acc = 0.f;
    for (int n = t; n < NVOC; n += 256) acc += ehr[(size_t)b * NVOC + n];
    s[t] = acc;
    __syncthreads();
    for (int o = 128; o; o >>= 1) {
        if (t < o) s[t] += s[t + o];
        __syncthreads();
    }
    if (t == 0) den[b] = s[0];
}

__global__ void k_xnode_partial(const float* __restrict__ ehr,
                                const float* __restrict__ node_emb,
                                float* __restrict__ xacc) {
    int b = blockIdx.y, slice = blockIdx.x, h = threadIdx.x;
    int n0 = slice * (NVOC / 16), n1 = n0 + (NVOC / 16);
    float acc = 0.f;
    for (int n = n0; n < n1; n++)
        acc += ehr[(size_t)b * NVOC + n] * node_emb[(size_t)n * NH + h];
    atomicAdd(&xacc[b * NH + h], acc);
}

__global__ void k_xnode_finish(const float* __restrict__ xacc, const float* __restrict__ den,
                               const float* __restrict__ lin_w, const float* __restrict__ lin_b,
                               float* __restrict__ xnode) {
    int b = blockIdx.x, h = threadIdx.x;
    __shared__ float t[NH];
    t[h] = xacc[b * NH + h] / den[b];
    __syncthreads();
    float s = 0.f;
#pragma unroll 8
    for (int hh = 0; hh < NH; hh++) s += t[hh] * lin_w[h * NH + hh];
    xnode[b * NH + h] = s + lin_b[h];
}

__global__ void k_final(const float* __restrict__ xg, const float* __restrict__ xn,
                        const float* __restrict__ mlp_w, const float* __restrict__ mlp_b,
                        float* __restrict__ out) {
    int b = blockIdx.x, t = threadIdx.x;
    __shared__ float s[2 * NH];
    s[t] = xg[b * NH + t];
    s[NH + t] = xn[b * NH + t];
    __syncthreads();
    if (t < NOUT) {
        float acc = mlp_b[t];
        const float* w = mlp_w + t * (2 * NH);
#pragma unroll 8
        for (int k = 0; k < 2 * NH; k++) acc += s[k] * w[k];
        out[b * NOUT + t] = acc;
    }
}

// ---------------- launch ----------------
extern "C" void kernel_launch(void* const* d_in, const int* in_sizes, int n_in,
                              void* d_out, int out_size) {
    const float* node_emb = (const float*)d_in[0];
    const float* rel_emb  = (const float*)d_in[1];
    const float* lin_w    = (const float*)d_in[2];
    const float* lin_b    = (const float*)d_in[3];
    const float* alpha_w  = (const float*)d_in[4];
    const float* alpha_b  = (const float*)d_in[5];
    const float* beta_w   = (const float*)d_in[6];
    const float* beta_b   = (const float*)d_in[7];
    const float* wr_w     = (const float*)d_in[8];
    const float* wr_b     = (const float*)d_in[9];
    const float* conv_w   = (const float*)d_in[10];
    const float* conv_b   = (const float*)d_in[11];
    const float* mlp_w    = (const float*)d_in[12];
    const float* mlp_b    = (const float*)d_in[13];
    const float* visit    = (const float*)d_in[14];
    const float* ehr      = (const float*)d_in[15];
    const int* node_ids   = (const int*)d_in[16];
    const int* rel_ids    = (const int*)d_in[17];
    const int* eidx       = (const int*)d_in[18];
    const int* batch      = (const int*)d_in[19];
    float* out = (float*)d_out;

    const int* srcArr = eidx;
    const int* dstArr = eidx + NEDGES;

    float *Zp, *Enodep, *Erelp, *wrelp, *attnp, *betap, *xp, *x2p, *aggp;
    float *xgp, *xaccp, *denp, *xnodep;
    int *degp, *rowstartp, *cursorp, *elistp, *partp, *bcntp, *bstartp;
    cudaGetSymbolAddress((void**)&Zp, g_Z);
    cudaGetSymbolAddress((void**)&Enodep, g_Enode);
    cudaGetSymbolAddress((void**)&Erelp, g_Erel);
    cudaGetSymbolAddress((void**)&wrelp, g_wrel);
    cudaGetSymbolAddress((void**)&attnp, g_attn);
    cudaGetSymbolAddress((void**)&betap, g_beta);
    cudaGetSymbolAddress((void**)&xp, g_x);
    cudaGetSymbolAddress((void**)&x2p, g_x2);
    cudaGetSymbolAddress((void**)&aggp, g_agg);
    cudaGetSymbolAddress((void**)&xgp, g_xg);
    cudaGetSymbolAddress((void**)&xaccp, g_xacc);
    cudaGetSymbolAddress((void**)&denp, g_den);
    cudaGetSymbolAddress((void**)&xnodep, g_xnode);
    cudaGetSymbolAddress((void**)&degp, g_deg);
    cudaGetSymbolAddress((void**)&rowstartp, g_rowstart);
    cudaGetSymbolAddress((void**)&cursorp, g_cursor);
    cudaGetSymbolAddress((void**)&elistp, g_elist);
    cudaGetSymbolAddress((void**)&partp, g_part);
    cudaGetSymbolAddress((void**)&bcntp, g_bcnt);
    cudaGetSymbolAddress((void**)&bstartp, g_bstart);

    const int SCAN_BLOCKS = (NNODES + 1023) / 1024;

    // #0 Enode, #1 Erel, #2 wrel
    gemm128_3xtf32<false, false><<<(NVOC + 127) / 128, 256>>>(
        node_emb, nullptr, lin_w, lin_b, Enodep, NVOC);
    gemm128_3xtf32<false, false><<<(NREL + 127) / 128, 256>>>(
        rel_emb, nullptr, lin_w, lin_b, Erelp, NREL);
    k_wrel<<<(NL * NREL * 32 + 255) / 256, 256>>>(Erelp, wr_w, wr_b, wrelp);

    // #3 alpha logits (ncu capture target)
    alpha_gemm_tf32<<<dim3((NVOC + TBN - 1) / TBN, (NBATCH * NV) / TBM, NL), 128>>>(
        visit, alpha_w, alpha_b, Zp);

    k_gather<<<(NNODES * 32 + 255) / 256, 256>>>(Enodep, node_ids, xp);
    k_beta<<<(NL * NBATCH * NV * 32 + 255) / 256, 256>>>(visit, beta_w, beta_b, betap);
    k_attn<<<dim3((NVOC + 255) / 256, NBATCH, NL), 256>>>(Zp, betap, attnp);

    // CSR build + batch offsets
    k_zero_int<<<(NNODES + 255) / 256, 256>>>(degp, NNODES);
    k_zero_int<<<1, 64>>>(bcntp, NBATCH);
    k_hist<<<(NEDGES + 255) / 256, 256>>>(dstArr, degp, NEDGES);
    k_hist_batch<<<(NNODES + 255) / 256, 256>>>(batch, bcntp);
    k_scan_block<<<SCAN_BLOCKS, 1024>>>(degp, rowstartp, partp, NNODES);
    k_scan_part<<<1, 1>>>(partp, SCAN_BLOCKS, rowstartp);
    k_scan_add<<<SCAN_BLOCKS, 1024>>>(rowstartp, partp, cursorp, NNODES);
    k_scatter<<<(NEDGES + 255) / 256, 256>>>(dstArr, cursorp, elistp, NEDGES);
    k_bscan<<<1, 1>>>(bcntp, bstartp);

    // message-passing layers
    float* xcur = xp;
    float* xalt = x2p;
    for (int l = 0; l < NL; l++) {
        k_aggregate<<<(NNODES * 32 + 255) / 256, 256>>>(
            xcur, Erelp, attnp + (size_t)l * NBATCH * NVOC, wrelp + l * NREL,
            elistp, rowstartp, srcArr, rel_ids, node_ids, batch, aggp);
        gemm128_3xtf32<true, true><<<(NNODES + 127) / 128, 256>>>(
            aggp, xcur, conv_w + (size_t)l * NH * NH, conv_b + (size_t)l * NH,
            xalt, NNODES);
        float* tmp = xcur; xcur = xalt; xalt = tmp;
    }

    // heads
    k_zero_float<<<(NBATCH * NH + 255) / 256, 256>>>(xgp, NBATCH * NH);
    k_zero_float<<<(NBATCH * NH + 255) / 256, 256>>>(xaccp, NBATCH * NH);
    k_pool_partial<<<dim3(8, NBATCH), NH>>>(xcur, bstartp, xgp);
    k_pool_finish<<<NBATCH, NH>>>(xgp, bcntp);
    k_ehrsum<<<NBATCH, 256>>>(ehr, denp);
    k_xnode_partial<<<dim3(16, NBATCH), NH>>>(ehr, node_emb, xaccp);
    k_xnode_finish<<<NBATCH, NH>>>(xaccp, denp, lin_w, lin_b, xnodep);
    k_final<<<NBATCH, NH>>>(xgp, xnodep, mlp_w, mlp_b, out);
}

// round 12
// speedup vs baseline: 3.6599x; 1.1176x over previous
#include <cuda_runtime.h>
#include <math.h>
#include <stdint.h>

#define NNODES 50000
#define NEDGES 800000
#define NBATCH 32
#define NV 20
#define NVOC 4000
#define NREL 200
#define NH 128
#define NL 3
#define NOUT 100

// ---------------- device scratch ----------------
__device__ float g_Z[(size_t)NL * NBATCH * NV * NVOC];
__device__ float g_Enode[NVOC * NH];
__device__ float g_Erel[NREL * NH];
__device__ float g_wrel[NL * NREL];
__device__ float g_attn[(size_t)NL * NBATCH * NVOC];
__device__ float g_beta[NL * NBATCH * NV];
__device__ float g_x[(size_t)NNODES * NH];
__device__ float g_x2[(size_t)NNODES * NH];
__device__ float g_agg[(size_t)NNODES * NH];
__device__ int   g_deg[NNODES];
__device__ int   g_rowstart[NNODES + 1];
__device__ int   g_cursor[NNODES];
__device__ int   g_elist[NEDGES];
__device__ int   g_part[64];
__device__ int   g_bcnt[NBATCH];
__device__ int   g_bstart[NBATCH + 1];
__device__ float g_xg[NBATCH * NH];
__device__ float g_xacc[NBATCH * NH];
__device__ float g_den[NBATCH];
__device__ float g_xnode[NBATCH * NH];

// ---------------- helpers ----------------
__device__ __forceinline__ void cp_async16(void* smem_dst, const void* gsrc, int src_size) {
    uint32_t s = (uint32_t)__cvta_generic_to_shared(smem_dst);
    asm volatile("cp.async.ca.shared.global [%0], [%1], 16, %2;\n"
                 :: "r"(s), "l"(gsrc), "r"(src_size));
}
__device__ __forceinline__ void cp_commit() { asm volatile("cp.async.commit_group;\n"); }
template <int W> __device__ __forceinline__ void cp_wait() {
    asm volatile("cp.async.wait_group %0;\n" :: "n"(W));
}
__device__ __forceinline__ uint32_t smem_u32(const void* p) {
    return (uint32_t)__cvta_generic_to_shared(p);
}
__device__ __forceinline__ void ldsm_x4(uint32_t& r0, uint32_t& r1, uint32_t& r2,
                                        uint32_t& r3, uint32_t addr) {
    asm volatile("ldmatrix.sync.aligned.m8n8.x4.shared.b16 {%0,%1,%2,%3}, [%4];"
                 : "=r"(r0), "=r"(r1), "=r"(r2), "=r"(r3) : "r"(addr));
}
__device__ __forceinline__ void split_tf32(float v, uint32_t& hi, uint32_t& lo) {
    uint32_t h;
    asm("cvt.rna.tf32.f32 %0, %1;" : "=r"(h) : "f"(v));
    float l = v - __uint_as_float(h);
    uint32_t lt;
    asm("cvt.rna.tf32.f32 %0, %1;" : "=r"(lt) : "f"(l));
    hi = h; lo = lt;
}

// ---------------- tf32 tensor-core GEMM for alpha logits ----------------
// 4 warps, 64x64 warp tiles; ldmatrix loads; TPAD=20; 2-stage ring. (R10 proven)
#define TBM 128
#define TBN 128
#define TBK 16
#define TPAD 20

__global__ __launch_bounds__(128, 2) void alpha_gemm_tf32(
    const float* __restrict__ A,
    const float* __restrict__ Ball,
    const float* __restrict__ biasAll,
    float* __restrict__ Zall)
{
    const int M = NBATCH * NV, N = NVOC, K = NVOC;
    const int KITERS = K / TBK;

    int l = blockIdx.z;
    const float* B = Ball + (size_t)l * N * K;
    const float* bias = biasAll + (size_t)l * N;
    float* C = Zall + (size_t)l * M * N;

    __shared__ float As[2][TBM * TPAD];
    __shared__ float Bs[2][TBN * TPAD];

    int tid = threadIdx.x;
    int m0 = blockIdx.y * TBM;
    int n0 = blockIdx.x * TBN;
    int warp = tid >> 5, lane = tid & 31;
    int wm = (warp & 1) * 64;
    int wn = (warp >> 1) * 64;
    int lq = lane >> 2;
    int lr = lane & 3;
    int tile = lane >> 3, trow = lane & 7;

    float acc[4][8][4];
#pragma unroll
    for (int i = 0; i < 4; i++)
#pragma unroll
        for (int j = 0; j < 8; j++)
#pragma unroll
            for (int r = 0; r < 4; r++) acc[i][j][r] = 0.f;

#define ISSUE_TILES(stage, k0)                                                        \
    do {                                                                              \
        _Pragma("unroll")                                                             \
        for (int t = tid; t < 512; t += 128) {                                        \
            int row = t >> 2, ch = (t & 3) * 4;                                       \
            cp_async16(&As[stage][row * TPAD + ch],                                   \
                       A + (size_t)(m0 + row) * K + (k0) + ch, 16);                   \
        }                                                                             \
        _Pragma("unroll")                                                             \
        for (int t = tid; t < 512; t += 128) {                                        \
            int row = t >> 2, ch = (t & 3) * 4;                                       \
            int gn = n0 + row;                                                        \
            int ok = gn < N;                                                          \
            cp_async16(&Bs[stage][row * TPAD + ch],                                   \
                       B + (size_t)(ok ? gn : 0) * K + (k0) + ch, ok ? 16 : 0);       \
        }                                                                             \
    } while (0)

    ISSUE_TILES(0, 0);
    cp_commit();

    int aRow = wm + ((tile & 1) << 3) + trow;
    int aKof = (tile >> 1) << 2;
    int bCol = wn + ((tile >> 1) << 3) + trow;
    int bKof = (tile & 1) << 2;

    for (int kt = 0; kt < KITERS; kt++) {
        int st = kt & 1;
        if (kt + 1 < KITERS) {
            ISSUE_TILES(st ^ 1, (kt + 1) * TBK);
            cp_commit();
            cp_wait<1>();
        } else {
            cp_wait<0>();
        }
        __syncthreads();

        const float* as = As[st];
        const float* bs = Bs[st];
        uint32_t abase = smem_u32(&as[aRow * TPAD + aKof]);
        uint32_t bbase = smem_u32(&bs[bCol * TPAD + bKof]);

#pragma unroll
        for (int kk = 0; kk < TBK; kk += 8) {
            uint32_t af[4][4];
            uint32_t bf[8][2];
#pragma unroll
            for (int mi = 0; mi < 4; mi++)
                ldsm_x4(af[mi][0], af[mi][1], af[mi][2], af[mi][3],
                        abase + (kk + mi * 16 * TPAD) * 4);
#pragma unroll
            for (int np = 0; np < 4; np++)
                ldsm_x4(bf[2 * np][0], bf[2 * np][1], bf[2 * np + 1][0], bf[2 * np + 1][1],
                        bbase + (kk + np * 16 * TPAD) * 4);
#pragma unroll
            for (int mi = 0; mi < 4; mi++)
#pragma unroll
                for (int ni = 0; ni < 8; ni++) {
                    asm volatile(
                        "mma.sync.aligned.m16n8k8.row.col.f32.tf32.tf32.f32 "
                        "{%0,%1,%2,%3}, {%4,%5,%6,%7}, {%8,%9}, {%0,%1,%2,%3};\n"
                        : "+f"(acc[mi][ni][0]), "+f"(acc[mi][ni][1]),
                          "+f"(acc[mi][ni][2]), "+f"(acc[mi][ni][3])
                        : "r"(af[mi][0]), "r"(af[mi][1]), "r"(af[mi][2]), "r"(af[mi][3]),
                          "r"(bf[ni][0]), "r"(bf[ni][1]));
                }
        }
        __syncthreads();
    }

#pragma unroll
    for (int mi = 0; mi < 4; mi++) {
#pragma unroll
        for (int ni = 0; ni < 8; ni++) {
            int r = m0 + wm + mi * 16 + lq;
            int c = n0 + wn + ni * 8 + lr * 2;
            if (c < N) {
                float2 bb = *(const float2*)(bias + c);
                float2 o0, o1;
                o0.x = acc[mi][ni][0] + bb.x; o0.y = acc[mi][ni][1] + bb.y;
                o1.x = acc[mi][ni][2] + bb.x; o1.y = acc[mi][ni][3] + bb.y;
                *(float2*)(C + (size_t)r * N + c) = o0;
                *(float2*)(C + (size_t)(r + 8) * N + c) = o1;
            }
        }
    }
#undef ISSUE_TILES
}

// ---------------- 3xTF32 compensated mma GEMM: K=128, N=128 -----------------
#define CPW 36

template <bool RELU, bool ADD2>
__global__ __launch_bounds__(256) void gemm128_3xtf32(
    const float* __restrict__ A, const float* __restrict__ A2,
    const float* __restrict__ B, const float* __restrict__ bias,
    float* __restrict__ C, int M)
{
    __shared__ float As[128 * CPW];
    __shared__ float Bs[128 * CPW];

    int tid = threadIdx.x;
    int m0 = blockIdx.x * 128;
    int warp = tid >> 5, lane = tid & 31;
    int wm = (warp & 1) * 64;
    int wn = (warp >> 1) * 32;
    int lq = lane >> 2;
    int lr = lane & 3;

    float acc[4][4][4];
#pragma unroll
    for (int i = 0; i < 4; i++)
#pragma unroll
        for (int j = 0; j < 4; j++)
#pragma unroll
            for (int r = 0; r < 4; r++) acc[i][j][r] = 0.f;

    for (int k0 = 0; k0 < NH; k0 += 32) {
        __syncthreads();
#pragma unroll
        for (int t = tid; t < 1024; t += 256) {
            int row = t >> 3, seg = (t & 7) * 4;
            int gm = m0 + row;
            float4 v = {0, 0, 0, 0};
            if (gm < M) {
                v = *(const float4*)(A + (size_t)gm * NH + k0 + seg);
                if (ADD2) {
                    float4 w = *(const float4*)(A2 + (size_t)gm * NH + k0 + seg);
                    v.x += w.x; v.y += w.y; v.z += w.z; v.w += w.w;
                }
            }
            *(float4*)&As[row * CPW + seg] = v;
            *(float4*)&Bs[row * CPW + seg] = *(const float4*)(B + (size_t)row * NH + k0 + seg);
        }
        __syncthreads();

#pragma unroll
        for (int kk = 0; kk < 32; kk += 8) {
            uint32_t ah[4][4], al[4][4];
            uint32_t bh[4][2], bl[4][2];
#pragma unroll
            for (int mi = 0; mi < 4; mi++) {
                int base = (wm + mi * 16 + lq) * CPW + kk + lr;
                split_tf32(As[base],               ah[mi][0], al[mi][0]);
                split_tf32(As[base + 8 * CPW],     ah[mi][1], al[mi][1]);
                split_tf32(As[base + 4],           ah[mi][2], al[mi][2]);
                split_tf32(As[base + 8 * CPW + 4], ah[mi][3], al[mi][3]);
            }
#pragma unroll
            for (int ni = 0; ni < 4; ni++) {
                int base = (wn + ni * 8 + lq) * CPW + kk + lr;
                split_tf32(Bs[base],     bh[ni][0], bl[ni][0]);
                split_tf32(Bs[base + 4], bh[ni][1], bl[ni][1]);
            }
#define MMA_TF32(Aop, Bop)                                                            \
    asm volatile(                                                                     \
        "mma.sync.aligned.m16n8k8.row.col.f32.tf32.tf32.f32 "                         \
        "{%0,%1,%2,%3}, {%4,%5,%6,%7}, {%8,%9}, {%0,%1,%2,%3};\n"                     \
        : "+f"(acc[mi][ni][0]), "+f"(acc[mi][ni][1]),                                 \
          "+f"(acc[mi][ni][2]), "+f"(acc[mi][ni][3])                                  \
        : "r"(Aop[mi][0]), "r"(Aop[mi][1]), "r"(Aop[mi][2]), "r"(Aop[mi][3]),         \
          "r"(Bop[ni][0]), "r"(Bop[ni][1]))
#pragma unroll
            for (int mi = 0; mi < 4; mi++)
#pragma unroll
                for (int ni = 0; ni < 4; ni++) {
                    MMA_TF32(ah, bh);
                    MMA_TF32(ah, bl);
                    MMA_TF32(al, bh);
                }
#undef MMA_TF32
        }
    }

#pragma unroll
    for (int mi = 0; mi < 4; mi++) {
#pragma unroll
        for (int ni = 0; ni < 4; ni++) {
            int r = m0 + wm + mi * 16 + lq;
            int c = wn + ni * 8 + lr * 2;
            float2 bb = *(const float2*)(bias + c);
            float2 o0, o1;
            o0.x = acc[mi][ni][0] + bb.x; o0.y = acc[mi][ni][1] + bb.y;
            o1.x = acc[mi][ni][2] + bb.x; o1.y = acc[mi][ni][3] + bb.y;
            if (RELU) {
                o0.x = fmaxf(o0.x, 0.f); o0.y = fmaxf(o0.y, 0.f);
                o1.x = fmaxf(o1.x, 0.f); o1.y = fmaxf(o1.y, 0.f);
            }
            if (r < M)     *(float2*)(C + (size_t)r * NH + c) = o0;
            if (r + 8 < M) *(float2*)(C + (size_t)(r + 8) * NH + c) = o1;
        }
    }
}

// ---------------- small kernels ----------------
__global__ void k_zero_int(int* __restrict__ p, int n) {
    int i = blockIdx.x * blockDim.x + threadIdx.x;
    if (i < n) p[i] = 0;
}
__global__ void k_zero_float(float* __restrict__ p, int n) {
    int i = blockIdx.x * blockDim.x + threadIdx.x;
    if (i < n) p[i] = 0.f;
}

__global__ void k_hist(const int* __restrict__ keys, int* __restrict__ cnt, int n) {
    int i = blockIdx.x * blockDim.x + threadIdx.x;
    if (i < n) atomicAdd(&cnt[keys[i]], 1);
}

__global__ void k_hist_batch(const int* __restrict__ batch, int* __restrict__ bcnt) {
    __shared__ int h[NBATCH];
    if (threadIdx.x < NBATCH) h[threadIdx.x] = 0;
    __syncthreads();
    int i = blockIdx.x * blockDim.x + threadIdx.x;
    if (i < NNODES) atomicAdd(&h[batch[i]], 1);
    __syncthreads();
    if (threadIdx.x < NBATCH) atomicAdd(&bcnt[threadIdx.x], h[threadIdx.x]);
}

__global__ void k_scan_block(const int* __restrict__ in, int* __restrict__ outEx,
                             int* __restrict__ part, int n) {
    __shared__ int s[1024];
    int t = threadIdx.x;
    int i = blockIdx.x * 1024 + t;
    int v = (i < n) ? in[i] : 0;
    s[t] = v;
    __syncthreads();
    for (int off = 1; off < 1024; off <<= 1) {
        int y = (t >= off) ? s[t - off] : 0;
        __syncthreads();
        s[t] += y;
        __syncthreads();
    }
    if (i < n) outEx[i] = s[t] - v;
    if (t == 1023) part[blockIdx.x] = s[1023];
}

__global__ void k_scan_part(int* __restrict__ part, int nb, int* __restrict__ rowstart) {
    if (threadIdx.x == 0 && blockIdx.x == 0) {
        int acc = 0;
        for (int i = 0; i < nb; i++) { int v = part[i]; part[i] = acc; acc += v; }
        rowstart[NNODES] = NEDGES;
    }
}

__global__ void k_scan_add(int* __restrict__ rowstart, const int* __restrict__ part,
                           int* __restrict__ cursor, int n) {
    int i = blockIdx.x * 1024 + threadIdx.x;
    if (i < n) {
        int v = rowstart[i] + part[blockIdx.x];
        rowstart[i] = v;
        cursor[i] = v;
    }
}

__global__ void k_scatter(const int* __restrict__ dst, int* __restrict__ cursor,
                          int* __restrict__ elist, int n) {
    int e = blockIdx.x * blockDim.x + threadIdx.x;
    if (e < n) {
        int d = dst[e];
        int p = atomicAdd(&cursor[d], 1);
        elist[p] = e;
    }
}

__global__ void k_bscan(const int* __restrict__ bcnt, int* __restrict__ bstart) {
    if (threadIdx.x == 0 && blockIdx.x == 0) {
        int acc = 0;
        for (int b = 0; b < NBATCH; b++) { bstart[b] = acc; acc += bcnt[b]; }
        bstart[NBATCH] = acc;
    }
}

__global__ void k_wrel(const float* __restrict__ Erel, const float* __restrict__ wr_w,
                       const float* __restrict__ wr_b, float* __restrict__ wrel) {
    int w = (blockIdx.x * blockDim.x + threadIdx.x) >> 5;
    int lane = threadIdx.x & 31;
    if (w >= NL * NREL) return;
    int l = w / NREL, r = w % NREL;
    float acc = 0.f;
#pragma unroll
    for (int h = lane; h < NH; h += 32) acc += Erel[r * NH + h] * wr_w[l * NH + h];
#pragma unroll
    for (int o = 16; o; o >>= 1) acc += __shfl_down_sync(0xffffffffu, acc, o);
    if (lane == 0) wrel[w] = acc + wr_b[l];
}

__global__ void k_gather(const float* __restrict__ Enode, const int* __restrict__ node_ids,
                         float* __restrict__ x) {
    int t = blockIdx.x * blockDim.x + threadIdx.x;
    if (t >= NNODES * 32) return;
    int i = t >> 5, q = t & 31;
    int nid = node_ids[i];
    *(float4*)(x + (size_t)i * NH + q * 4) =
        *(const float4*)(Enode + (size_t)nid * NH + q * 4);
}

__global__ void k_beta(const float* __restrict__ vn, const float* __restrict__ beta_w,
                       const float* __restrict__ beta_b, float* __restrict__ betaOut) {
    int w = (blockIdx.x * blockDim.x + threadIdx.x) >> 5;
    int lane = threadIdx.x & 31;
    if (w >= NL * NBATCH * NV) return;
    int l = w / (NBATCH * NV);
    int rem = w % (NBATCH * NV);
    int b = rem / NV, v = rem % NV;
    const float* row = vn + ((size_t)b * NV + v) * NVOC;
    const float* bw = beta_w + l * NVOC;
    float acc = 0.f;
    for (int n = lane; n < NVOC; n += 32) acc += row[n] * bw[n];
#pragma unroll
    for (int o = 16; o; o >>= 1) acc += __shfl_down_sync(0xffffffffu, acc, o);
    if (lane == 0)
        betaOut[w] = tanhf(acc + beta_b[l]) * expf(0.03f * (float)(NV - v));
}

__global__ void k_attn(const float* __restrict__ Zall, const float* __restrict__ betaAll,
                       float* __restrict__ attnAll) {
    int m = blockIdx.x * blockDim.x + threadIdx.x;
    int b = blockIdx.y;
    int l = blockIdx.z;
    if (m >= NVOC) return;
    const float* Z = Zall + (size_t)l * NBATCH * NV * NVOC;
    const float* betaL = betaAll + l * NBATCH * NV;
    float z[NV];
    float mx = -1e30f;
#pragma unroll
    for (int v = 0; v < NV; v++) {
        z[v] = Z[((size_t)(b * NV + v)) * NVOC + m];
        mx = fmaxf(mx, z[v]);
    }
    float s = 0.f, num = 0.f;
#pragma unroll
    for (int v = 0; v < NV; v++) {
        float e = expf(z[v] - mx);
        s += e;
        num += e * betaL[b * NV + v];
    }
    attnAll[((size_t)l * NBATCH + b) * NVOC + m] = num / s;
}

// warp-per-node aggregate (R4 proven version)
__global__ void k_aggregate(const float* __restrict__ x, const float* __restrict__ Erel,
                            const float* __restrict__ attnL, const float* __restrict__ wrelL,
                            const int* __restrict__ elist, const int* __restrict__ rowstart,
                            const int* __restrict__ srcArr, const int* __restrict__ ridArr,
                            const int* __restrict__ nodeIds, const int* __restrict__ batchArr,
                            float* __restrict__ agg) {
    int warp = (blockIdx.x * blockDim.x + threadIdx.x) >> 5;
    int lane = threadIdx.x & 31;
    if (warp >= NNODES) return;
    int s0 = rowstart[warp], s1 = rowstart[warp + 1];
    float4 acc = {0.f, 0.f, 0.f, 0.f};
    for (int idx = s0; idx < s1; idx++) {
        int e = elist[idx];
        int s = srcArr[e];
        int r = ridArr[e];
        float ea = attnL[(size_t)batchArr[s] * NVOC + nodeIds[s]];
        float w = wrelL[r];
        float4 xv = *(const float4*)(x + (size_t)s * NH + lane * 4);
        float4 ev = *(const float4*)(Erel + (size_t)r * NH + lane * 4);
        acc.x += fmaxf(fmaf(xv.x, ea, w * ev.x), 0.f);
        acc.y += fmaxf(fmaf(xv.y, ea, w * ev.y), 0.f);
        acc.z += fmaxf(fmaf(xv.z, ea, w * ev.z), 0.f);
        acc.w += fmaxf(fmaf(xv.w, ea, w * ev.w), 0.f);
    }
    *(float4*)(agg + (size_t)warp * NH + lane * 4) = acc;
}

__global__ void k_pool_partial(const float* __restrict__ x, const int* __restrict__ bstart,
                               float* __restrict__ xg) {
    int b = blockIdx.y, chunk = blockIdx.x, h = threadIdx.x;
    int s0 = bstart[b], s1 = bstart[b + 1];
    int len = s1 - s0;
    int r0 = s0 + (int)((long long)len * chunk / 8);
    int r1 = s0 + (int)((long long)len * (chunk + 1) / 8);
    float acc = 0.f;
    for (int i = r0; i < r1; i++) acc += x[(size_t)i * NH + h];
    atomicAdd(&xg[b * NH + h], acc);
}

__global__ void k_pool_finish(float* __restrict__ xg, const int* __restrict__ bcnt) {
    int b = blockIdx.x, h = threadIdx.x;
    float c = (float)bcnt[b];
    xg[b * NH + h] /= fmaxf(c, 1.f);
}

__global__ void k_ehrsum(const float* __restrict__ ehr, float* __restrict__ den) {
    int b = blockIdx.x, t = threadIdx.x;
    __shared__ float s[256];
    float acc = 0.f;
    for (int n = t; n < NVOC; n += 256) acc += ehr[(size_t)b * NVOC + n];
    s[t] = acc;
    __syncthreads();
    for (int o = 128; o; o >>= 1) {
        if (t < o) s[t] += s[t + o];
        __syncthreads();
    }
    if (t == 0) den[b] = s[0];
}

__global__ void k_xnode_partial(const float* __restrict__ ehr,
                                const float* __restrict__ node_emb,
                                float* __restrict__ xacc) {
    int b = blockIdx.y, slice = blockIdx.x, h = threadIdx.x;
    int n0 = slice * (NVOC / 16), n1 = n0 + (NVOC / 16);
    float acc = 0.f;
    for (int n = n0; n < n1; n++)
        acc += ehr[(size_t)b * NVOC + n] * node_emb[(size_t)n * NH + h];
    atomicAdd(&xacc[b * NH + h], acc);
}

__global__ void k_xnode_finish(const float* __restrict__ xacc, const float* __restrict__ den,
                               const float* __restrict__ lin_w, const float* __restrict__ lin_b,
                               float* __restrict__ xnode) {
    int b = blockIdx.x, h = threadIdx.x;
    __shared__ float t[NH];
    t[h] = xacc[b * NH + h] / den[b];
    __syncthreads();
    float s = 0.f;
#pragma unroll 8
    for (int hh = 0; hh < NH; hh++) s += t[hh] * lin_w[h * NH + hh];
    xnode[b * NH + h] = s + lin_b[h];
}

__global__ void k_final(const float* __restrict__ xg, const float* __restrict__ xn,
                        const float* __restrict__ mlp_w, const float* __restrict__ mlp_b,
                        float* __restrict__ out) {
    int b = blockIdx.x, t = threadIdx.x;
    __shared__ float s[2 * NH];
    s[t] = xg[b * NH + t];
    s[NH + t] = xn[b * NH + t];
    __syncthreads();
    if (t < NOUT) {
        float acc = mlp_b[t];
        const float* w = mlp_w + t * (2 * NH);
#pragma unroll 8
        for (int k = 0; k < 2 * NH; k++) acc += s[k] * w[k];
        out[b * NOUT + t] = acc;
    }
}

// ---------------- launch ----------------
extern "C" void kernel_launch(void* const* d_in, const int* in_sizes, int n_in,
                              void* d_out, int out_size) {
    const float* node_emb = (const float*)d_in[0];
    const float* rel_emb  = (const float*)d_in[1];
    const float* lin_w    = (const float*)d_in[2];
    const float* lin_b    = (const float*)d_in[3];
    const float* alpha_w  = (const float*)d_in[4];
    const float* alpha_b  = (const float*)d_in[5];
    const float* beta_w   = (const float*)d_in[6];
    const float* beta_b   = (const float*)d_in[7];
    const float* wr_w     = (const float*)d_in[8];
    const float* wr_b     = (const float*)d_in[9];
    const float* conv_w   = (const float*)d_in[10];
    const float* conv_b   = (const float*)d_in[11];
    const float* mlp_w    = (const float*)d_in[12];
    const float* mlp_b    = (const float*)d_in[13];
    const float* visit    = (const float*)d_in[14];
    const float* ehr      = (const float*)d_in[15];
    const int* node_ids   = (const int*)d_in[16];
    const int* rel_ids    = (const int*)d_in[17];
    const int* eidx       = (const int*)d_in[18];
    const int* batch      = (const int*)d_in[19];
    float* out = (float*)d_out;

    const int* srcArr = eidx;
    const int* dstArr = eidx + NEDGES;

    float *Zp, *Enodep, *Erelp, *wrelp, *attnp, *betap, *xp, *x2p, *aggp;
    float *xgp, *xaccp, *denp, *xnodep;
    int *degp, *rowstartp, *cursorp, *elistp, *partp, *bcntp, *bstartp;
    cudaGetSymbolAddress((void**)&Zp, g_Z);
    cudaGetSymbolAddress((void**)&Enodep, g_Enode);
    cudaGetSymbolAddress((void**)&Erelp, g_Erel);
    cudaGetSymbolAddress((void**)&wrelp, g_wrel);
    cudaGetSymbolAddress((void**)&attnp, g_attn);
    cudaGetSymbolAddress((void**)&betap, g_beta);
    cudaGetSymbolAddress((void**)&xp, g_x);
    cudaGetSymbolAddress((void**)&x2p, g_x2);
    cudaGetSymbolAddress((void**)&aggp, g_agg);
    cudaGetSymbolAddress((void**)&xgp, g_xg);
    cudaGetSymbolAddress((void**)&xaccp, g_xacc);
    cudaGetSymbolAddress((void**)&denp, g_den);
    cudaGetSymbolAddress((void**)&xnodep, g_xnode);
    cudaGetSymbolAddress((void**)&degp, g_deg);
    cudaGetSymbolAddress((void**)&rowstartp, g_rowstart);
    cudaGetSymbolAddress((void**)&cursorp, g_cursor);
    cudaGetSymbolAddress((void**)&elistp, g_elist);
    cudaGetSymbolAddress((void**)&partp, g_part);
    cudaGetSymbolAddress((void**)&bcntp, g_bcnt);
    cudaGetSymbolAddress((void**)&bstartp, g_bstart);

    // One-time resource creation (host handles only; no device memory).
    static cudaStream_t sSide = nullptr;
    static cudaEvent_t evFork = nullptr, evJoin = nullptr;
    if (sSide == nullptr) {
        cudaStreamCreateWithFlags(&sSide, cudaStreamNonBlocking);
        cudaEventCreateWithFlags(&evFork, cudaEventDisableTiming);
        cudaEventCreateWithFlags(&evJoin, cudaEventDisableTiming);
    }

    const int SCAN_BLOCKS = (NNODES + 1023) / 1024;

    // ---- fork: side stream does alpha-independent work ----
    cudaEventRecord(evFork, 0);
    cudaStreamWaitEvent(sSide, evFork, 0);

    // main stream: alpha logits (dominant, ~390us)
    alpha_gemm_tf32<<<dim3((NVOC + TBN - 1) / TBN, (NBATCH * NV) / TBM, NL), 128>>>(
        visit, alpha_w, alpha_b, Zp);

    // side stream: feature precompute + CSR build
    gemm128_3xtf32<false, false><<<(NVOC + 127) / 128, 256, 0, sSide>>>(
        node_emb, nullptr, lin_w, lin_b, Enodep, NVOC);
    gemm128_3xtf32<false, false><<<(NREL + 127) / 128, 256, 0, sSide>>>(
        rel_emb, nullptr, lin_w, lin_b, Erelp, NREL);
    k_wrel<<<(NL * NREL * 32 + 255) / 256, 256, 0, sSide>>>(Erelp, wr_w, wr_b, wrelp);
    k_gather<<<(NNODES * 32 + 255) / 256, 256, 0, sSide>>>(Enodep, node_ids, xp);
    k_beta<<<(NL * NBATCH * NV * 32 + 255) / 256, 256, 0, sSide>>>(
        visit, beta_w, beta_b, betap);
    k_zero_int<<<(NNODES + 255) / 256, 256, 0, sSide>>>(degp, NNODES);
    k_zero_int<<<1, 64, 0, sSide>>>(bcntp, NBATCH);
    k_hist<<<(NEDGES + 255) / 256, 256, 0, sSide>>>(dstArr, degp, NEDGES);
    k_hist_batch<<<(NNODES + 255) / 256, 256, 0, sSide>>>(batch, bcntp);
    k_scan_block<<<SCAN_BLOCKS, 1024, 0, sSide>>>(degp, rowstartp, partp, NNODES);
    k_scan_part<<<1, 1, 0, sSide>>>(partp, SCAN_BLOCKS, rowstartp);
    k_scan_add<<<SCAN_BLOCKS, 1024, 0, sSide>>>(rowstartp, partp, cursorp, NNODES);
    k_scatter<<<(NEDGES + 255) / 256, 256, 0, sSide>>>(dstArr, cursorp, elistp, NEDGES);
    k_bscan<<<1, 1, 0, sSide>>>(bcntp, bstartp);
    k_zero_float<<<(NBATCH * NH + 255) / 256, 256, 0, sSide>>>(xgp, NBATCH * NH);
    k_zero_float<<<(NBATCH * NH + 255) / 256, 256, 0, sSide>>>(xaccp, NBATCH * NH);
    k_ehrsum<<<NBATCH, 256, 0, sSide>>>(ehr, denp);
    k_xnode_partial<<<dim3(16, NBATCH), NH, 0, sSide>>>(ehr, node_emb, xaccp);
    k_xnode_finish<<<NBATCH, NH, 0, sSide>>>(xaccp, denp, lin_w, lin_b, xnodep);

    // ---- join ----
    cudaEventRecord(evJoin, sSide);
    cudaStreamWaitEvent(0, evJoin, 0);

    // needs Z (main) + beta (side)
    k_attn<<<dim3((NVOC + 255) / 256, NBATCH, NL), 256>>>(Zp, betap, attnp);

    // message-passing layers
    float* xcur = xp;
    float* xalt = x2p;
    for (int l = 0; l < NL; l++) {
        k_aggregate<<<(NNODES * 32 + 255) / 256, 256>>>(
            xcur, Erelp, attnp + (size_t)l * NBATCH * NVOC, wrelp + l * NREL,
            elistp, rowstartp, srcArr, rel_ids, node_ids, batch, aggp);
        gemm128_3xtf32<true, true><<<(NNODES + 127) / 128, 256>>>(
            aggp, xcur, conv_w + (size_t)l * NH * NH, conv_b + (size_t)l * NH,
            xalt, NNODES);
        float* tmp = xcur; xcur = xalt; xalt = tmp;
    }

    // heads
    k_pool_partial<<<dim3(8, NBATCH), NH>>>(xcur, bstartp, xgp);
    k_pool_finish<<<NBATCH, NH>>>(xgp, bcntp);
    k_final<<<NBATCH, NH>>>(xgp, xnodep, mlp_w, mlp_b, out);
}

// round 13
// speedup vs baseline: 4.2951x; 1.1736x over previous
#include <cuda_runtime.h>
#include <math.h>
#include <stdint.h>

#define NNODES 50000
#define NEDGES 800000
#define NBATCH 32
#define NV 20
#define NVOC 4000
#define NREL 200
#define NH 128
#define NL 3
#define NOUT 100

// ---------------- device scratch ----------------
__device__ float g_Z[(size_t)NL * NBATCH * NV * NVOC];
__device__ float g_Enode[NVOC * NH];
__device__ float g_Erel[NREL * NH];
__device__ float g_wrel[NL * NREL];
__device__ float g_attn[(size_t)NL * NBATCH * NVOC];
__device__ float g_beta[NL * NBATCH * NV];
__device__ float g_x[(size_t)NNODES * NH];
__device__ float g_x2[(size_t)NNODES * NH];
__device__ float g_agg[(size_t)NNODES * NH];
__device__ int   g_deg[NNODES];
__device__ int   g_rowstart[NNODES + 1];
__device__ int   g_cursor[NNODES];
__device__ int   g_elist[NEDGES];
__device__ int   g_esrc[NEDGES];
__device__ int   g_erid[NEDGES];
__device__ int   g_eaidx[NEDGES];
__device__ int   g_part[64];
__device__ int   g_bcnt[NBATCH];
__device__ int   g_bstart[NBATCH + 1];
__device__ float g_xg[NBATCH * NH];
__device__ float g_xacc[NBATCH * NH];
__device__ float g_den[NBATCH];
__device__ float g_xnode[NBATCH * NH];

// ---------------- helpers ----------------
__device__ __forceinline__ void cp_async16(void* smem_dst, const void* gsrc, int src_size) {
    uint32_t s = (uint32_t)__cvta_generic_to_shared(smem_dst);
    asm volatile("cp.async.ca.shared.global [%0], [%1], 16, %2;\n"
                 :: "r"(s), "l"(gsrc), "r"(src_size));
}
__device__ __forceinline__ void cp_commit() { asm volatile("cp.async.commit_group;\n"); }
template <int W> __device__ __forceinline__ void cp_wait() {
    asm volatile("cp.async.wait_group %0;\n" :: "n"(W));
}
__device__ __forceinline__ uint32_t smem_u32(const void* p) {
    return (uint32_t)__cvta_generic_to_shared(p);
}
__device__ __forceinline__ void ldsm_x4(uint32_t& r0, uint32_t& r1, uint32_t& r2,
                                        uint32_t& r3, uint32_t addr) {
    asm volatile("ldmatrix.sync.aligned.m8n8.x4.shared.b16 {%0,%1,%2,%3}, [%4];"
                 : "=r"(r0), "=r"(r1), "=r"(r2), "=r"(r3) : "r"(addr));
}
__device__ __forceinline__ void split_tf32(float v, uint32_t& hi, uint32_t& lo) {
    uint32_t h;
    asm("cvt.rna.tf32.f32 %0, %1;" : "=r"(h) : "f"(v));
    float l = v - __uint_as_float(h);
    uint32_t lt;
    asm("cvt.rna.tf32.f32 %0, %1;" : "=r"(lt) : "f"(l));
    hi = h; lo = lt;
}

// ---------------- tf32 tensor-core GEMM for alpha logits ----------------
// One layer per launch (grid.z=1, pre-offset pointers). 4 warps, 64x64 warp
// tiles; ldmatrix loads; TPAD=20; 2-stage ring. (R10 proven)
#define TBM 128
#define TBN 128
#define TBK 16
#define TPAD 20

__global__ __launch_bounds__(128, 2) void alpha_gemm_tf32(
    const float* __restrict__ A,
    const float* __restrict__ B,
    const float* __restrict__ bias,
    float* __restrict__ C)
{
    const int M = NBATCH * NV, N = NVOC, K = NVOC;
    const int KITERS = K / TBK;

    __shared__ float As[2][TBM * TPAD];
    __shared__ float Bs[2][TBN * TPAD];

    int tid = threadIdx.x;
    int m0 = blockIdx.y * TBM;
    int n0 = blockIdx.x * TBN;
    int warp = tid >> 5, lane = tid & 31;
    int wm = (warp & 1) * 64;
    int wn = (warp >> 1) * 64;
    int lq = lane >> 2;
    int lr = lane & 3;
    int tile = lane >> 3, trow = lane & 7;

    float acc[4][8][4];
#pragma unroll
    for (int i = 0; i < 4; i++)
#pragma unroll
        for (int j = 0; j < 8; j++)
#pragma unroll
            for (int r = 0; r < 4; r++) acc[i][j][r] = 0.f;

#define ISSUE_TILES(stage, k0)                                                        \
    do {                                                                              \
        _Pragma("unroll")                                                             \
        for (int t = tid; t < 512; t += 128) {                                        \
            int row = t >> 2, ch = (t & 3) * 4;                                       \
            cp_async16(&As[stage][row * TPAD + ch],                                   \
                       A + (size_t)(m0 + row) * K + (k0) + ch, 16);                   \
        }                                                                             \
        _Pragma("unroll")                                                             \
        for (int t = tid; t < 512; t += 128) {                                        \
            int row = t >> 2, ch = (t & 3) * 4;                                       \
            int gn = n0 + row;                                                        \
            int ok = gn < N;                                                          \
            cp_async16(&Bs[stage][row * TPAD + ch],                                   \
                       B + (size_t)(ok ? gn : 0) * K + (k0) + ch, ok ? 16 : 0);       \
        }                                                                             \
    } while (0)

    ISSUE_TILES(0, 0);
    cp_commit();

    int aRow = wm + ((tile & 1) << 3) + trow;
    int aKof = (tile >> 1) << 2;
    int bCol = wn + ((tile >> 1) << 3) + trow;
    int bKof = (tile & 1) << 2;

    for (int kt = 0; kt < KITERS; kt++) {
        int st = kt & 1;
        if (kt + 1 < KITERS) {
            ISSUE_TILES(st ^ 1, (kt + 1) * TBK);
            cp_commit();
            cp_wait<1>();
        } else {
            cp_wait<0>();
        }
        __syncthreads();

        const float* as = As[st];
        const float* bs = Bs[st];
        uint32_t abase = smem_u32(&as[aRow * TPAD + aKof]);
        uint32_t bbase = smem_u32(&bs[bCol * TPAD + bKof]);

#pragma unroll
        for (int kk = 0; kk < TBK; kk += 8) {
            uint32_t af[4][4];
            uint32_t bf[8][2];
#pragma unroll
            for (int mi = 0; mi < 4; mi++)
                ldsm_x4(af[mi][0], af[mi][1], af[mi][2], af[mi][3],
                        abase + (kk + mi * 16 * TPAD) * 4);
#pragma unroll
            for (int np = 0; np < 4; np++)
                ldsm_x4(bf[2 * np][0], bf[2 * np][1], bf[2 * np + 1][0], bf[2 * np + 1][1],
                        bbase + (kk + np * 16 * TPAD) * 4);
#pragma unroll
            for (int mi = 0; mi < 4; mi++)
#pragma unroll
                for (int ni = 0; ni < 8; ni++) {
                    asm volatile(
                        "mma.sync.aligned.m16n8k8.row.col.f32.tf32.tf32.f32 "
                        "{%0,%1,%2,%3}, {%4,%5,%6,%7}, {%8,%9}, {%0,%1,%2,%3};\n"
                        : "+f"(acc[mi][ni][0]), "+f"(acc[mi][ni][1]),
                          "+f"(acc[mi][ni][2]), "+f"(acc[mi][ni][3])
                        : "r"(af[mi][0]), "r"(af[mi][1]), "r"(af[mi][2]), "r"(af[mi][3]),
                          "r"(bf[ni][0]), "r"(bf[ni][1]));
                }
        }
        __syncthreads();
    }

#pragma unroll
    for (int mi = 0; mi < 4; mi++) {
#pragma unroll
        for (int ni = 0; ni < 8; ni++) {
            int r = m0 + wm + mi * 16 + lq;
            int c = n0 + wn + ni * 8 + lr * 2;
            if (c < N) {
                float2 bb = *(const float2*)(bias + c);
                float2 o0, o1;
                o0.x = acc[mi][ni][0] + bb.x; o0.y = acc[mi][ni][1] + bb.y;
                o1.x = acc[mi][ni][2] + bb.x; o1.y = acc[mi][ni][3] + bb.y;
                *(float2*)(C + (size_t)r * N + c) = o0;
                *(float2*)(C + (size_t)(r + 8) * N + c) = o1;
            }
        }
    }
#undef ISSUE_TILES
}

// ---------------- 3xTF32 compensated mma GEMM: K=128, N=128 -----------------
#define CPW 36

template <bool RELU, bool ADD2>
__global__ __launch_bounds__(256) void gemm128_3xtf32(
    const float* __restrict__ A, const float* __restrict__ A2,
    const float* __restrict__ B, const float* __restrict__ bias,
    float* __restrict__ C, int M)
{
    __shared__ float As[128 * CPW];
    __shared__ float Bs[128 * CPW];

    int tid = threadIdx.x;
    int m0 = blockIdx.x * 128;
    int warp = tid >> 5, lane = tid & 31;
    int wm = (warp & 1) * 64;
    int wn = (warp >> 1) * 32;
    int lq = lane >> 2;
    int lr = lane & 3;

    float acc[4][4][4];
#pragma unroll
    for (int i = 0; i < 4; i++)
#pragma unroll
        for (int j = 0; j < 4; j++)
#pragma unroll
            for (int r = 0; r < 4; r++) acc[i][j][r] = 0.f;

    for (int k0 = 0; k0 < NH; k0 += 32) {
        __syncthreads();
#pragma unroll
        for (int t = tid; t < 1024; t += 256) {
            int row = t >> 3, seg = (t & 7) * 4;
            int gm = m0 + row;
            float4 v = {0, 0, 0, 0};
            if (gm < M) {
                v = *(const float4*)(A + (size_t)gm * NH + k0 + seg);
                if (ADD2) {
                    float4 w = *(const float4*)(A2 + (size_t)gm * NH + k0 + seg);
                    v.x += w.x; v.y += w.y; v.z += w.z; v.w += w.w;
                }
            }
            *(float4*)&As[row * CPW + seg] = v;
            *(float4*)&Bs[row * CPW + seg] = *(const float4*)(B + (size_t)row * NH + k0 + seg);
        }
        __syncthreads();

#pragma unroll
        for (int kk = 0; kk < 32; kk += 8) {
            uint32_t ah[4][4], al[4][4];
            uint32_t bh[4][2], bl[4][2];
#pragma unroll
            for (int mi = 0; mi < 4; mi++) {
                int base = (wm + mi * 16 + lq) * CPW + kk + lr;
                split_tf32(As[base],               ah[mi][0], al[mi][0]);
                split_tf32(As[base + 8 * CPW],     ah[mi][1], al[mi][1]);
                split_tf32(As[base + 4],           ah[mi][2], al[mi][2]);
                split_tf32(As[base + 8 * CPW + 4], ah[mi][3], al[mi][3]);
            }
#pragma unroll
            for (int ni = 0; ni < 4; ni++) {
                int base = (wn + ni * 8 + lq) * CPW + kk + lr;
                split_tf32(Bs[base],     bh[ni][0], bl[ni][0]);
                split_tf32(Bs[base + 4], bh[ni][1], bl[ni][1]);
            }
#define MMA_TF32(Aop, Bop)                                                            \
    asm volatile(                                                                     \
        "mma.sync.aligned.m16n8k8.row.col.f32.tf32.tf32.f32 "                         \
        "{%0,%1,%2,%3}, {%4,%5,%6,%7}, {%8,%9}, {%0,%1,%2,%3};\n"                     \
        : "+f"(acc[mi][ni][0]), "+f"(acc[mi][ni][1]),                                 \
          "+f"(acc[mi][ni][2]), "+f"(acc[mi][ni][3])                                  \
        : "r"(Aop[mi][0]), "r"(Aop[mi][1]), "r"(Aop[mi][2]), "r"(Aop[mi][3]),         \
          "r"(Bop[ni][0]), "r"(Bop[ni][1]))
#pragma unroll
            for (int mi = 0; mi < 4; mi++)
#pragma unroll
                for (int ni = 0; ni < 4; ni++) {
                    MMA_TF32(ah, bh);
                    MMA_TF32(ah, bl);
                    MMA_TF32(al, bh);
                }
#undef MMA_TF32
        }
    }

#pragma unroll
    for (int mi = 0; mi < 4; mi++) {
#pragma unroll
        for (int ni = 0; ni < 4; ni++) {
            int r = m0 + wm + mi * 16 + lq;
            int c = wn + ni * 8 + lr * 2;
            float2 bb = *(const float2*)(bias + c);
            float2 o0, o1;
            o0.x = acc[mi][ni][0] + bb.x; o0.y = acc[mi][ni][1] + bb.y;
            o1.x = acc[mi][ni][2] + bb.x; o1.y = acc[mi][ni][3] + bb.y;
            if (RELU) {
                o0.x = fmaxf(o0.x, 0.f); o0.y = fmaxf(o0.y, 0.f);
                o1.x = fmaxf(o1.x, 0.f); o1.y = fmaxf(o1.y, 0.f);
            }
            if (r < M)     *(float2*)(C + (size_t)r * NH + c) = o0;
            if (r + 8 < M) *(float2*)(C + (size_t)(r + 8) * NH + c) = o1;
        }
    }
}

// ---------------- small kernels ----------------
__global__ void k_zero_int(int* __restrict__ p, int n) {
    int i = blockIdx.x * blockDim.x + threadIdx.x;
    if (i < n) p[i] = 0;
}
__global__ void k_zero_float(float* __restrict__ p, int n) {
    int i = blockIdx.x * blockDim.x + threadIdx.x;
    if (i < n) p[i] = 0.f;
}

__global__ void k_hist(const int* __restrict__ keys, int* __restrict__ cnt, int n) {
    int i = blockIdx.x * blockDim.x + threadIdx.x;
    if (i < n) atomicAdd(&cnt[keys[i]], 1);
}

__global__ void k_hist_batch(const int* __restrict__ batch, int* __restrict__ bcnt) {
    __shared__ int h[NBATCH];
    if (threadIdx.x < NBATCH) h[threadIdx.x] = 0;
    __syncthreads();
    int i = blockIdx.x * blockDim.x + threadIdx.x;
    if (i < NNODES) atomicAdd(&h[batch[i]], 1);
    __syncthreads();
    if (threadIdx.x < NBATCH) atomicAdd(&bcnt[threadIdx.x], h[threadIdx.x]);
}

__global__ void k_scan_block(const int* __restrict__ in, int* __restrict__ outEx,
                             int* __restrict__ part, int n) {
    __shared__ int s[1024];
    int t = threadIdx.x;
    int i = blockIdx.x * 1024 + t;
    int v = (i < n) ? in[i] : 0;
    s[t] = v;
    __syncthreads();
    for (int off = 1; off < 1024; off <<= 1) {
        int y = (t >= off) ? s[t - off] : 0;
        __syncthreads();
        s[t] += y;
        __syncthreads();
    }
    if (i < n) outEx[i] = s[t] - v;
    if (t == 1023) part[blockIdx.x] = s[1023];
}

__global__ void k_scan_part(int* __restrict__ part, int nb, int* __restrict__ rowstart) {
    if (threadIdx.x == 0 && blockIdx.x == 0) {
        int acc = 0;
        for (int i = 0; i < nb; i++) { int v = part[i]; part[i] = acc; acc += v; }
        rowstart[NNODES] = NEDGES;
    }
}

__global__ void k_scan_add(int* __restrict__ rowstart, const int* __restrict__ part,
                           int* __restrict__ cursor, int n) {
    int i = blockIdx.x * 1024 + threadIdx.x;
    if (i < n) {
        int v = rowstart[i] + part[blockIdx.x];
        rowstart[i] = v;
        cursor[i] = v;
    }
}

__global__ void k_scatter(const int* __restrict__ dst, int* __restrict__ cursor,
                          int* __restrict__ elist, int n) {
    int e = blockIdx.x * blockDim.x + threadIdx.x;
    if (e < n) {
        int d = dst[e];
        int p = atomicAdd(&cursor[d], 1);
        elist[p] = e;
    }
}

// permute edge metadata into elist (dst-sorted) order; fold the
// batch/node_ids gather into a single attn index per edge.
__global__ void k_eperm(const int* __restrict__ elist, const int* __restrict__ srcArr,
                        const int* __restrict__ ridArr, const int* __restrict__ nodeIds,
                        const int* __restrict__ batchArr,
                        int* __restrict__ esrc, int* __restrict__ erid,
                        int* __restrict__ eaidx, int n) {
    int i = blockIdx.x * blockDim.x + threadIdx.x;
    if (i < n) {
        int e = elist[i];
        int s = srcArr[e];
        esrc[i] = s;
        erid[i] = ridArr[e];
        eaidx[i] = batchArr[s] * NVOC + nodeIds[s];
    }
}

__global__ void k_bscan(const int* __restrict__ bcnt, int* __restrict__ bstart) {
    if (threadIdx.x == 0 && blockIdx.x == 0) {
        int acc = 0;
        for (int b = 0; b < NBATCH; b++) { bstart[b] = acc; acc += bcnt[b]; }
        bstart[NBATCH] = acc;
    }
}

__global__ void k_wrel(const float* __restrict__ Erel, const float* __restrict__ wr_w,
                       const float* __restrict__ wr_b, float* __restrict__ wrel) {
    int w = (blockIdx.x * blockDim.x + threadIdx.x) >> 5;
    int lane = threadIdx.x & 31;
    if (w >= NL * NREL) return;
    int l = w / NREL, r = w % NREL;
    float acc = 0.f;
#pragma unroll
    for (int h = lane; h < NH; h += 32) acc += Erel[r * NH + h] * wr_w[l * NH + h];
#pragma unroll
    for (int o = 16; o; o >>= 1) acc += __shfl_down_sync(0xffffffffu, acc, o);
    if (lane == 0) wrel[w] = acc + wr_b[l];
}

__global__ void k_gather(const float* __restrict__ Enode, const int* __restrict__ node_ids,
                         float* __restrict__ x) {
    int t = blockIdx.x * blockDim.x + threadIdx.x;
    if (t >= NNODES * 32) return;
    int i = t >> 5, q = t & 31;
    int nid = node_ids[i];
    *(float4*)(x + (size_t)i * NH + q * 4) =
        *(const float4*)(Enode + (size_t)nid * NH + q * 4);
}

__global__ void k_beta(const float* __restrict__ vn, const float* __restrict__ beta_w,
                       const float* __restrict__ beta_b, float* __restrict__ betaOut) {
    int w = (blockIdx.x * blockDim.x + threadIdx.x) >> 5;
    int lane = threadIdx.x & 31;
    if (w >= NL * NBATCH * NV) return;
    int l = w / (NBATCH * NV);
    int rem = w % (NBATCH * NV);
    int b = rem / NV, v = rem % NV;
    const float* row = vn + ((size_t)b * NV + v) * NVOC;
    const float* bw = beta_w + l * NVOC;
    float acc = 0.f;
    for (int n = lane; n < NVOC; n += 32) acc += row[n] * bw[n];
#pragma unroll
    for (int o = 16; o; o >>= 1) acc += __shfl_down_sync(0xffffffffu, acc, o);
    if (lane == 0)
        betaOut[w] = tanhf(acc + beta_b[l]) * expf(0.03f * (float)(NV - v));
}

// single-layer attn (pre-offset pointers)
__global__ void k_attn(const float* __restrict__ Z, const float* __restrict__ betaL,
                       float* __restrict__ attnL) {
    int m = blockIdx.x * blockDim.x + threadIdx.x;
    int b = blockIdx.y;
    if (m >= NVOC) return;
    float z[NV];
    float mx = -1e30f;
#pragma unroll
    for (int v = 0; v < NV; v++) {
        z[v] = Z[((size_t)(b * NV + v)) * NVOC + m];
        mx = fmaxf(mx, z[v]);
    }
    float s = 0.f, num = 0.f;
#pragma unroll
    for (int v = 0; v < NV; v++) {
        float e = expf(z[v] - mx);
        s += e;
        num += e * betaL[b * NV + v];
    }
    attnL[(size_t)b * NVOC + m] = num / s;
}

// warp-per-node aggregate with permuted (sequential) edge metadata
__global__ void k_aggregate(const float* __restrict__ x, const float* __restrict__ Erel,
                            const float* __restrict__ attnL, const float* __restrict__ wrelL,
                            const int* __restrict__ esrc, const int* __restrict__ erid,
                            const int* __restrict__ eaidx, const int* __restrict__ rowstart,
                            float* __restrict__ agg) {
    int warp = (blockIdx.x * blockDim.x + threadIdx.x) >> 5;
    int lane = threadIdx.x & 31;
    if (warp >= NNODES) return;
    int s0 = rowstart[warp], s1 = rowstart[warp + 1];
    float4 acc = {0.f, 0.f, 0.f, 0.f};
    for (int idx = s0; idx < s1; idx++) {
        int s = esrc[idx];
        int r = erid[idx];
        float ea = attnL[eaidx[idx]];
        float w = wrelL[r];
        float4 xv = *(const float4*)(x + (size_t)s * NH + lane * 4);
        float4 ev = *(const float4*)(Erel + (size_t)r * NH + lane * 4);
        acc.x += fmaxf(fmaf(xv.x, ea, w * ev.x), 0.f);
        acc.y += fmaxf(fmaf(xv.y, ea, w * ev.y), 0.f);
        acc.z += fmaxf(fmaf(xv.z, ea, w * ev.z), 0.f);
        acc.w += fmaxf(fmaf(xv.w, ea, w * ev.w), 0.f);
    }
    *(float4*)(agg + (size_t)warp * NH + lane * 4) = acc;
}

__global__ void k_pool_partial(const float* __restrict__ x, const int* __restrict__ bstart,
                               float* __restrict__ xg) {
    int b = blockIdx.y, chunk = blockIdx.x, h = threadIdx.x;
    int s0 = bstart[b], s1 = bstart[b + 1];
    int len = s1 - s0;
    int r0 = s0 + (int)((long long)len * chunk / 8);
    int r1 = s0 + (int)((long long)len * (chunk + 1) / 8);
    float acc = 0.f;
    for (int i = r0; i < r1; i++) acc += x[(size_t)i * NH + h];
    atomicAdd(&xg[b * NH + h], acc);
}

__global__ void k_pool_finish(float* __restrict__ xg, const int* __restrict__ bcnt) {
    int b = blockIdx.x, h = threadIdx.x;
    float c = (float)bcnt[b];
    xg[b * NH + h] /= fmaxf(c, 1.f);
}

__global__ void k_ehrsum(const float* __restrict__ ehr, float* __restrict__ den) {
    int b = blockIdx.x, t = threadIdx.x;
    __shared__ float s[256];
    float acc = 0.f;
    for (int n = t; n < NVOC; n += 256) acc += ehr[(size_t)b * NVOC + n];
    s[t] = acc;
    __syncthreads();
    for (int o = 128; o; o >>= 1) {
        if (t < o) s[t] += s[t + o];
        __syncthreads();
    }
    if (t == 0) den[b] = s[0];
}

__global__ void k_xnode_partial(const float* __restrict__ ehr,
                                const float* __restrict__ node_emb,
                                float* __restrict__ xacc) {
    int b = blockIdx.y, slice = blockIdx.x, h = threadIdx.x;
    int n0 = slice * (NVOC / 16), n1 = n0 + (NVOC / 16);
    float acc = 0.f;
    for (int n = n0; n < n1; n++)
        acc += ehr[(size_t)b * NVOC + n] * node_emb[(size_t)n * NH + h];
    atomicAdd(&xacc[b * NH + h], acc);
}

__global__ void k_xnode_finish(const float* __restrict__ xacc, const float* __restrict__ den,
                               const float* __restrict__ lin_w, const float* __restrict__ lin_b,
                               float* __restrict__ xnode) {
    int b = blockIdx.x, h = threadIdx.x;
    __shared__ float t[NH];
    t[h] = xacc[b * NH + h] / den[b];
    __syncthreads();
    float s = 0.f;
#pragma unroll 8
    for (int hh = 0; hh < NH; hh++) s += t[hh] * lin_w[h * NH + hh];
    xnode[b * NH + h] = s + lin_b[h];
}

__global__ void k_final(const float* __restrict__ xg, const float* __restrict__ xn,
                        const float* __restrict__ mlp_w, const float* __restrict__ mlp_b,
                        float* __restrict__ out) {
    int b = blockIdx.x, t = threadIdx.x;
    __shared__ float s[2 * NH];
    s[t] = xg[b * NH + t];
    s[NH + t] = xn[b * NH + t];
    __syncthreads();
    if (t < NOUT) {
        float acc = mlp_b[t];
        const float* w = mlp_w + t * (2 * NH);
#pragma unroll 8
        for (int k = 0; k < 2 * NH; k++) acc += s[k] * w[k];
        out[b * NOUT + t] = acc;
    }
}

// ---------------- launch ----------------
extern "C" void kernel_launch(void* const* d_in, const int* in_sizes, int n_in,
                              void* d_out, int out_size) {
    const float* node_emb = (const float*)d_in[0];
    const float* rel_emb  = (const float*)d_in[1];
    const float* lin_w    = (const float*)d_in[2];
    const float* lin_b    = (const float*)d_in[3];
    const float* alpha_w  = (const float*)d_in[4];
    const float* alpha_b  = (const float*)d_in[5];
    const float* beta_w   = (const float*)d_in[6];
    const float* beta_b   = (const float*)d_in[7];
    const float* wr_w     = (const float*)d_in[8];
    const float* wr_b     = (const float*)d_in[9];
    const float* conv_w   = (const float*)d_in[10];
    const float* conv_b   = (const float*)d_in[11];
    const float* mlp_w    = (const float*)d_in[12];
    const float* mlp_b    = (const float*)d_in[13];
    const float* visit    = (const float*)d_in[14];
    const float* ehr      = (const float*)d_in[15];
    const int* node_ids   = (const int*)d_in[16];
    const int* rel_ids    = (const int*)d_in[17];
    const int* eidx       = (const int*)d_in[18];
    const int* batch      = (const int*)d_in[19];
    float* out = (float*)d_out;

    const int* srcArr = eidx;
    const int* dstArr = eidx + NEDGES;

    float *Zp, *Enodep, *Erelp, *wrelp, *attnp, *betap, *xp, *x2p, *aggp;
    float *xgp, *xaccp, *denp, *xnodep;
    int *degp, *rowstartp, *cursorp, *elistp, *esrcp, *eridp, *eaidxp;
    int *partp, *bcntp, *bstartp;
    cudaGetSymbolAddress((void**)&Zp, g_Z);
    cudaGetSymbolAddress((void**)&Enodep, g_Enode);
    cudaGetSymbolAddress((void**)&Erelp, g_Erel);
    cudaGetSymbolAddress((void**)&wrelp, g_wrel);
    cudaGetSymbolAddress((void**)&attnp, g_attn);
    cudaGetSymbolAddress((void**)&betap, g_beta);
    cudaGetSymbolAddress((void**)&xp, g_x);
    cudaGetSymbolAddress((void**)&x2p, g_x2);
    cudaGetSymbolAddress((void**)&aggp, g_agg);
    cudaGetSymbolAddress((void**)&xgp, g_xg);
    cudaGetSymbolAddress((void**)&xaccp, g_xacc);
    cudaGetSymbolAddress((void**)&denp, g_den);
    cudaGetSymbolAddress((void**)&xnodep, g_xnode);
    cudaGetSymbolAddress((void**)&degp, g_deg);
    cudaGetSymbolAddress((void**)&rowstartp, g_rowstart);
    cudaGetSymbolAddress((void**)&cursorp, g_cursor);
    cudaGetSymbolAddress((void**)&elistp, g_elist);
    cudaGetSymbolAddress((void**)&esrcp, g_esrc);
    cudaGetSymbolAddress((void**)&eridp, g_erid);
    cudaGetSymbolAddress((void**)&eaidxp, g_eaidx);
    cudaGetSymbolAddress((void**)&partp, g_part);
    cudaGetSymbolAddress((void**)&bcntp, g_bcnt);
    cudaGetSymbolAddress((void**)&bstartp, g_bstart);

    // One-time resource creation (host handles only; no device memory).
    static cudaStream_t sSide = nullptr;
    static cudaEvent_t evFork = nullptr, evJoin = nullptr;
    static cudaEvent_t evZ[NL] = {nullptr, nullptr, nullptr};
    if (sSide == nullptr) {
        cudaStreamCreateWithFlags(&sSide, cudaStreamNonBlocking);
        cudaEventCreateWithFlags(&evFork, cudaEventDisableTiming);
        cudaEventCreateWithFlags(&evJoin, cudaEventDisableTiming);
        for (int l = 0; l < NL; l++)
            cudaEventCreateWithFlags(&evZ[l], cudaEventDisableTiming);
    }

    const int SCAN_BLOCKS = (NNODES + 1023) / 1024;
    const size_t ZL = (size_t)NBATCH * NV * NVOC;

    // ---- fork ----
    cudaEventRecord(evFork, 0);
    cudaStreamWaitEvent(sSide, evFork, 0);

    // main stream: per-layer alpha GEMMs, each signals its event
    for (int l = 0; l < NL; l++) {
        alpha_gemm_tf32<<<dim3((NVOC + TBN - 1) / TBN, (NBATCH * NV) / TBM), 128>>>(
            visit, alpha_w + (size_t)l * NVOC * NVOC, alpha_b + (size_t)l * NVOC,
            Zp + l * ZL);
        cudaEventRecord(evZ[l], 0);
    }

    // side stream: alpha-independent pre-work
    gemm128_3xtf32<false, false><<<(NVOC + 127) / 128, 256, 0, sSide>>>(
        node_emb, nullptr, lin_w, lin_b, Enodep, NVOC);
    gemm128_3xtf32<false, false><<<(NREL + 127) / 128, 256, 0, sSide>>>(
        rel_emb, nullptr, lin_w, lin_b, Erelp, NREL);
    k_wrel<<<(NL * NREL * 32 + 255) / 256, 256, 0, sSide>>>(Erelp, wr_w, wr_b, wrelp);
    k_gather<<<(NNODES * 32 + 255) / 256, 256, 0, sSide>>>(Enodep, node_ids, xp);
    k_beta<<<(NL * NBATCH * NV * 32 + 255) / 256, 256, 0, sSide>>>(
        visit, beta_w, beta_b, betap);
    k_zero_int<<<(NNODES + 255) / 256, 256, 0, sSide>>>(degp, NNODES);
    k_zero_int<<<1, 64, 0, sSide>>>(bcntp, NBATCH);
    k_hist<<<(NEDGES + 255) / 256, 256, 0, sSide>>>(dstArr, degp, NEDGES);
    k_hist_batch<<<(NNODES + 255) / 256, 256, 0, sSide>>>(batch, bcntp);
    k_scan_block<<<SCAN_BLOCKS, 1024, 0, sSide>>>(degp, rowstartp, partp, NNODES);
    k_scan_part<<<1, 1, 0, sSide>>>(partp, SCAN_BLOCKS, rowstartp);
    k_scan_add<<<SCAN_BLOCKS, 1024, 0, sSide>>>(rowstartp, partp, cursorp, NNODES);
    k_scatter<<<(NEDGES + 255) / 256, 256, 0, sSide>>>(dstArr, cursorp, elistp, NEDGES);
    k_eperm<<<(NEDGES + 255) / 256, 256, 0, sSide>>>(
        elistp, srcArr, rel_ids, node_ids, batch, esrcp, eridp, eaidxp, NEDGES);
    k_bscan<<<1, 1, 0, sSide>>>(bcntp, bstartp);
    k_zero_float<<<(NBATCH * NH + 255) / 256, 256, 0, sSide>>>(xgp, NBATCH * NH);
    k_zero_float<<<(NBATCH * NH + 255) / 256, 256, 0, sSide>>>(xaccp, NBATCH * NH);
    k_ehrsum<<<NBATCH, 256, 0, sSide>>>(ehr, denp);
    k_xnode_partial<<<dim3(16, NBATCH), NH, 0, sSide>>>(ehr, node_emb, xaccp);
    k_xnode_finish<<<NBATCH, NH, 0, sSide>>>(xaccp, denp, lin_w, lin_b, xnodep);

    // side stream: per-layer pipeline (layer l waits only on Z_l)
    float* xcur = xp;
    float* xalt = x2p;
    for (int l = 0; l < NL; l++) {
        cudaStreamWaitEvent(sSide, evZ[l], 0);
        k_attn<<<dim3((NVOC + 255) / 256, NBATCH), 256, 0, sSide>>>(
            Zp + l * ZL, betap + l * NBATCH * NV, attnp + (size_t)l * NBATCH * NVOC);
        k_aggregate<<<(NNODES * 32 + 255) / 256, 256, 0, sSide>>>(
            xcur, Erelp, attnp + (size_t)l * NBATCH * NVOC, wrelp + l * NREL,
            esrcp, eridp, eaidxp, rowstartp, aggp);
        gemm128_3xtf32<true, true><<<(NNODES + 127) / 128, 256, 0, sSide>>>(
            aggp, xcur, conv_w + (size_t)l * NH * NH, conv_b + (size_t)l * NH,
            xalt, NNODES);
        float* tmp = xcur; xcur = xalt; xalt = tmp;
    }

    // side stream: pooling
    k_pool_partial<<<dim3(8, NBATCH), NH, 0, sSide>>>(xcur, bstartp, xgp);
    k_pool_finish<<<NBATCH, NH, 0, sSide>>>(xgp, bcntp);

    // ---- join ----
    cudaEventRecord(evJoin, sSide);
    cudaStreamWaitEvent(0, evJoin, 0);

    k_final<<<NBATCH, NH>>>(xgp, xnodep, mlp_w, mlp_b, out);
}

// round 14
// speedup vs baseline: 4.3667x; 1.0167x over previous
#include <cuda_runtime.h>
#include <cuda_fp16.h>
#include <math.h>
#include <stdint.h>

#define NNODES 50000
#define NEDGES 800000
#define NBATCH 32
#define NV 20
#define NVOC 4000
#define NREL 200
#define NH 128
#define NL 3
#define NOUT 100

// ---------------- device scratch ----------------
__device__ float g_Z[(size_t)NL * NBATCH * NV * NVOC];
__device__ float g_Enode[NVOC * NH];
__device__ float g_Erel[NREL * NH];
__device__ float g_wrel[NL * NREL];
__device__ float g_attn[(size_t)NL * NBATCH * NVOC];
__device__ float g_beta[NL * NBATCH * NV];
__device__ float g_x[(size_t)NNODES * NH];
__device__ float g_x2[(size_t)NNODES * NH];
__device__ __half g_xh[(size_t)NNODES * NH];
__device__ __half g_xh2[(size_t)NNODES * NH];
__device__ float g_agg[(size_t)NNODES * NH];
__device__ int   g_deg[NNODES];
__device__ int   g_rowstart[NNODES + 1];
__device__ int   g_cursor[NNODES];
__device__ int   g_elist[NEDGES];
__device__ int   g_esrc[NEDGES];
__device__ int   g_erid[NEDGES];
__device__ int   g_eaidx[NEDGES];
__device__ int   g_part[64];
__device__ int   g_bcnt[NBATCH];
__device__ int   g_bstart[NBATCH + 1];
__device__ float g_xg[NBATCH * NH];
__device__ float g_xacc[NBATCH * NH];
__device__ float g_den[NBATCH];
__device__ float g_xnode[NBATCH * NH];

// ---------------- helpers ----------------
__device__ __forceinline__ void cp_async16(void* smem_dst, const void* gsrc, int src_size) {
    uint32_t s = (uint32_t)__cvta_generic_to_shared(smem_dst);
    asm volatile("cp.async.ca.shared.global [%0], [%1], 16, %2;\n"
                 :: "r"(s), "l"(gsrc), "r"(src_size));
}
__device__ __forceinline__ void cp_commit() { asm volatile("cp.async.commit_group;\n"); }
template <int W> __device__ __forceinline__ void cp_wait() {
    asm volatile("cp.async.wait_group %0;\n" :: "n"(W));
}
__device__ __forceinline__ uint32_t smem_u32(const void* p) {
    return (uint32_t)__cvta_generic_to_shared(p);
}
__device__ __forceinline__ void ldsm_x4(uint32_t& r0, uint32_t& r1, uint32_t& r2,
                                        uint32_t& r3, uint32_t addr) {
    asm volatile("ldmatrix.sync.aligned.m8n8.x4.shared.b16 {%0,%1,%2,%3}, [%4];"
                 : "=r"(r0), "=r"(r1), "=r"(r2), "=r"(r3) : "r"(addr));
}
__device__ __forceinline__ void split_tf32(float v, uint32_t& hi, uint32_t& lo) {
    uint32_t h;
    asm("cvt.rna.tf32.f32 %0, %1;" : "=r"(h) : "f"(v));
    float l = v - __uint_as_float(h);
    uint32_t lt;
    asm("cvt.rna.tf32.f32 %0, %1;" : "=r"(lt) : "f"(l));
    hi = h; lo = lt;
}

// ---------------- tf32 tensor-core GEMM for alpha logits ----------------
// One layer per launch. 4 warps, 64x64 warp tiles; ldmatrix; TPAD=20; 2-stage.
#define TBM 128
#define TBN 128
#define TBK 16
#define TPAD 20

__global__ __launch_bounds__(128, 2) void alpha_gemm_tf32(
    const float* __restrict__ A,
    const float* __restrict__ B,
    const float* __restrict__ bias,
    float* __restrict__ C)
{
    const int M = NBATCH * NV, N = NVOC, K = NVOC;
    const int KITERS = K / TBK;

    __shared__ float As[2][TBM * TPAD];
    __shared__ float Bs[2][TBN * TPAD];

    int tid = threadIdx.x;
    int m0 = blockIdx.y * TBM;
    int n0 = blockIdx.x * TBN;
    int warp = tid >> 5, lane = tid & 31;
    int wm = (warp & 1) * 64;
    int wn = (warp >> 1) * 64;
    int lq = lane >> 2;
    int lr = lane & 3;
    int tile = lane >> 3, trow = lane & 7;

    float acc[4][8][4];
#pragma unroll
    for (int i = 0; i < 4; i++)
#pragma unroll
        for (int j = 0; j < 8; j++)
#pragma unroll
            for (int r = 0; r < 4; r++) acc[i][j][r] = 0.f;

#define ISSUE_TILES(stage, k0)                                                        \
    do {                                                                              \
        _Pragma("unroll")                                                             \
        for (int t = tid; t < 512; t += 128) {                                        \
            int row = t >> 2, ch = (t & 3) * 4;                                       \
            cp_async16(&As[stage][row * TPAD + ch],                                   \
                       A + (size_t)(m0 + row) * K + (k0) + ch, 16);                   \
        }                                                                             \
        _Pragma("unroll")                                                             \
        for (int t = tid; t < 512; t += 128) {                                        \
            int row = t >> 2, ch = (t & 3) * 4;                                       \
            int gn = n0 + row;                                                        \
            int ok = gn < N;                                                          \
            cp_async16(&Bs[stage][row * TPAD + ch],                                   \
                       B + (size_t)(ok ? gn : 0) * K + (k0) + ch, ok ? 16 : 0);       \
        }                                                                             \
    } while (0)

    ISSUE_TILES(0, 0);
    cp_commit();

    int aRow = wm + ((tile & 1) << 3) + trow;
    int aKof = (tile >> 1) << 2;
    int bCol = wn + ((tile >> 1) << 3) + trow;
    int bKof = (tile & 1) << 2;

    for (int kt = 0; kt < KITERS; kt++) {
        int st = kt & 1;
        if (kt + 1 < KITERS) {
            ISSUE_TILES(st ^ 1, (kt + 1) * TBK);
            cp_commit();
            cp_wait<1>();
        } else {
            cp_wait<0>();
        }
        __syncthreads();

        const float* as = As[st];
        const float* bs = Bs[st];
        uint32_t abase = smem_u32(&as[aRow * TPAD + aKof]);
        uint32_t bbase = smem_u32(&bs[bCol * TPAD + bKof]);

#pragma unroll
        for (int kk = 0; kk < TBK; kk += 8) {
            uint32_t af[4][4];
            uint32_t bf[8][2];
#pragma unroll
            for (int mi = 0; mi < 4; mi++)
                ldsm_x4(af[mi][0], af[mi][1], af[mi][2], af[mi][3],
                        abase + (kk + mi * 16 * TPAD) * 4);
#pragma unroll
            for (int np = 0; np < 4; np++)
                ldsm_x4(bf[2 * np][0], bf[2 * np][1], bf[2 * np + 1][0], bf[2 * np + 1][1],
                        bbase + (kk + np * 16 * TPAD) * 4);
#pragma unroll
            for (int mi = 0; mi < 4; mi++)
#pragma unroll
                for (int ni = 0; ni < 8; ni++) {
                    asm volatile(
                        "mma.sync.aligned.m16n8k8.row.col.f32.tf32.tf32.f32 "
                        "{%0,%1,%2,%3}, {%4,%5,%6,%7}, {%8,%9}, {%0,%1,%2,%3};\n"
                        : "+f"(acc[mi][ni][0]), "+f"(acc[mi][ni][1]),
                          "+f"(acc[mi][ni][2]), "+f"(acc[mi][ni][3])
                        : "r"(af[mi][0]), "r"(af[mi][1]), "r"(af[mi][2]), "r"(af[mi][3]),
                          "r"(bf[ni][0]), "r"(bf[ni][1]));
                }
        }
        __syncthreads();
    }

#pragma unroll
    for (int mi = 0; mi < 4; mi++) {
#pragma unroll
        for (int ni = 0; ni < 8; ni++) {
            int r = m0 + wm + mi * 16 + lq;
            int c = n0 + wn + ni * 8 + lr * 2;
            if (c < N) {
                float2 bb = *(const float2*)(bias + c);
                float2 o0, o1;
                o0.x = acc[mi][ni][0] + bb.x; o0.y = acc[mi][ni][1] + bb.y;
                o1.x = acc[mi][ni][2] + bb.x; o1.y = acc[mi][ni][3] + bb.y;
                *(float2*)(C + (size_t)r * N + c) = o0;
                *(float2*)(C + (size_t)(r + 8) * N + c) = o1;
            }
        }
    }
#undef ISSUE_TILES
}

// ---------------- 3xTF32 compensated mma GEMM: K=128, N=128 -----------------
// HOUT: additionally emit fp16 copy of C into Ch.
#define CPW 36

template <bool RELU, bool ADD2, bool HOUT>
__global__ __launch_bounds__(256) void gemm128_3xtf32(
    const float* __restrict__ A, const float* __restrict__ A2,
    const float* __restrict__ B, const float* __restrict__ bias,
    float* __restrict__ C, __half* __restrict__ Ch, int M)
{
    __shared__ float As[128 * CPW];
    __shared__ float Bs[128 * CPW];

    int tid = threadIdx.x;
    int m0 = blockIdx.x * 128;
    int warp = tid >> 5, lane = tid & 31;
    int wm = (warp & 1) * 64;
    int wn = (warp >> 1) * 32;
    int lq = lane >> 2;
    int lr = lane & 3;

    float acc[4][4][4];
#pragma unroll
    for (int i = 0; i < 4; i++)
#pragma unroll
        for (int j = 0; j < 4; j++)
#pragma unroll
            for (int r = 0; r < 4; r++) acc[i][j][r] = 0.f;

    for (int k0 = 0; k0 < NH; k0 += 32) {
        __syncthreads();
#pragma unroll
        for (int t = tid; t < 1024; t += 256) {
            int row = t >> 3, seg = (t & 7) * 4;
            int gm = m0 + row;
            float4 v = {0, 0, 0, 0};
            if (gm < M) {
                v = *(const float4*)(A + (size_t)gm * NH + k0 + seg);
                if (ADD2) {
                    float4 w = *(const float4*)(A2 + (size_t)gm * NH + k0 + seg);
                    v.x += w.x; v.y += w.y; v.z += w.z; v.w += w.w;
                }
            }
            *(float4*)&As[row * CPW + seg] = v;
            *(float4*)&Bs[row * CPW + seg] = *(const float4*)(B + (size_t)row * NH + k0 + seg);
        }
        __syncthreads();

#pragma unroll
        for (int kk = 0; kk < 32; kk += 8) {
            uint32_t ah[4][4], al[4][4];
            uint32_t bh[4][2], bl[4][2];
#pragma unroll
            for (int mi = 0; mi < 4; mi++) {
                int base = (wm + mi * 16 + lq) * CPW + kk + lr;
                split_tf32(As[base],               ah[mi][0], al[mi][0]);
                split_tf32(As[base + 8 * CPW],     ah[mi][1], al[mi][1]);
                split_tf32(As[base + 4],           ah[mi][2], al[mi][2]);
                split_tf32(As[base + 8 * CPW + 4], ah[mi][3], al[mi][3]);
            }
#pragma unroll
            for (int ni = 0; ni < 4; ni++) {
                int base = (wn + ni * 8 + lq) * CPW + kk + lr;
                split_tf32(Bs[base],     bh[ni][0], bl[ni][0]);
                split_tf32(Bs[base + 4], bh[ni][1], bl[ni][1]);
            }
#define MMA_TF32(Aop, Bop)                                                            \
    asm volatile(                                                                     \
        "mma.sync.aligned.m16n8k8.row.col.f32.tf32.tf32.f32 "                         \
        "{%0,%1,%2,%3}, {%4,%5,%6,%7}, {%8,%9}, {%0,%1,%2,%3};\n"                     \
        : "+f"(acc[mi][ni][0]), "+f"(acc[mi][ni][1]),                                 \
          "+f"(acc[mi][ni][2]), "+f"(acc[mi][ni][3])                                  \
        : "r"(Aop[mi][0]), "r"(Aop[mi][1]), "r"(Aop[mi][2]), "r"(Aop[mi][3]),         \
          "r"(Bop[ni][0]), "r"(Bop[ni][1]))
#pragma unroll
            for (int mi = 0; mi < 4; mi++)
#pragma unroll
                for (int ni = 0; ni < 4; ni++) {
                    MMA_TF32(ah, bh);
                    MMA_TF32(ah, bl);
                    MMA_TF32(al, bh);
                }
#undef MMA_TF32
        }
    }

#pragma unroll
    for (int mi = 0; mi < 4; mi++) {
#pragma unroll
        for (int ni = 0; ni < 4; ni++) {
            int r = m0 + wm + mi * 16 + lq;
            int c = wn + ni * 8 + lr * 2;
            float2 bb = *(const float2*)(bias + c);
            float2 o0, o1;
            o0.x = acc[mi][ni][0] + bb.x; o0.y = acc[mi][ni][1] + bb.y;
            o1.x = acc[mi][ni][2] + bb.x; o1.y = acc[mi][ni][3] + bb.y;
            if (RELU) {
                o0.x = fmaxf(o0.x, 0.f); o0.y = fmaxf(o0.y, 0.f);
                o1.x = fmaxf(o1.x, 0.f); o1.y = fmaxf(o1.y, 0.f);
            }
            if (r < M) {
                *(float2*)(C + (size_t)r * NH + c) = o0;
                if (HOUT) {
                    __half2 h = __floats2half2_rn(o0.x, o0.y);
                    *(__half2*)(Ch + (size_t)r * NH + c) = h;
                }
            }
            if (r + 8 < M) {
                *(float2*)(C + (size_t)(r + 8) * NH + c) = o1;
                if (HOUT) {
                    __half2 h = __floats2half2_rn(o1.x, o1.y);
                    *(__half2*)(Ch + (size_t)(r + 8) * NH + c) = h;
                }
            }
        }
    }
}

// ---------------- small kernels ----------------
__global__ void k_zero_int(int* __restrict__ p, int n) {
    int i = blockIdx.x * blockDim.x + threadIdx.x;
    if (i < n) p[i] = 0;
}
__global__ void k_zero_float(float* __restrict__ p, int n) {
    int i = blockIdx.x * blockDim.x + threadIdx.x;
    if (i < n) p[i] = 0.f;
}

__global__ void k_hist(const int* __restrict__ keys, int* __restrict__ cnt, int n) {
    int i = blockIdx.x * blockDim.x + threadIdx.x;
    if (i < n) atomicAdd(&cnt[keys[i]], 1);
}

__global__ void k_hist_batch(const int* __restrict__ batch, int* __restrict__ bcnt) {
    __shared__ int h[NBATCH];
    if (threadIdx.x < NBATCH) h[threadIdx.x] = 0;
    __syncthreads();
    int i = blockIdx.x * blockDim.x + threadIdx.x;
    if (i < NNODES) atomicAdd(&h[batch[i]], 1);
    __syncthreads();
    if (threadIdx.x < NBATCH) atomicAdd(&bcnt[threadIdx.x], h[threadIdx.x]);
}

__global__ void k_scan_block(const int* __restrict__ in, int* __restrict__ outEx,
                             int* __restrict__ part, int n) {
    __shared__ int s[1024];
    int t = threadIdx.x;
    int i = blockIdx.x * 1024 + t;
    int v = (i < n) ? in[i] : 0;
    s[t] = v;
    __syncthreads();
    for (int off = 1; off < 1024; off <<= 1) {
        int y = (t >= off) ? s[t - off] : 0;
        __syncthreads();
        s[t] += y;
        __syncthreads();
    }
    if (i < n) outEx[i] = s[t] - v;
    if (t == 1023) part[blockIdx.x] = s[1023];
}

__global__ void k_scan_part(int* __restrict__ part, int nb, int* __restrict__ rowstart) {
    if (threadIdx.x == 0 && blockIdx.x == 0) {
        int acc = 0;
        for (int i = 0; i < nb; i++) { int v = part[i]; part[i] = acc; acc += v; }
        rowstart[NNODES] = NEDGES;
    }
}

__global__ void k_scan_add(int* __restrict__ rowstart, const int* __restrict__ part,
                           int* __restrict__ cursor, int n) {
    int i = blockIdx.x * 1024 + threadIdx.x;
    if (i < n) {
        int v = rowstart[i] + part[blockIdx.x];
        rowstart[i] = v;
        cursor[i] = v;
    }
}

__global__ void k_scatter(const int* __restrict__ dst, int* __restrict__ cursor,
                          int* __restrict__ elist, int n) {
    int e = blockIdx.x * blockDim.x + threadIdx.x;
    if (e < n) {
        int d = dst[e];
        int p = atomicAdd(&cursor[d], 1);
        elist[p] = e;
    }
}

__global__ void k_eperm(const int* __restrict__ elist, const int* __restrict__ srcArr,
                        const int* __restrict__ ridArr, const int* __restrict__ nodeIds,
                        const int* __restrict__ batchArr,
                        int* __restrict__ esrc, int* __restrict__ erid,
                        int* __restrict__ eaidx, int n) {
    int i = blockIdx.x * blockDim.x + threadIdx.x;
    if (i < n) {
        int e = elist[i];
        int s = srcArr[e];
        esrc[i] = s;
        erid[i] = ridArr[e];
        eaidx[i] = batchArr[s] * NVOC + nodeIds[s];
    }
}

__global__ void k_bscan(const int* __restrict__ bcnt, int* __restrict__ bstart) {
    if (threadIdx.x == 0 && blockIdx.x == 0) {
        int acc = 0;
        for (int b = 0; b < NBATCH; b++) { bstart[b] = acc; acc += bcnt[b]; }
        bstart[NBATCH] = acc;
    }
}

__global__ void k_wrel(const float* __restrict__ Erel, const float* __restrict__ wr_w,
                       const float* __restrict__ wr_b, float* __restrict__ wrel) {
    int w = (blockIdx.x * blockDim.x + threadIdx.x) >> 5;
    int lane = threadIdx.x & 31;
    if (w >= NL * NREL) return;
    int l = w / NREL, r = w % NREL;
    float acc = 0.f;
#pragma unroll
    for (int h = lane; h < NH; h += 32) acc += Erel[r * NH + h] * wr_w[l * NH + h];
#pragma unroll
    for (int o = 16; o; o >>= 1) acc += __shfl_down_sync(0xffffffffu, acc, o);
    if (lane == 0) wrel[w] = acc + wr_b[l];
}

__global__ void k_gather(const float* __restrict__ Enode, const int* __restrict__ node_ids,
                         float* __restrict__ x, __half* __restrict__ xh) {
    int t = blockIdx.x * blockDim.x + threadIdx.x;
    if (t >= NNODES * 32) return;
    int i = t >> 5, q = t & 31;
    int nid = node_ids[i];
    float4 v = *(const float4*)(Enode + (size_t)nid * NH + q * 4);
    *(float4*)(x + (size_t)i * NH + q * 4) = v;
    __half2 h0 = __floats2half2_rn(v.x, v.y);
    __half2 h1 = __floats2half2_rn(v.z, v.w);
    uint2 raw;
    raw.x = *(uint32_t*)&h0; raw.y = *(uint32_t*)&h1;
    *(uint2*)(xh + (size_t)i * NH + q * 4) = raw;
}

__global__ void k_beta(const float* __restrict__ vn, const float* __restrict__ beta_w,
                       const float* __restrict__ beta_b, float* __restrict__ betaOut) {
    int w = (blockIdx.x * blockDim.x + threadIdx.x) >> 5;
    int lane = threadIdx.x & 31;
    if (w >= NL * NBATCH * NV) return;
    int l = w / (NBATCH * NV);
    int rem = w % (NBATCH * NV);
    int b = rem / NV, v = rem % NV;
    const float* row = vn + ((size_t)b * NV + v) * NVOC;
    const float* bw = beta_w + l * NVOC;
    float acc = 0.f;
    for (int n = lane; n < NVOC; n += 32) acc += row[n] * bw[n];
#pragma unroll
    for (int o = 16; o; o >>= 1) acc += __shfl_down_sync(0xffffffffu, acc, o);
    if (lane == 0)
        betaOut[w] = tanhf(acc + beta_b[l]) * expf(0.03f * (float)(NV - v));
}

__global__ void k_attn(const float* __restrict__ Z, const float* __restrict__ betaL,
                       float* __restrict__ attnL) {
    int m = blockIdx.x * blockDim.x + threadIdx.x;
    int b = blockIdx.y;
    if (m >= NVOC) return;
    float z[NV];
    float mx = -1e30f;
#pragma unroll
    for (int v = 0; v < NV; v++) {
        z[v] = Z[((size_t)(b * NV + v)) * NVOC + m];
        mx = fmaxf(mx, z[v]);
    }
    float s = 0.f, num = 0.f;
#pragma unroll
    for (int v = 0; v < NV; v++) {
        float e = expf(z[v] - mx);
        s += e;
        num += e * betaL[b * NV + v];
    }
    attnL[(size_t)b * NVOC + m] = num / s;
}

// warp-per-node aggregate; x gathered in fp16 (halved L2 traffic), fp32 accum
__global__ void k_aggregate(const __half* __restrict__ xh, const float* __restrict__ Erel,
                            const float* __restrict__ attnL, const float* __restrict__ wrelL,
                            const int* __restrict__ esrc, const int* __restrict__ erid,
                            const int* __restrict__ eaidx, const int* __restrict__ rowstart,
                            float* __restrict__ agg) {
    int warp = (blockIdx.x * blockDim.x + threadIdx.x) >> 5;
    int lane = threadIdx.x & 31;
    if (warp >= NNODES) return;
    int s0 = rowstart[warp], s1 = rowstart[warp + 1];
    float4 acc = {0.f, 0.f, 0.f, 0.f};
    for (int idx = s0; idx < s1; idx++) {
        int s = esrc[idx];
        int r = erid[idx];
        float ea = attnL[eaidx[idx]];
        float w = wrelL[r];
        uint2 raw = *(const uint2*)(xh + (size_t)s * NH + lane * 4);
        __half2 h0 = *(__half2*)&raw.x;
        __half2 h1 = *(__half2*)&raw.y;
        float2 f0 = __half22float2(h0);
        float2 f1 = __half22float2(h1);
        float4 ev = *(const float4*)(Erel + (size_t)r * NH + lane * 4);
        acc.x += fmaxf(fmaf(f0.x, ea, w * ev.x), 0.f);
        acc.y += fmaxf(fmaf(f0.y, ea, w * ev.y), 0.f);
        acc.z += fmaxf(fmaf(f1.x, ea, w * ev.z), 0.f);
        acc.w += fmaxf(fmaf(f1.y, ea, w * ev.w), 0.f);
    }
    *(float4*)(agg + (size_t)warp * NH + lane * 4) = acc;
}

__global__ void k_pool_partial(const float* __restrict__ x, const int* __restrict__ bstart,
                               float* __restrict__ xg) {
    int b = blockIdx.y, chunk = blockIdx.x, h = threadIdx.x;
    int s0 = bstart[b], s1 = bstart[b + 1];
    int len = s1 - s0;
    int r0 = s0 + (int)((long long)len * chunk / 8);
    int r1 = s0 + (int)((long long)len * (chunk + 1) / 8);
    float acc = 0.f;
    for (int i = r0; i < r1; i++) acc += x[(size_t)i * NH + h];
    atomicAdd(&xg[b * NH + h], acc);
}

__global__ void k_pool_finish(float* __restrict__ xg, const int* __restrict__ bcnt) {
    int b = blockIdx.x, h = threadIdx.x;
    float c = (float)bcnt[b];
    xg[b * NH + h] /= fmaxf(c, 1.f);
}

__global__ void k_ehrsum(const float* __restrict__ ehr, float* __restrict__ den) {
    int b = blockIdx.x, t = threadIdx.x;
    __shared__ float s[256];
    float acc = 0.f;
    for (int n = t; n < NVOC; n += 256) acc += ehr[(size_t)b * NVOC + n];
    s[t] = acc;
    __syncthreads();
    for (int o = 128; o; o >>= 1) {
        if (t < o) s[t] += s[t + o];
        __syncthreads();
    }
    if (t == 0) den[b] = s[0];
}

__global__ void k_xnode_partial(const float* __restrict__ ehr,
                                const float* __restrict__ node_emb,
                                float* __restrict__ xacc) {
    int b = blockIdx.y, slice = blockIdx.x, h = threadIdx.x;
    int n0 = slice * (NVOC / 16), n1 = n0 + (NVOC / 16);
    float acc = 0.f;
    for (int n = n0; n < n1; n++)
        acc += ehr[(size_t)b * NVOC + n] * node_emb[(size_t)n * NH + h];
    atomicAdd(&xacc[b * NH + h], acc);
}

__global__ void k_xnode_finish(const float* __restrict__ xacc, const float* __restrict__ den,
                               const float* __restrict__ lin_w, const float* __restrict__ lin_b,
                               float* __restrict__ xnode) {
    int b = blockIdx.x, h = threadIdx.x;
    __shared__ float t[NH];
    t[h] = xacc[b * NH + h] / den[b];
    __syncthreads();
    float s = 0.f;
#pragma unroll 8
    for (int hh = 0; hh < NH; hh++) s += t[hh] * lin_w[h * NH + hh];
    xnode[b * NH + h] = s + lin_b[h];
}

__global__ void k_final(const float* __restrict__ xg, const float* __restrict__ xn,
                        const float* __restrict__ mlp_w, const float* __restrict__ mlp_b,
                        float* __restrict__ out) {
    int b = blockIdx.x, t = threadIdx.x;
    __shared__ float s[2 * NH];
    s[t] = xg[b * NH + t];
    s[NH + t] = xn[b * NH + t];
    __syncthreads();
    if (t < NOUT) {
        float acc = mlp_b[t];
        const float* w = mlp_w + t * (2 * NH);
#pragma unroll 8
        for (int k = 0; k < 2 * NH; k++) acc += s[k] * w[k];
        out[b * NOUT + t] = acc;
    }
}

// ---------------- launch ----------------
extern "C" void kernel_launch(void* const* d_in, const int* in_sizes, int n_in,
                              void* d_out, int out_size) {
    const float* node_emb = (const float*)d_in[0];
    const float* rel_emb  = (const float*)d_in[1];
    const float* lin_w    = (const float*)d_in[2];
    const float* lin_b    = (const float*)d_in[3];
    const float* alpha_w  = (const float*)d_in[4];
    const float* alpha_b  = (const float*)d_in[5];
    const float* beta_w   = (const float*)d_in[6];
    const float* beta_b   = (const float*)d_in[7];
    const float* wr_w     = (const float*)d_in[8];
    const float* wr_b     = (const float*)d_in[9];
    const float* conv_w   = (const float*)d_in[10];
    const float* conv_b   = (const float*)d_in[11];
    const float* mlp_w    = (const float*)d_in[12];
    const float* mlp_b    = (const float*)d_in[13];
    const float* visit    = (const float*)d_in[14];
    const float* ehr      = (const float*)d_in[15];
    const int* node_ids   = (const int*)d_in[16];
    const int* rel_ids    = (const int*)d_in[17];
    const int* eidx       = (const int*)d_in[18];
    const int* batch      = (const int*)d_in[19];
    float* out = (float*)d_out;

    const int* srcArr = eidx;
    const int* dstArr = eidx + NEDGES;

    float *Zp, *Enodep, *Erelp, *wrelp, *attnp, *betap, *xp, *x2p, *aggp;
    float *xgp, *xaccp, *denp, *xnodep;
    __half *xhp, *xh2p;
    int *degp, *rowstartp, *cursorp, *elistp, *esrcp, *eridp, *eaidxp;
    int *partp, *bcntp, *bstartp;
    cudaGetSymbolAddress((void**)&Zp, g_Z);
    cudaGetSymbolAddress((void**)&Enodep, g_Enode);
    cudaGetSymbolAddress((void**)&Erelp, g_Erel);
    cudaGetSymbolAddress((void**)&wrelp, g_wrel);
    cudaGetSymbolAddress((void**)&attnp, g_attn);
    cudaGetSymbolAddress((void**)&betap, g_beta);
    cudaGetSymbolAddress((void**)&xp, g_x);
    cudaGetSymbolAddress((void**)&x2p, g_x2);
    cudaGetSymbolAddress((void**)&xhp, g_xh);
    cudaGetSymbolAddress((void**)&xh2p, g_xh2);
    cudaGetSymbolAddress((void**)&aggp, g_agg);
    cudaGetSymbolAddress((void**)&xgp, g_xg);
    cudaGetSymbolAddress((void**)&xaccp, g_xacc);
    cudaGetSymbolAddress((void**)&denp, g_den);
    cudaGetSymbolAddress((void**)&xnodep, g_xnode);
    cudaGetSymbolAddress((void**)&degp, g_deg);
    cudaGetSymbolAddress((void**)&rowstartp, g_rowstart);
    cudaGetSymbolAddress((void**)&cursorp, g_cursor);
    cudaGetSymbolAddress((void**)&elistp, g_elist);
    cudaGetSymbolAddress((void**)&esrcp, g_esrc);
    cudaGetSymbolAddress((void**)&eridp, g_erid);
    cudaGetSymbolAddress((void**)&eaidxp, g_eaidx);
    cudaGetSymbolAddress((void**)&partp, g_part);
    cudaGetSymbolAddress((void**)&bcntp, g_bcnt);
    cudaGetSymbolAddress((void**)&bstartp, g_bstart);

    // One-time resource creation (host handles only; no device memory).
    static cudaStream_t sMain = nullptr, sSide = nullptr;
    static cudaEvent_t evFork = nullptr, evJoin = nullptr;
    static cudaEvent_t evZ[NL] = {nullptr, nullptr, nullptr};
    if (sMain == nullptr) {
        int prLo, prHi;
        cudaDeviceGetStreamPriorityRange(&prLo, &prHi);   // prHi = highest prio
        cudaStreamCreateWithPriority(&sMain, cudaStreamNonBlocking, prHi);
        cudaStreamCreateWithPriority(&sSide, cudaStreamNonBlocking, prLo);
        cudaEventCreateWithFlags(&evFork, cudaEventDisableTiming);
        cudaEventCreateWithFlags(&evJoin, cudaEventDisableTiming);
        for (int l = 0; l < NL; l++)
            cudaEventCreateWithFlags(&evZ[l], cudaEventDisableTiming);
    }

    const int SCAN_BLOCKS = (NNODES + 1023) / 1024;
    const size_t ZL = (size_t)NBATCH * NV * NVOC;

    // ---- fork ----
    cudaEventRecord(evFork, 0);
    cudaStreamWaitEvent(sMain, evFork, 0);
    cudaStreamWaitEvent(sSide, evFork, 0);

    // sMain (high prio): per-layer alpha GEMMs, each signals its event
    for (int l = 0; l < NL; l++) {
        alpha_gemm_tf32<<<dim3((NVOC + TBN - 1) / TBN, (NBATCH * NV) / TBM), 128, 0,
                          sMain>>>(
            visit, alpha_w + (size_t)l * NVOC * NVOC, alpha_b + (size_t)l * NVOC,
            Zp + l * ZL);
        cudaEventRecord(evZ[l], sMain);
    }

    // sSide (low prio): alpha-independent pre-work
    gemm128_3xtf32<false, false, false><<<(NVOC + 127) / 128, 256, 0, sSide>>>(
        node_emb, nullptr, lin_w, lin_b, Enodep, nullptr, NVOC);
    gemm128_3xtf32<false, false, false><<<(NREL + 127) / 128, 256, 0, sSide>>>(
        rel_emb, nullptr, lin_w, lin_b, Erelp, nullptr, NREL);
    k_wrel<<<(NL * NREL * 32 + 255) / 256, 256, 0, sSide>>>(Erelp, wr_w, wr_b, wrelp);
    k_gather<<<(NNODES * 32 + 255) / 256, 256, 0, sSide>>>(Enodep, node_ids, xp, xhp);
    k_beta<<<(NL * NBATCH * NV * 32 + 255) / 256, 256, 0, sSide>>>(
        visit, beta_w, beta_b, betap);
    k_zero_int<<<(NNODES + 255) / 256, 256, 0, sSide>>>(degp, NNODES);
    k_zero_int<<<1, 64, 0, sSide>>>(bcntp, NBATCH);
    k_hist<<<(NEDGES + 255) / 256, 256, 0, sSide>>>(dstArr, degp, NEDGES);
    k_hist_batch<<<(NNODES + 255) / 256, 256, 0, sSide>>>(batch, bcntp);
    k_scan_block<<<SCAN_BLOCKS, 1024, 0, sSide>>>(degp, rowstartp, partp, NNODES);
    k_scan_part<<<1, 1, 0, sSide>>>(partp, SCAN_BLOCKS, rowstartp);
    k_scan_add<<<SCAN_BLOCKS, 1024, 0, sSide>>>(rowstartp, partp, cursorp, NNODES);
    k_scatter<<<(NEDGES + 255) / 256, 256, 0, sSide>>>(dstArr, cursorp, elistp, NEDGES);
    k_eperm<<<(NEDGES + 255) / 256, 256, 0, sSide>>>(
        elistp, srcArr, rel_ids, node_ids, batch, esrcp, eridp, eaidxp, NEDGES);
    k_bscan<<<1, 1, 0, sSide>>>(bcntp, bstartp);
    k_zero_float<<<(NBATCH * NH + 255) / 256, 256, 0, sSide>>>(xgp, NBATCH * NH);
    k_zero_float<<<(NBATCH * NH + 255) / 256, 256, 0, sSide>>>(xaccp, NBATCH * NH);
    k_ehrsum<<<NBATCH, 256, 0, sSide>>>(ehr, denp);
    k_xnode_partial<<<dim3(16, NBATCH), NH, 0, sSide>>>(ehr, node_emb, xaccp);
    k_xnode_finish<<<NBATCH, NH, 0, sSide>>>(xaccp, denp, lin_w, lin_b, xnodep);

    // sSide: per-layer pipeline (layer l waits only on Z_l)
    float* xcur = xp;
    float* xalt = x2p;
    __half* xhcur = xhp;
    __half* xhalt = xh2p;
    for (int l = 0; l < NL; l++) {
        cudaStreamWaitEvent(sSide, evZ[l], 0);
        k_attn<<<dim3((NVOC + 255) / 256, NBATCH), 256, 0, sSide>>>(
            Zp + l * ZL, betap + l * NBATCH * NV, attnp + (size_t)l * NBATCH * NVOC);
        k_aggregate<<<(NNODES * 32 + 255) / 256, 256, 0, sSide>>>(
            xhcur, Erelp, attnp + (size_t)l * NBATCH * NVOC, wrelp + l * NREL,
            esrcp, eridp, eaidxp, rowstartp, aggp);
        gemm128_3xtf32<true, true, true><<<(NNODES + 127) / 128, 256, 0, sSide>>>(
            aggp, xcur, conv_w + (size_t)l * NH * NH, conv_b + (size_t)l * NH,
            xalt, xhalt, NNODES);
        float* tf = xcur; xcur = xalt; xalt = tf;
        __half* th = xhcur; xhcur = xhalt; xhalt = th;
    }

    // sSide: pooling
    k_pool_partial<<<dim3(8, NBATCH), NH, 0, sSide>>>(xcur, bstartp, xgp);
    k_pool_finish<<<NBATCH, NH, 0, sSide>>>(xgp, bcntp);

    // ---- join ----
    cudaEventRecord(evJoin, sSide);
    cudaStreamWaitEvent(0, evJoin, 0);

    k_final<<<NBATCH, NH>>>(xgp, xnodep, mlp_w, mlp_b, out);
}

// round 15
// speedup vs baseline: 5.0191x; 1.1494x over previous
#include <cuda_runtime.h>
#include <cuda_fp16.h>
#include <math.h>
#include <stdint.h>

#define NNODES 50000
#define NEDGES 800000
#define NBATCH 32
#define NV 20
#define NVOC 4000
#define NREL 200
#define NH 128
#define NL 3
#define NOUT 100

// ---------------- device scratch ----------------
__device__ float g_Z[(size_t)NL * NBATCH * NV * NVOC];
__device__ __half g_vh[(size_t)NBATCH * NV * NVOC];          // fp16 visit
__device__ __half g_wh[(size_t)NL * NVOC * NVOC];            // fp16 alpha_w
__device__ float g_Enode[NVOC * NH];
__device__ float g_Erel[NREL * NH];
__device__ float g_wrel[NL * NREL];
__device__ float g_attn[(size_t)NL * NBATCH * NVOC];
__device__ float g_beta[NL * NBATCH * NV];
__device__ float g_x[(size_t)NNODES * NH];
__device__ float g_x2[(size_t)NNODES * NH];
__device__ __half g_xh[(size_t)NNODES * NH];
__device__ __half g_xh2[(size_t)NNODES * NH];
__device__ float g_agg[(size_t)NNODES * NH];
__device__ int   g_deg[NNODES];
__device__ int   g_rowstart[NNODES + 1];
__device__ int   g_cursor[NNODES];
__device__ int   g_elist[NEDGES];
__device__ int   g_esrc[NEDGES];
__device__ int   g_erid[NEDGES];
__device__ int   g_eaidx[NEDGES];
__device__ int   g_part[64];
__device__ int   g_bcnt[NBATCH];
__device__ int   g_bstart[NBATCH + 1];
__device__ float g_xg[NBATCH * NH];
__device__ float g_xacc[NBATCH * NH];
__device__ float g_den[NBATCH];
__device__ float g_xnode[NBATCH * NH];

// ---------------- helpers ----------------
__device__ __forceinline__ void cp_async16(void* smem_dst, const void* gsrc, int src_size) {
    uint32_t s = (uint32_t)__cvta_generic_to_shared(smem_dst);
    asm volatile("cp.async.ca.shared.global [%0], [%1], 16, %2;\n"
                 :: "r"(s), "l"(gsrc), "r"(src_size));
}
__device__ __forceinline__ void cp_commit() { asm volatile("cp.async.commit_group;\n"); }
template <int W> __device__ __forceinline__ void cp_wait() {
    asm volatile("cp.async.wait_group %0;\n" :: "n"(W));
}
__device__ __forceinline__ uint32_t smem_u32(const void* p) {
    return (uint32_t)__cvta_generic_to_shared(p);
}
__device__ __forceinline__ void ldsm_x4(uint32_t& r0, uint32_t& r1, uint32_t& r2,
                                        uint32_t& r3, uint32_t addr) {
    asm volatile("ldmatrix.sync.aligned.m8n8.x4.shared.b16 {%0,%1,%2,%3}, [%4];"
                 : "=r"(r0), "=r"(r1), "=r"(r2), "=r"(r3) : "r"(addr));
}
__device__ __forceinline__ void split_tf32(float v, uint32_t& hi, uint32_t& lo) {
    uint32_t h;
    asm("cvt.rna.tf32.f32 %0, %1;" : "=r"(h) : "f"(v));
    float l = v - __uint_as_float(h);
    uint32_t lt;
    asm("cvt.rna.tf32.f32 %0, %1;" : "=r"(lt) : "f"(l));
    hi = h; lo = lt;
}

// fp32 -> fp16 conversion (8 elems/thread)
__global__ void k_f2h(const float* __restrict__ in, __half* __restrict__ out, size_t n) {
    size_t i = ((size_t)blockIdx.x * blockDim.x + threadIdx.x) * 8;
    if (i >= n) return;
    float4 v0 = *(const float4*)(in + i);
    float4 v1 = *(const float4*)(in + i + 4);
    __half2 p0 = __floats2half2_rn(v0.x, v0.y);
    __half2 p1 = __floats2half2_rn(v0.z, v0.w);
    __half2 p2 = __floats2half2_rn(v1.x, v1.y);
    __half2 p3 = __floats2half2_rn(v1.z, v1.w);
    uint4 o;
    o.x = *(uint32_t*)&p0; o.y = *(uint32_t*)&p1;
    o.z = *(uint32_t*)&p2; o.w = *(uint32_t*)&p3;
    *(uint4*)(out + i) = o;
}

// ---------------- fp16 tensor-core GEMM for alpha logits ----------------
// One layer per launch. 4 warps, 64x64 warp tiles; m16n8k16 HMMA, fp32 accum.
// K-stage 32 halves (64B rows); HPB=40 halves/row -> conflict-free LDSM.
#define TBM 128
#define TBN 128
#define HBK 32
#define HPB 40

__global__ __launch_bounds__(128, 2) void alpha_gemm_fp16(
    const __half* __restrict__ A,
    const __half* __restrict__ B,
    const float* __restrict__ bias,
    float* __restrict__ C)
{
    const int M = NBATCH * NV, N = NVOC, K = NVOC;
    const int KITERS = K / HBK;    // 125

    __shared__ __half As[2][TBM * HPB];
    __shared__ __half Bs[2][TBN * HPB];

    int tid = threadIdx.x;
    int m0 = blockIdx.y * TBM;
    int n0 = blockIdx.x * TBN;
    int warp = tid >> 5, lane = tid & 31;
    int wm = (warp & 1) * 64;
    int wn = (warp >> 1) * 64;
    int lq = lane >> 2;
    int lr = lane & 3;
    int tile = lane >> 3, trow = lane & 7;

    float acc[4][8][4];
#pragma unroll
    for (int i = 0; i < 4; i++)
#pragma unroll
        for (int j = 0; j < 8; j++)
#pragma unroll
            for (int r = 0; r < 4; r++) acc[i][j][r] = 0.f;

#define ISSUE_TILES(stage, k0)                                                        \
    do {                                                                              \
        _Pragma("unroll")                                                             \
        for (int t = tid; t < 512; t += 128) {                                        \
            int row = t >> 2, ch = (t & 3) * 8;                                       \
            cp_async16(&As[stage][row * HPB + ch],                                    \
                       A + (size_t)(m0 + row) * K + (k0) + ch, 16);                   \
        }                                                                             \
        _Pragma("unroll")                                                             \
        for (int t = tid; t < 512; t += 128) {                                        \
            int row = t >> 2, ch = (t & 3) * 8;                                       \
            int gn = n0 + row;                                                        \
            int ok = gn < N;                                                          \
            cp_async16(&Bs[stage][row * HPB + ch],                                    \
                       B + (size_t)(ok ? gn : 0) * K + (k0) + ch, ok ? 16 : 0);       \
        }                                                                             \
    } while (0)

    ISSUE_TILES(0, 0);
    cp_commit();

    // LDSM address components (b16 native):
    //  A x4 per mi: r0=(rows lo,k lo) r1=(rows hi,k lo) r2=(rows lo,k hi) r3=(rows hi,k hi)
    int aRow = wm + ((tile & 1) << 3) + trow;
    int aKof = (tile >> 1) << 3;     // 0 or 8 halves
    //  B x4 per ni-pair: r0=b0(ni) r1=b1(ni) r2=b0(ni+1) r3=b1(ni+1)
    int bCol = wn + ((tile >> 1) << 3) + trow;
    int bKof = (tile & 1) << 3;

    for (int kt = 0; kt < KITERS; kt++) {
        int st = kt & 1;
        if (kt + 1 < KITERS) {
            ISSUE_TILES(st ^ 1, (kt + 1) * HBK);
            cp_commit();
            cp_wait<1>();
        } else {
            cp_wait<0>();
        }
        __syncthreads();

        const __half* as = As[st];
        const __half* bs = Bs[st];
        uint32_t abase = smem_u32(&as[aRow * HPB + aKof]);
        uint32_t bbase = smem_u32(&bs[bCol * HPB + bKof]);

#pragma unroll
        for (int kk = 0; kk < HBK; kk += 16) {
            uint32_t af[4][4];
            uint32_t bf[8][2];
#pragma unroll
            for (int mi = 0; mi < 4; mi++)
                ldsm_x4(af[mi][0], af[mi][1], af[mi][2], af[mi][3],
                        abase + (kk + mi * 16 * HPB) * 2);
#pragma unroll
            for (int np = 0; np < 4; np++)
                ldsm_x4(bf[2 * np][0], bf[2 * np][1], bf[2 * np + 1][0], bf[2 * np + 1][1],
                        bbase + (kk + np * 16 * HPB) * 2);
#pragma unroll
            for (int mi = 0; mi < 4; mi++)
#pragma unroll
                for (int ni = 0; ni < 8; ni++) {
                    asm volatile(
                        "mma.sync.aligned.m16n8k16.row.col.f32.f16.f16.f32 "
                        "{%0,%1,%2,%3}, {%4,%5,%6,%7}, {%8,%9}, {%0,%1,%2,%3};\n"
                        : "+f"(acc[mi][ni][0]), "+f"(acc[mi][ni][1]),
                          "+f"(acc[mi][ni][2]), "+f"(acc[mi][ni][3])
                        : "r"(af[mi][0]), "r"(af[mi][1]), "r"(af[mi][2]), "r"(af[mi][3]),
                          "r"(bf[ni][0]), "r"(bf[ni][1]));
                }
        }
        __syncthreads();
    }

#pragma unroll
    for (int mi = 0; mi < 4; mi++) {
#pragma unroll
        for (int ni = 0; ni < 8; ni++) {
            int r = m0 + wm + mi * 16 + lq;
            int c = n0 + wn + ni * 8 + lr * 2;
            if (c < N) {
                float2 bb = *(const float2*)(bias + c);
                float2 o0, o1;
                o0.x = acc[mi][ni][0] + bb.x; o0.y = acc[mi][ni][1] + bb.y;
                o1.x = acc[mi][ni][2] + bb.x; o1.y = acc[mi][ni][3] + bb.y;
                *(float2*)(C + (size_t)r * N + c) = o0;
                *(float2*)(C + (size_t)(r + 8) * N + c) = o1;
            }
        }
    }
#undef ISSUE_TILES
}

// ---------------- 3xTF32 compensated mma GEMM: K=128, N=128 -----------------
#define CPW 36

template <bool RELU, bool ADD2, bool HOUT>
__global__ __launch_bounds__(256) void gemm128_3xtf32(
    const float* __restrict__ A, const float* __restrict__ A2,
    const float* __restrict__ B, const float* __restrict__ bias,
    float* __restrict__ C, __half* __restrict__ Ch, int M)
{
    __shared__ float As[128 * CPW];
    __shared__ float Bs[128 * CPW];

    int tid = threadIdx.x;
    int m0 = blockIdx.x * 128;
    int warp = tid >> 5, lane = tid & 31;
    int wm = (warp & 1) * 64;
    int wn = (warp >> 1) * 32;
    int lq = lane >> 2;
    int lr = lane & 3;

    float acc[4][4][4];
#pragma unroll
    for (int i = 0; i < 4; i++)
#pragma unroll
        for (int j = 0; j < 4; j++)
#pragma unroll
            for (int r = 0; r < 4; r++) acc[i][j][r] = 0.f;

    for (int k0 = 0; k0 < NH; k0 += 32) {
        __syncthreads();
#pragma unroll
        for (int t = tid; t < 1024; t += 256) {
            int row = t >> 3, seg = (t & 7) * 4;
            int gm = m0 + row;
            float4 v = {0, 0, 0, 0};
            if (gm < M) {
                v = *(const float4*)(A + (size_t)gm * NH + k0 + seg);
                if (ADD2) {
                    float4 w = *(const float4*)(A2 + (size_t)gm * NH + k0 + seg);
                    v.x += w.x; v.y += w.y; v.z += w.z; v.w += w.w;
                }
            }
            *(float4*)&As[row * CPW + seg] = v;
            *(float4*)&Bs[row * CPW + seg] = *(const float4*)(B + (size_t)row * NH + k0 + seg);
        }
        __syncthreads();

#pragma unroll
        for (int kk = 0; kk < 32; kk += 8) {
            uint32_t ah[4][4], al[4][4];
            uint32_t bh[4][2], bl[4][2];
#pragma unroll
            for (int mi = 0; mi < 4; mi++) {
                int base = (wm + mi * 16 + lq) * CPW + kk + lr;
                split_tf32(As[base],               ah[mi][0], al[mi][0]);
                split_tf32(As[base + 8 * CPW],     ah[mi][1], al[mi][1]);
                split_tf32(As[base + 4],           ah[mi][2], al[mi][2]);
                split_tf32(As[base + 8 * CPW + 4], ah[mi][3], al[mi][3]);
            }
#pragma unroll
            for (int ni = 0; ni < 4; ni++) {
                int base = (wn + ni * 8 + lq) * CPW + kk + lr;
                split_tf32(Bs[base],     bh[ni][0], bl[ni][0]);
                split_tf32(Bs[base + 4], bh[ni][1], bl[ni][1]);
            }
#define MMA_TF32(Aop, Bop)                                                            \
    asm volatile(                                                                     \
        "mma.sync.aligned.m16n8k8.row.col.f32.tf32.tf32.f32 "                         \
        "{%0,%1,%2,%3}, {%4,%5,%6,%7}, {%8,%9}, {%0,%1,%2,%3};\n"                     \
        : "+f"(acc[mi][ni][0]), "+f"(acc[mi][ni][1]),                                 \
          "+f"(acc[mi][ni][2]), "+f"(acc[mi][ni][3])                                  \
        : "r"(Aop[mi][0]), "r"(Aop[mi][1]), "r"(Aop[mi][2]), "r"(Aop[mi][3]),         \
          "r"(Bop[ni][0]), "r"(Bop[ni][1]))
#pragma unroll
            for (int mi = 0; mi < 4; mi++)
#pragma unroll
                for (int ni = 0; ni < 4; ni++) {
                    MMA_TF32(ah, bh);
                    MMA_TF32(ah, bl);
                    MMA_TF32(al, bh);
                }
#undef MMA_TF32
        }
    }

#pragma unroll
    for (int mi = 0; mi < 4; mi++) {
#pragma unroll
        for (int ni = 0; ni < 4; ni++) {
            int r = m0 + wm + mi * 16 + lq;
            int c = wn + ni * 8 + lr * 2;
            float2 bb = *(const float2*)(bias + c);
            float2 o0, o1;
            o0.x = acc[mi][ni][0] + bb.x; o0.y = acc[mi][ni][1] + bb.y;
            o1.x = acc[mi][ni][2] + bb.x; o1.y = acc[mi][ni][3] + bb.y;
            if (RELU) {
                o0.x = fmaxf(o0.x, 0.f); o0.y = fmaxf(o0.y, 0.f);
                o1.x = fmaxf(o1.x, 0.f); o1.y = fmaxf(o1.y, 0.f);
            }
            if (r < M) {
                *(float2*)(C + (size_t)r * NH + c) = o0;
                if (HOUT) {
                    __half2 h = __floats2half2_rn(o0.x, o0.y);
                    *(__half2*)(Ch + (size_t)r * NH + c) = h;
                }
            }
            if (r + 8 < M) {
                *(float2*)(C + (size_t)(r + 8) * NH + c) = o1;
                if (HOUT) {
                    __half2 h = __floats2half2_rn(o1.x, o1.y);
                    *(__half2*)(Ch + (size_t)(r + 8) * NH + c) = h;
                }
            }
        }
    }
}

// ---------------- small kernels ----------------
__global__ void k_zero_int(int* __restrict__ p, int n) {
    int i = blockIdx.x * blockDim.x + threadIdx.x;
    if (i < n) p[i] = 0;
}
__global__ void k_zero_float(float* __restrict__ p, int n) {
    int i = blockIdx.x * blockDim.x + threadIdx.x;
    if (i < n) p[i] = 0.f;
}

__global__ void k_hist(const int* __restrict__ keys, int* __restrict__ cnt, int n) {
    int i = blockIdx.x * blockDim.x + threadIdx.x;
    if (i < n) atomicAdd(&cnt[keys[i]], 1);
}

__global__ void k_hist_batch(const int* __restrict__ batch, int* __restrict__ bcnt) {
    __shared__ int h[NBATCH];
    if (threadIdx.x < NBATCH) h[threadIdx.x] = 0;
    __syncthreads();
    int i = blockIdx.x * blockDim.x + threadIdx.x;
    if (i < NNODES) atomicAdd(&h[batch[i]], 1);
    __syncthreads();
    if (threadIdx.x < NBATCH) atomicAdd(&bcnt[threadIdx.x], h[threadIdx.x]);
}

__global__ void k_scan_block(const int* __restrict__ in, int* __restrict__ outEx,
                             int* __restrict__ part, int n) {
    __shared__ int s[1024];
    int t = threadIdx.x;
    int i = blockIdx.x * 1024 + t;
    int v = (i < n) ? in[i] : 0;
    s[t] = v;
    __syncthreads();
    for (int off = 1; off < 1024; off <<= 1) {
        int y = (t >= off) ? s[t - off] : 0;
        __syncthreads();
        s[t] += y;
        __syncthreads();
    }
    if (i < n) outEx[i] = s[t] - v;
    if (t == 1023) part[blockIdx.x] = s[1023];
}

__global__ void k_scan_part(int* __restrict__ part, int nb, int* __restrict__ rowstart) {
    if (threadIdx.x == 0 && blockIdx.x == 0) {
        int acc = 0;
        for (int i = 0; i < nb; i++) { int v = part[i]; part[i] = acc; acc += v; }
        rowstart[NNODES] = NEDGES;
    }
}

__global__ void k_scan_add(int* __restrict__ rowstart, const int* __restrict__ part,
                           int* __restrict__ cursor, int n) {
    int i = blockIdx.x * 1024 + threadIdx.x;
    if (i < n) {
        int v = rowstart[i] + part[blockIdx.x];
        rowstart[i] = v;
        cursor[i] = v;
    }
}

__global__ void k_scatter(const int* __restrict__ dst, int* __restrict__ cursor,
                          int* __restrict__ elist, int n) {
    int e = blockIdx.x * blockDim.x + threadIdx.x;
    if (e < n) {
        int d = dst[e];
        int p = atomicAdd(&cursor[d], 1);
        elist[p] = e;
    }
}

__global__ void k_eperm(const int* __restrict__ elist, const int* __restrict__ srcArr,
                        const int* __restrict__ ridArr, const int* __restrict__ nodeIds,
                        const int* __restrict__ batchArr,
                        int* __restrict__ esrc, int* __restrict__ erid,
                        int* __restrict__ eaidx, int n) {
    int i = blockIdx.x * blockDim.x + threadIdx.x;
    if (i < n) {
        int e = elist[i];
        int s = srcArr[e];
        esrc[i] = s;
        erid[i] = ridArr[e];
        eaidx[i] = batchArr[s] * NVOC + nodeIds[s];
    }
}

__global__ void k_bscan(const int* __restrict__ bcnt, int* __restrict__ bstart) {
    if (threadIdx.x == 0 && blockIdx.x == 0) {
        int acc = 0;
        for (int b = 0; b < NBATCH; b++) { bstart[b] = acc; acc += bcnt[b]; }
        bstart[NBATCH] = acc;
    }
}

__global__ void k_wrel(const float* __restrict__ Erel, const float* __restrict__ wr_w,
                       const float* __restrict__ wr_b, float* __restrict__ wrel) {
    int w = (blockIdx.x * blockDim.x + threadIdx.x) >> 5;
    int lane = threadIdx.x & 31;
    if (w >= NL * NREL) return;
    int l = w / NREL, r = w % NREL;
    float acc = 0.f;
#pragma unroll
    for (int h = lane; h < NH; h += 32) acc += Erel[r * NH + h] * wr_w[l * NH + h];
#pragma unroll
    for (int o = 16; o; o >>= 1) acc += __shfl_down_sync(0xffffffffu, acc, o);
    if (lane == 0) wrel[w] = acc + wr_b[l];
}

__global__ void k_gather(const float* __restrict__ Enode, const int* __restrict__ node_ids,
                         float* __restrict__ x, __half* __restrict__ xh) {
    int t = blockIdx.x * blockDim.x + threadIdx.x;
    if (t >= NNODES * 32) return;
    int i = t >> 5, q = t & 31;
    int nid = node_ids[i];
    float4 v = *(const float4*)(Enode + (size_t)nid * NH + q * 4);
    *(float4*)(x + (size_t)i * NH + q * 4) = v;
    __half2 h0 = __floats2half2_rn(v.x, v.y);
    __half2 h1 = __floats2half2_rn(v.z, v.w);
    uint2 raw;
    raw.x = *(uint32_t*)&h0; raw.y = *(uint32_t*)&h1;
    *(uint2*)(xh + (size_t)i * NH + q * 4) = raw;
}

__global__ void k_beta(const float* __restrict__ vn, const float* __restrict__ beta_w,
                       const float* __restrict__ beta_b, float* __restrict__ betaOut) {
    int w = (blockIdx.x * blockDim.x + threadIdx.x) >> 5;
    int lane = threadIdx.x & 31;
    if (w >= NL * NBATCH * NV) return;
    int l = w / (NBATCH * NV);
    int rem = w % (NBATCH * NV);
    int b = rem / NV, v = rem % NV;
    const float* row = vn + ((size_t)b * NV + v) * NVOC;
    const float* bw = beta_w + l * NVOC;
    float acc = 0.f;
    for (int n = lane; n < NVOC; n += 32) acc += row[n] * bw[n];
#pragma unroll
    for (int o = 16; o; o >>= 1) acc += __shfl_down_sync(0xffffffffu, acc, o);
    if (lane == 0)
        betaOut[w] = tanhf(acc + beta_b[l]) * expf(0.03f * (float)(NV - v));
}

__global__ void k_attn(const float* __restrict__ Z, const float* __restrict__ betaL,
                       float* __restrict__ attnL) {
    int m = blockIdx.x * blockDim.x + threadIdx.x;
    int b = blockIdx.y;
    if (m >= NVOC) return;
    float z[NV];
    float mx = -1e30f;
#pragma unroll
    for (int v = 0; v < NV; v++) {
        z[v] = Z[((size_t)(b * NV + v)) * NVOC + m];
        mx = fmaxf(mx, z[v]);
    }
    float s = 0.f, num = 0.f;
#pragma unroll
    for (int v = 0; v < NV; v++) {
        float e = expf(z[v] - mx);
        s += e;
        num += e * betaL[b * NV + v];
    }
    attnL[(size_t)b * NVOC + m] = num / s;
}

// warp-per-node aggregate; x gathered in fp16, fp32 accum
__global__ void k_aggregate(const __half* __restrict__ xh, const float* __restrict__ Erel,
                            const float* __restrict__ attnL, const float* __restrict__ wrelL,
                            const int* __restrict__ esrc, const int* __restrict__ erid,
                            const int* __restrict__ eaidx, const int* __restrict__ rowstart,
                            float* __restrict__ agg) {
    int warp = (blockIdx.x * blockDim.x + threadIdx.x) >> 5;
    int lane = threadIdx.x & 31;
    if (warp >= NNODES) return;
    int s0 = rowstart[warp], s1 = rowstart[warp + 1];
    float4 acc = {0.f, 0.f, 0.f, 0.f};
    for (int idx = s0; idx < s1; idx++) {
        int s = esrc[idx];
        int r = erid[idx];
        float ea = attnL[eaidx[idx]];
        float w = wrelL[r];
        uint2 raw = *(const uint2*)(xh + (size_t)s * NH + lane * 4);
        __half2 h0 = *(__half2*)&raw.x;
        __half2 h1 = *(__half2*)&raw.y;
        float2 f0 = __half22float2(h0);
        float2 f1 = __half22float2(h1);
        float4 ev = *(const float4*)(Erel + (size_t)r * NH + lane * 4);
        acc.x += fmaxf(fmaf(f0.x, ea, w * ev.x), 0.f);
        acc.y += fmaxf(fmaf(f0.y, ea, w * ev.y), 0.f);
        acc.z += fmaxf(fmaf(f1.x, ea, w * ev.z), 0.f);
        acc.w += fmaxf(fmaf(f1.y, ea, w * ev.w), 0.f);
    }
    *(float4*)(agg + (size_t)warp * NH + lane * 4) = acc;
}

__global__ void k_pool_partial(const float* __restrict__ x, const int* __restrict__ bstart,
                               float* __restrict__ xg) {
    int b = blockIdx.y, chunk = blockIdx.x, h = threadIdx.x;
    int s0 = bstart[b], s1 = bstart[b + 1];
    int len = s1 - s0;
    int r0 = s0 + (int)((long long)len * chunk / 8);
    int r1 = s0 + (int)((long long)len * (chunk + 1) / 8);
    float acc = 0.f;
    for (int i = r0; i < r1; i++) acc += x[(size_t)i * NH + h];
    atomicAdd(&xg[b * NH + h], acc);
}

__global__ void k_pool_finish(float* __restrict__ xg, const int* __restrict__ bcnt) {
    int b = blockIdx.x, h = threadIdx.x;
    float c = (float)bcnt[b];
    xg[b * NH + h] /= fmaxf(c, 1.f);
}

__global__ void k_ehrsum(const float* __restrict__ ehr, float* __restrict__ den) {
    int b = blockIdx.x, t = threadIdx.x;
    __shared__ float s[256];
    float acc = 0.f;
    for (int n = t; n < NVOC; n += 256) acc += ehr[(size_t)b * NVOC + n];
    s[t] = acc;
    __syncthreads();
    for (int o = 128; o; o >>= 1) {
        if (t < o) s[t] += s[t + o];
        __syncthreads();
    }
    if (t == 0) den[b] = s[0];
}

__global__ void k_xnode_partial(const float* __restrict__ ehr,
                                const float* __restrict__ node_emb,
                                float* __restrict__ xacc) {
    int b = blockIdx.y, slice = blockIdx.x, h = threadIdx.x;
    int n0 = slice * (NVOC / 16), n1 = n0 + (NVOC / 16);
    float acc = 0.f;
    for (int n = n0; n < n1; n++)
        acc += ehr[(size_t)b * NVOC + n] * node_emb[(size_t)n * NH + h];
    atomicAdd(&xacc[b * NH + h], acc);
}

__global__ void k_xnode_finish(const float* __restrict__ xacc, const float* __restrict__ den,
                               const float* __restrict__ lin_w, const float* __restrict__ lin_b,
                               float* __restrict__ xnode) {
    int b = blockIdx.x, h = threadIdx.x;
    __shared__ float t[NH];
    t[h] = xacc[b * NH + h] / den[b];
    __syncthreads();
    float s = 0.f;
#pragma unroll 8
    for (int hh = 0; hh < NH; hh++) s += t[hh] * lin_w[h * NH + hh];
    xnode[b * NH + h] = s + lin_b[h];
}

__global__ void k_final(const float* __restrict__ xg, const float* __restrict__ xn,
                        const float* __restrict__ mlp_w, const float* __restrict__ mlp_b,
                        float* __restrict__ out) {
    int b = blockIdx.x, t = threadIdx.x;
    __shared__ float s[2 * NH];
    s[t] = xg[b * NH + t];
    s[NH + t] = xn[b * NH + t];
    __syncthreads();
    if (t < NOUT) {
        float acc = mlp_b[t];
        const float* w = mlp_w + t * (2 * NH);
#pragma unroll 8
        for (int k = 0; k < 2 * NH; k++) acc += s[k] * w[k];
        out[b * NOUT + t] = acc;
    }
}

// ---------------- launch ----------------
extern "C" void kernel_launch(void* const* d_in, const int* in_sizes, int n_in,
                              void* d_out, int out_size) {
    const float* node_emb = (const float*)d_in[0];
    const float* rel_emb  = (const float*)d_in[1];
    const float* lin_w    = (const float*)d_in[2];
    const float* lin_b    = (const float*)d_in[3];
    const float* alpha_w  = (const float*)d_in[4];
    const float* alpha_b  = (const float*)d_in[5];
    const float* beta_w   = (const float*)d_in[6];
    const float* beta_b   = (const float*)d_in[7];
    const float* wr_w     = (const float*)d_in[8];
    const float* wr_b     = (const float*)d_in[9];
    const float* conv_w   = (const float*)d_in[10];
    const float* conv_b   = (const float*)d_in[11];
    const float* mlp_w    = (const float*)d_in[12];
    const float* mlp_b    = (const float*)d_in[13];
    const float* visit    = (const float*)d_in[14];
    const float* ehr      = (const float*)d_in[15];
    const int* node_ids   = (const int*)d_in[16];
    const int* rel_ids    = (const int*)d_in[17];
    const int* eidx       = (const int*)d_in[18];
    const int* batch      = (const int*)d_in[19];
    float* out = (float*)d_out;

    const int* srcArr = eidx;
    const int* dstArr = eidx + NEDGES;

    float *Zp, *Enodep, *Erelp, *wrelp, *attnp, *betap, *xp, *x2p, *aggp;
    float *xgp, *xaccp, *denp, *xnodep;
    __half *xhp, *xh2p, *vhp, *whp;
    int *degp, *rowstartp, *cursorp, *elistp, *esrcp, *eridp, *eaidxp;
    int *partp, *bcntp, *bstartp;
    cudaGetSymbolAddress((void**)&Zp, g_Z);
    cudaGetSymbolAddress((void**)&vhp, g_vh);
    cudaGetSymbolAddress((void**)&whp, g_wh);
    cudaGetSymbolAddress((void**)&Enodep, g_Enode);
    cudaGetSymbolAddress((void**)&Erelp, g_Erel);
    cudaGetSymbolAddress((void**)&wrelp, g_wrel);
    cudaGetSymbolAddress((void**)&attnp, g_attn);
    cudaGetSymbolAddress((void**)&betap, g_beta);
    cudaGetSymbolAddress((void**)&xp, g_x);
    cudaGetSymbolAddress((void**)&x2p, g_x2);
    cudaGetSymbolAddress((void**)&xhp, g_xh);
    cudaGetSymbolAddress((void**)&xh2p, g_xh2);
    cudaGetSymbolAddress((void**)&aggp, g_agg);
    cudaGetSymbolAddress((void**)&xgp, g_xg);
    cudaGetSymbolAddress((void**)&xaccp, g_xacc);
    cudaGetSymbolAddress((void**)&denp, g_den);
    cudaGetSymbolAddress((void**)&xnodep, g_xnode);
    cudaGetSymbolAddress((void**)&degp, g_deg);
    cudaGetSymbolAddress((void**)&rowstartp, g_rowstart);
    cudaGetSymbolAddress((void**)&cursorp, g_cursor);
    cudaGetSymbolAddress((void**)&elistp, g_elist);
    cudaGetSymbolAddress((void**)&esrcp, g_esrc);
    cudaGetSymbolAddress((void**)&eridp, g_erid);
    cudaGetSymbolAddress((void**)&eaidxp, g_eaidx);
    cudaGetSymbolAddress((void**)&partp, g_part);
    cudaGetSymbolAddress((void**)&bcntp, g_bcnt);
    cudaGetSymbolAddress((void**)&bstartp, g_bstart);

    static cudaStream_t sMain = nullptr, sSide = nullptr;
    static cudaEvent_t evFork = nullptr, evJoin = nullptr;
    static cudaEvent_t evZ[NL] = {nullptr, nullptr, nullptr};
    static cudaEvent_t evW[NL] = {nullptr, nullptr, nullptr};
    if (sMain == nullptr) {
        int prLo, prHi;
        cudaDeviceGetStreamPriorityRange(&prLo, &prHi);
        cudaStreamCreateWithPriority(&sMain, cudaStreamNonBlocking, prHi);
        cudaStreamCreateWithPriority(&sSide, cudaStreamNonBlocking, prLo);
        cudaEventCreateWithFlags(&evFork, cudaEventDisableTiming);
        cudaEventCreateWithFlags(&evJoin, cudaEventDisableTiming);
        for (int l = 0; l < NL; l++) {
            cudaEventCreateWithFlags(&evZ[l], cudaEventDisableTiming);
            cudaEventCreateWithFlags(&evW[l], cudaEventDisableTiming);
        }
    }

    const int SCAN_BLOCKS = (NNODES + 1023) / 1024;
    const size_t ZL = (size_t)NBATCH * NV * NVOC;
    const size_t WL = (size_t)NVOC * NVOC;

    // ---- fork ----
    cudaEventRecord(evFork, 0);
    cudaStreamWaitEvent(sMain, evFork, 0);
    cudaStreamWaitEvent(sSide, evFork, 0);

    // sMain: convert visit + W0, then alpha layers (fp16)
    k_f2h<<<(unsigned)((ZL / 8 + 255) / 256), 256, 0, sMain>>>(visit, vhp, ZL);
    k_f2h<<<(unsigned)((WL / 8 + 255) / 256), 256, 0, sMain>>>(alpha_w, whp, WL);
    // sSide: convert W1, W2 first (signaled), then pre-work
    k_f2h<<<(unsigned)((WL / 8 + 255) / 256), 256, 0, sSide>>>(
        alpha_w + WL, whp + WL, WL);
    cudaEventRecord(evW[1], sSide);
    k_f2h<<<(unsigned)((WL / 8 + 255) / 256), 256, 0, sSide>>>(
        alpha_w + 2 * WL, whp + 2 * WL, WL);
    cudaEventRecord(evW[2], sSide);

    for (int l = 0; l < NL; l++) {
        if (l > 0) cudaStreamWaitEvent(sMain, evW[l], 0);
        alpha_gemm_fp16<<<dim3((NVOC + TBN - 1) / TBN, (NBATCH * NV) / TBM), 128, 0,
                          sMain>>>(
            vhp, whp + (size_t)l * WL, alpha_b + (size_t)l * NVOC, Zp + l * ZL);
        cudaEventRecord(evZ[l], sMain);
    }

    // sSide: alpha-independent pre-work
    gemm128_3xtf32<false, false, false><<<(NVOC + 127) / 128, 256, 0, sSide>>>(
        node_emb, nullptr, lin_w, lin_b, Enodep, nullptr, NVOC);
    gemm128_3xtf32<false, false, false><<<(NREL + 127) / 128, 256, 0, sSide>>>(
        rel_emb, nullptr, lin_w, lin_b, Erelp, nullptr, NREL);
    k_wrel<<<(NL * NREL * 32 + 255) / 256, 256, 0, sSide>>>(Erelp, wr_w, wr_b, wrelp);
    k_gather<<<(NNODES * 32 + 255) / 256, 256, 0, sSide>>>(Enodep, node_ids, xp, xhp);
    k_beta<<<(NL * NBATCH * NV * 32 + 255) / 256, 256, 0, sSide>>>(
        visit, beta_w, beta_b, betap);
    k_zero_int<<<(NNODES + 255) / 256, 256, 0, sSide>>>(degp, NNODES);
    k_zero_int<<<1, 64, 0, sSide>>>(bcntp, NBATCH);
    k_hist<<<(NEDGES + 255) / 256, 256, 0, sSide>>>(dstArr, degp, NEDGES);
    k_hist_batch<<<(NNODES + 255) / 256, 256, 0, sSide>>>(batch, bcntp);
    k_scan_block<<<SCAN_BLOCKS, 1024, 0, sSide>>>(degp, rowstartp, partp, NNODES);
    k_scan_part<<<1, 1, 0, sSide>>>(partp, SCAN_BLOCKS, rowstartp);
    k_scan_add<<<SCAN_BLOCKS, 1024, 0, sSide>>>(rowstartp, partp, cursorp, NNODES);
    k_scatter<<<(NEDGES + 255) / 256, 256, 0, sSide>>>(dstArr, cursorp, elistp, NEDGES);
    k_eperm<<<(NEDGES + 255) / 256, 256, 0, sSide>>>(
        elistp, srcArr, rel_ids, node_ids, batch, esrcp, eridp, eaidxp, NEDGES);
    k_bscan<<<1, 1, 0, sSide>>>(bcntp, bstartp);
    k_zero_float<<<(NBATCH * NH + 255) / 256, 256, 0, sSide>>>(xgp, NBATCH * NH);
    k_zero_float<<<(NBATCH * NH + 255) / 256, 256, 0, sSide>>>(xaccp, NBATCH * NH);
    k_ehrsum<<<NBATCH, 256, 0, sSide>>>(ehr, denp);
    k_xnode_partial<<<dim3(16, NBATCH), NH, 0, sSide>>>(ehr, node_emb, xaccp);
    k_xnode_finish<<<NBATCH, NH, 0, sSide>>>(xaccp, denp, lin_w, lin_b, xnodep);

    // sSide: per-layer pipeline
    float* xcur = xp;
    float* xalt = x2p;
    __half* xhcur = xhp;
    __half* xhalt = xh2p;
    for (int l = 0; l < NL; l++) {
        cudaStreamWaitEvent(sSide, evZ[l], 0);
        k_attn<<<dim3((NVOC + 255) / 256, NBATCH), 256, 0, sSide>>>(
            Zp + l * ZL, betap + l * NBATCH * NV, attnp + (size_t)l * NBATCH * NVOC);
        k_aggregate<<<(NNODES * 32 + 255) / 256, 256, 0, sSide>>>(
            xhcur, Erelp, attnp + (size_t)l * NBATCH * NVOC, wrelp + l * NREL,
            esrcp, eridp, eaidxp, rowstartp, aggp);
        gemm128_3xtf32<true, true, true><<<(NNODES + 127) / 128, 256, 0, sSide>>>(
            aggp, xcur, conv_w + (size_t)l * NH * NH, conv_b + (size_t)l * NH,
            xalt, xhalt, NNODES);
        float* tf = xcur; xcur = xalt; xalt = tf;
        __half* th = xhcur; xhcur = xhalt; xhalt = th;
    }

    // sSide: pooling
    k_pool_partial<<<dim3(8, NBATCH), NH, 0, sSide>>>(xcur, bstartp, xgp);
    k_pool_finish<<<NBATCH, NH, 0, sSide>>>(xgp, bcntp);

    // ---- join ----
    cudaEventRecord(evJoin, sSide);
    cudaStreamWaitEvent(0, evJoin, 0);

    k_final<<<NBATCH, NH>>>(xgp, xnodep, mlp_w, mlp_b, out);
}

// round 17
// speedup vs baseline: 5.6288x; 1.1215x over previous
#include <cuda_runtime.h>
#include <cuda_fp16.h>
#include <math.h>
#include <stdint.h>

#define NNODES 50000
#define NEDGES 800000
#define NBATCH 32
#define NV 20
#define NVOC 4000
#define NREL 200
#define NH 128
#define NL 3
#define NOUT 100

// ---------------- device scratch ----------------
__device__ float g_Z[(size_t)NL * NBATCH * NV * NVOC];
__device__ __half g_vh[(size_t)NBATCH * NV * NVOC];
__device__ __half g_wh[(size_t)NL * NVOC * NVOC];
__device__ float g_Enode[NVOC * NH];
__device__ float g_Erel[NREL * NH];
__device__ float g_wrel[NL * NREL];
__device__ float g_attn[(size_t)NL * NBATCH * NVOC];
__device__ float g_beta[NL * NBATCH * NV];
__device__ float g_x[(size_t)NNODES * NH];
__device__ float g_x2[(size_t)NNODES * NH];
__device__ __half g_xh[(size_t)NNODES * NH];
__device__ __half g_xh2[(size_t)NNODES * NH];
__device__ float g_agg[(size_t)NNODES * NH];
__device__ int   g_deg[NNODES];
__device__ int   g_rowstart[NNODES + 1];
__device__ int   g_cursor[NNODES];
__device__ int   g_elist[NEDGES];
__device__ int   g_esrc[NEDGES];
__device__ int   g_erid[NEDGES];
__device__ int   g_eaidx[NEDGES];
__device__ int   g_part[64];
__device__ int   g_bcnt[NBATCH];
__device__ int   g_bstart[NBATCH + 1];
__device__ float g_xg[NBATCH * NH];
__device__ float g_xacc[NBATCH * NH];
__device__ float g_den[NBATCH];
__device__ float g_xnode[NBATCH * NH];

// ---------------- helpers ----------------
__device__ __forceinline__ void cp_async16(void* smem_dst, const void* gsrc, int src_size) {
    uint32_t s = (uint32_t)__cvta_generic_to_shared(smem_dst);
    asm volatile("cp.async.ca.shared.global [%0], [%1], 16, %2;\n"
                 :: "r"(s), "l"(gsrc), "r"(src_size));
}
__device__ __forceinline__ void cp_commit() { asm volatile("cp.async.commit_group;\n"); }
template <int W> __device__ __forceinline__ void cp_wait() {
    asm volatile("cp.async.wait_group %0;\n" :: "n"(W));
}
__device__ __forceinline__ uint32_t smem_u32(const void* p) {
    return (uint32_t)__cvta_generic_to_shared(p);
}
__device__ __forceinline__ void ldsm_x4(uint32_t& r0, uint32_t& r1, uint32_t& r2,
                                        uint32_t& r3, uint32_t addr) {
    asm volatile("ldmatrix.sync.aligned.m8n8.x4.shared.b16 {%0,%1,%2,%3}, [%4];"
                 : "=r"(r0), "=r"(r1), "=r"(r2), "=r"(r3) : "r"(addr));
}
__device__ __forceinline__ void split_tf32(float v, uint32_t& hi, uint32_t& lo) {
    uint32_t h;
    asm("cvt.rna.tf32.f32 %0, %1;" : "=r"(h) : "f"(v));
    float l = v - __uint_as_float(h);
    uint32_t lt;
    asm("cvt.rna.tf32.f32 %0, %1;" : "=r"(lt) : "f"(l));
    hi = h; lo = lt;
}

__global__ void k_f2h(const float* __restrict__ in, __half* __restrict__ out, size_t n) {
    size_t i = ((size_t)blockIdx.x * blockDim.x + threadIdx.x) * 8;
    if (i >= n) return;
    float4 v0 = *(const float4*)(in + i);
    float4 v1 = *(const float4*)(in + i + 4);
    __half2 p0 = __floats2half2_rn(v0.x, v0.y);
    __half2 p1 = __floats2half2_rn(v0.z, v0.w);
    __half2 p2 = __floats2half2_rn(v1.x, v1.y);
    __half2 p3 = __floats2half2_rn(v1.z, v1.w);
    uint4 o;
    o.x = *(uint32_t*)&p0; o.y = *(uint32_t*)&p1;
    o.z = *(uint32_t*)&p2; o.w = *(uint32_t*)&p3;
    *(uint4*)(out + i) = o;
}

// ---------------- fp16 tensor-core GEMM for alpha logits (R15 proven) -------
#define TBM 128
#define TBN 128
#define HBK 32
#define HPB 40

__global__ __launch_bounds__(128, 2) void alpha_gemm_fp16(
    const __half* __restrict__ A,
    const __half* __restrict__ B,
    const float* __restrict__ bias,
    float* __restrict__ C)
{
    const int M = NBATCH * NV, N = NVOC, K = NVOC;
    const int KITERS = K / HBK;

    __shared__ __half As[2][TBM * HPB];
    __shared__ __half Bs[2][TBN * HPB];

    int tid = threadIdx.x;
    int m0 = blockIdx.y * TBM;
    int n0 = blockIdx.x * TBN;
    int warp = tid >> 5, lane = tid & 31;
    int wm = (warp & 1) * 64;
    int wn = (warp >> 1) * 64;
    int lq = lane >> 2;
    int lr = lane & 3;
    int tile = lane >> 3, trow = lane & 7;

    float acc[4][8][4];
#pragma unroll
    for (int i = 0; i < 4; i++)
#pragma unroll
        for (int j = 0; j < 8; j++)
#pragma unroll
            for (int r = 0; r < 4; r++) acc[i][j][r] = 0.f;

#define ISSUE_TILES(stage, k0)                                                        \
    do {                                                                              \
        _Pragma("unroll")                                                             \
        for (int t = tid; t < 512; t += 128) {                                        \
            int row = t >> 2, ch = (t & 3) * 8;                                       \
            cp_async16(&As[stage][row * HPB + ch],                                    \
                       A + (size_t)(m0 + row) * K + (k0) + ch, 16);                   \
        }                                                                             \
        _Pragma("unroll")                                                             \
        for (int t = tid; t < 512; t += 128) {                                        \
            int row = t >> 2, ch = (t & 3) * 8;                                       \
            int gn = n0 + row;                                                        \
            int ok = gn < N;                                                          \
            cp_async16(&Bs[stage][row * HPB + ch],                                    \
                       B + (size_t)(ok ? gn : 0) * K + (k0) + ch, ok ? 16 : 0);       \
        }                                                                             \
    } while (0)

    ISSUE_TILES(0, 0);
    cp_commit();

    int aRow = wm + ((tile & 1) << 3) + trow;
    int aKof = (tile >> 1) << 3;
    int bCol = wn + ((tile >> 1) << 3) + trow;
    int bKof = (tile & 1) << 3;

    for (int kt = 0; kt < KITERS; kt++) {
        int st = kt & 1;
        if (kt + 1 < KITERS) {
            ISSUE_TILES(st ^ 1, (kt + 1) * HBK);
            cp_commit();
            cp_wait<1>();
        } else {
            cp_wait<0>();
        }
        __syncthreads();

        const __half* as = As[st];
        const __half* bs = Bs[st];
        uint32_t abase = smem_u32(&as[aRow * HPB + aKof]);
        uint32_t bbase = smem_u32(&bs[bCol * HPB + bKof]);

#pragma unroll
        for (int kk = 0; kk < HBK; kk += 16) {
            uint32_t af[4][4];
            uint32_t bf[8][2];
#pragma unroll
            for (int mi = 0; mi < 4; mi++)
                ldsm_x4(af[mi][0], af[mi][1], af[mi][2], af[mi][3],
                        abase + (kk + mi * 16 * HPB) * 2);
#pragma unroll
            for (int np = 0; np < 4; np++)
                ldsm_x4(bf[2 * np][0], bf[2 * np][1], bf[2 * np + 1][0], bf[2 * np + 1][1],
                        bbase + (kk + np * 16 * HPB) * 2);
#pragma unroll
            for (int mi = 0; mi < 4; mi++)
#pragma unroll
                for (int ni = 0; ni < 8; ni++) {
                    asm volatile(
                        "mma.sync.aligned.m16n8k16.row.col.f32.f16.f16.f32 "
                        "{%0,%1,%2,%3}, {%4,%5,%6,%7}, {%8,%9}, {%0,%1,%2,%3};\n"
                        : "+f"(acc[mi][ni][0]), "+f"(acc[mi][ni][1]),
                          "+f"(acc[mi][ni][2]), "+f"(acc[mi][ni][3])
                        : "r"(af[mi][0]), "r"(af[mi][1]), "r"(af[mi][2]), "r"(af[mi][3]),
                          "r"(bf[ni][0]), "r"(bf[ni][1]));
                }
        }
        __syncthreads();
    }

#pragma unroll
    for (int mi = 0; mi < 4; mi++) {
#pragma unroll
        for (int ni = 0; ni < 8; ni++) {
            int r = m0 + wm + mi * 16 + lq;
            int c = n0 + wn + ni * 8 + lr * 2;
            if (c < N) {
                float2 bb = *(const float2*)(bias + c);
                float2 o0, o1;
                o0.x = acc[mi][ni][0] + bb.x; o0.y = acc[mi][ni][1] + bb.y;
                o1.x = acc[mi][ni][2] + bb.x; o1.y = acc[mi][ni][3] + bb.y;
                *(float2*)(C + (size_t)r * N + c) = o0;
                *(float2*)(C + (size_t)(r + 8) * N + c) = o1;
            }
        }
    }
#undef ISSUE_TILES
}

// ---------------- conv: fp16-split compensated GEMM (fp32-equivalent) -------
// C[M,128] = relu((A+A2) @ B^T + bias); hi/lo fp16 planes, hi*hi+hi*lo+lo*hi.
__global__ __launch_bounds__(128, 2) void conv_fp16split(
    const float* __restrict__ A, const float* __restrict__ A2,
    const float* __restrict__ B, const float* __restrict__ bias,
    float* __restrict__ C, __half* __restrict__ Ch, int M)
{
    __shared__ __half Ahi[128 * HPB], Alo[128 * HPB];
    __shared__ __half Bhi[128 * HPB], Blo[128 * HPB];

    int tid = threadIdx.x;
    int m0 = blockIdx.x * 128;
    int warp = tid >> 5, lane = tid & 31;
    int wm = (warp & 1) * 64;
    int wn = (warp >> 1) * 64;
    int lq = lane >> 2;
    int lr = lane & 3;
    int tile = lane >> 3, trow = lane & 7;

    float acc[4][8][4];
#pragma unroll
    for (int i = 0; i < 4; i++)
#pragma unroll
        for (int j = 0; j < 8; j++)
#pragma unroll
            for (int r = 0; r < 4; r++) acc[i][j][r] = 0.f;

    int aRow = wm + ((tile & 1) << 3) + trow;
    int aKof = (tile >> 1) << 3;
    int bCol = wn + ((tile >> 1) << 3) + trow;
    int bKof = (tile & 1) << 3;

    for (int k0 = 0; k0 < NH; k0 += 32) {
        __syncthreads();
        // load + split: A rows (agg + x) and B rows (conv_w), 128x32 each
#pragma unroll
        for (int i = 0; i < 8; i++) {
            int idx = tid + i * 128;             // 0..1023
            int row = idx >> 3, seg = (idx & 7) * 4;
            int gm = m0 + row;
            float4 v = {0, 0, 0, 0};
            if (gm < M) {
                v = *(const float4*)(A + (size_t)gm * NH + k0 + seg);
                float4 w = *(const float4*)(A2 + (size_t)gm * NH + k0 + seg);
                v.x += w.x; v.y += w.y; v.z += w.z; v.w += w.w;
            }
            __half h0 = __float2half_rn(v.x), h1 = __float2half_rn(v.y);
            __half h2 = __float2half_rn(v.z), h3 = __float2half_rn(v.w);
            __half l0 = __float2half_rn(v.x - __half2float(h0));
            __half l1 = __float2half_rn(v.y - __half2float(h1));
            __half l2 = __float2half_rn(v.z - __half2float(h2));
            __half l3 = __float2half_rn(v.w - __half2float(h3));
            __half2 hh0 = __halves2half2(h0, h1), hh1 = __halves2half2(h2, h3);
            __half2 ll0 = __halves2half2(l0, l1), ll1 = __halves2half2(l2, l3);
            uint2 oh, ol;
            oh.x = *(uint32_t*)&hh0; oh.y = *(uint32_t*)&hh1;
            ol.x = *(uint32_t*)&ll0; ol.y = *(uint32_t*)&ll1;
            *(uint2*)&Ahi[row * HPB + seg] = oh;
            *(uint2*)&Alo[row * HPB + seg] = ol;

            float4 b = *(const float4*)(B + (size_t)row * NH + k0 + seg);
            __half g0 = __float2half_rn(b.x), g1 = __float2half_rn(b.y);
            __half g2 = __float2half_rn(b.z), g3 = __float2half_rn(b.w);
            __half m0h = __float2half_rn(b.x - __half2float(g0));
            __half m1h = __float2half_rn(b.y - __half2float(g1));
            __half m2h = __float2half_rn(b.z - __half2float(g2));
            __half m3h = __float2half_rn(b.w - __half2float(g3));
            __half2 gh0 = __halves2half2(g0, g1), gh1 = __halves2half2(g2, g3);
            __half2 gl0 = __halves2half2(m0h, m1h), gl1 = __halves2half2(m2h, m3h);
            uint2 obh, obl;
            obh.x = *(uint32_t*)&gh0; obh.y = *(uint32_t*)&gh1;
            obl.x = *(uint32_t*)&gl0; obl.y = *(uint32_t*)&gl1;
            *(uint2*)&Bhi[row * HPB + seg] = obh;
            *(uint2*)&Blo[row * HPB + seg] = obl;
        }
        __syncthreads();

        uint32_t ahb = smem_u32(&Ahi[aRow * HPB + aKof]);
        uint32_t alb = smem_u32(&Alo[aRow * HPB + aKof]);
        uint32_t bhb = smem_u32(&Bhi[bCol * HPB + bKof]);
        uint32_t blb = smem_u32(&Blo[bCol * HPB + bKof]);

#pragma unroll
        for (int kk = 0; kk < 32; kk += 16) {
            uint32_t afh[4][4], afl[4][4];
            uint32_t bfh[8][2], bfl[8][2];
#pragma unroll
            for (int mi = 0; mi < 4; mi++) {
                ldsm_x4(afh[mi][0], afh[mi][1], afh[mi][2], afh[mi][3],
                        ahb + (kk + mi * 16 * HPB) * 2);
                ldsm_x4(afl[mi][0], afl[mi][1], afl[mi][2], afl[mi][3],
                        alb + (kk + mi * 16 * HPB) * 2);
            }
#pragma unroll
            for (int np = 0; np < 4; np++) {
                ldsm_x4(bfh[2 * np][0], bfh[2 * np][1], bfh[2 * np + 1][0],
                        bfh[2 * np + 1][1], bhb + (kk + np * 16 * HPB) * 2);
                ldsm_x4(bfl[2 * np][0], bfl[2 * np][1], bfl[2 * np + 1][0],
                        bfl[2 * np + 1][1], blb + (kk + np * 16 * HPB) * 2);
            }
#define MMA_H(Aop, Bop)                                                               \
    asm volatile(                                                                     \
        "mma.sync.aligned.m16n8k16.row.col.f32.f16.f16.f32 "                          \
        "{%0,%1,%2,%3}, {%4,%5,%6,%7}, {%8,%9}, {%0,%1,%2,%3};\n"                     \
        : "+f"(acc[mi][ni][0]), "+f"(acc[mi][ni][1]),                                 \
          "+f"(acc[mi][ni][2]), "+f"(acc[mi][ni][3])                                  \
        : "r"(Aop[mi][0]), "r"(Aop[mi][1]), "r"(Aop[mi][2]), "r"(Aop[mi][3]),         \
          "r"(Bop[ni][0]), "r"(Bop[ni][1]))
#pragma unroll
            for (int mi = 0; mi < 4; mi++)
#pragma unroll
                for (int ni = 0; ni < 8; ni++) {
                    MMA_H(afh, bfh);
                    MMA_H(afh, bfl);
                    MMA_H(afl, bfh);
                }
#undef MMA_H
        }
    }

#pragma unroll
    for (int mi = 0; mi < 4; mi++) {
#pragma unroll
        for (int ni = 0; ni < 8; ni++) {
            int r = m0 + wm + mi * 16 + lq;
            int c = wn + ni * 8 + lr * 2;
            float2 bb = *(const float2*)(bias + c);
            float2 o0, o1;
            o0.x = fmaxf(acc[mi][ni][0] + bb.x, 0.f);
            o0.y = fmaxf(acc[mi][ni][1] + bb.y, 0.f);
            o1.x = fmaxf(acc[mi][ni][2] + bb.x, 0.f);
            o1.y = fmaxf(acc[mi][ni][3] + bb.y, 0.f);
            if (r < M) {
                *(float2*)(C + (size_t)r * NH + c) = o0;
                __half2 h = __floats2half2_rn(o0.x, o0.y);
                *(__half2*)(Ch + (size_t)r * NH + c) = h;
            }
            if (r + 8 < M) {
                *(float2*)(C + (size_t)(r + 8) * NH + c) = o1;
                __half2 h = __floats2half2_rn(o1.x, o1.y);
                *(__half2*)(Ch + (size_t)(r + 8) * NH + c) = h;
            }
        }
    }
}

// ---------------- 3xTF32 GEMM (Enode/Erel precompute only) ------------------
#define CPW 36

__global__ __launch_bounds__(256) void gemm128_3xtf32(
    const float* __restrict__ A,
    const float* __restrict__ B, const float* __restrict__ bias,
    float* __restrict__ C, int M)
{
    __shared__ float As[128 * CPW];
    __shared__ float Bs[128 * CPW];

    int tid = threadIdx.x;
    int m0 = blockIdx.x * 128;
    int warp = tid >> 5, lane = tid & 31;
    int wm = (warp & 1) * 64;
    int wn = (warp >> 1) * 32;
    int lq = lane >> 2;
    int lr = lane & 3;

    float acc[4][4][4];
#pragma unroll
    for (int i = 0; i < 4; i++)
#pragma unroll
        for (int j = 0; j < 4; j++)
#pragma unroll
            for (int r = 0; r < 4; r++) acc[i][j][r] = 0.f;

    for (int k0 = 0; k0 < NH; k0 += 32) {
        __syncthreads();
#pragma unroll
        for (int t = tid; t < 1024; t += 256) {
            int row = t >> 3, seg = (t & 7) * 4;
            int gm = m0 + row;
            float4 v = {0, 0, 0, 0};
            if (gm < M) v = *(const float4*)(A + (size_t)gm * NH + k0 + seg);
            *(float4*)&As[row * CPW + seg] = v;
            *(float4*)&Bs[row * CPW + seg] = *(const float4*)(B + (size_t)row * NH + k0 + seg);
        }
        __syncthreads();

#pragma unroll
        for (int kk = 0; kk < 32; kk += 8) {
            uint32_t ah[4][4], al[4][4];
            uint32_t bh[4][2], bl[4][2];
#pragma unroll
            for (int mi = 0; mi < 4; mi++) {
                int base = (wm + mi * 16 + lq) * CPW + kk + lr;
                split_tf32(As[base],               ah[mi][0], al[mi][0]);
                split_tf32(As[base + 8 * CPW],     ah[mi][1], al[mi][1]);
                split_tf32(As[base + 4],           ah[mi][2], al[mi][2]);
                split_tf32(As[base + 8 * CPW + 4], ah[mi][3], al[mi][3]);
            }
#pragma unroll
            for (int ni = 0; ni < 4; ni++) {
                int base = (wn + ni * 8 + lq) * CPW + kk + lr;
                split_tf32(Bs[base],     bh[ni][0], bl[ni][0]);
                split_tf32(Bs[base + 4], bh[ni][1], bl[ni][1]);
            }
#define MMA_TF32(Aop, Bop)                                                            \
    asm volatile(                                                                     \
        "mma.sync.aligned.m16n8k8.row.col.f32.tf32.tf32.f32 "                         \
        "{%0,%1,%2,%3}, {%4,%5,%6,%7}, {%8,%9}, {%0,%1,%2,%3};\n"                     \
        : "+f"(acc[mi][ni][0]), "+f"(acc[mi][ni][1]),                                 \
          "+f"(acc[mi][ni][2]), "+f"(acc[mi][ni][3])                                  \
        : "r"(Aop[mi][0]), "r"(Aop[mi][1]), "r"(Aop[mi][2]), "r"(Aop[mi][3]),         \
          "r"(Bop[ni][0]), "r"(Bop[ni][1]))
#pragma unroll
            for (int mi = 0; mi < 4; mi++)
#pragma unroll
                for (int ni = 0; ni < 4; ni++) {
                    MMA_TF32(ah, bh);
                    MMA_TF32(ah, bl);
                    MMA_TF32(al, bh);
                }
#undef MMA_TF32
        }
    }

#pragma unroll
    for (int mi = 0; mi < 4; mi++) {
#pragma unroll
        for (int ni = 0; ni < 4; ni++) {
            int r = m0 + wm + mi * 16 + lq;
            int c = wn + ni * 8 + lr * 2;
            float2 bb = *(const float2*)(bias + c);
            float2 o0, o1;
            o0.x = acc[mi][ni][0] + bb.x; o0.y = acc[mi][ni][1] + bb.y;
            o1.x = acc[mi][ni][2] + bb.x; o1.y = acc[mi][ni][3] + bb.y;
            if (r < M)     *(float2*)(C + (size_t)r * NH + c) = o0;
            if (r + 8 < M) *(float2*)(C + (size_t)(r + 8) * NH + c) = o1;
        }
    }
}

// ---------------- small kernels ----------------
__global__ void k_zero_int(int* __restrict__ p, int n) {
    int i = blockIdx.x * blockDim.x + threadIdx.x;
    if (i < n) p[i] = 0;
}
__global__ void k_zero_float(float* __restrict__ p, int n) {
    int i = blockIdx.x * blockDim.x + threadIdx.x;
    if (i < n) p[i] = 0.f;
}

__global__ void k_hist(const int* __restrict__ keys, int* __restrict__ cnt, int n) {
    int i = blockIdx.x * blockDim.x + threadIdx.x;
    if (i < n) atomicAdd(&cnt[keys[i]], 1);
}

__global__ void k_hist_batch(const int* __restrict__ batch, int* __restrict__ bcnt) {
    __shared__ int h[NBATCH];
    if (threadIdx.x < NBATCH) h[threadIdx.x] = 0;
    __syncthreads();
    int i = blockIdx.x * blockDim.x + threadIdx.x;
    if (i < NNODES) atomicAdd(&h[batch[i]], 1);
    __syncthreads();
    if (threadIdx.x < NBATCH) atomicAdd(&bcnt[threadIdx.x], h[threadIdx.x]);
}

__global__ void k_scan_block(const int* __restrict__ in, int* __restrict__ outEx,
                             int* __restrict__ part, int n) {
    __shared__ int s[1024];
    int t = threadIdx.x;
    int i = blockIdx.x * 1024 + t;
    int v = (i < n) ? in[i] : 0;
    s[t] = v;
    __syncthreads();
    for (int off = 1; off < 1024; off <<= 1) {
        int y = (t >= off) ? s[t - off] : 0;
        __syncthreads();
        s[t] += y;
        __syncthreads();
    }
    if (i < n) outEx[i] = s[t] - v;
    if (t == 1023) part[blockIdx.x] = s[1023];
}

__global__ void k_scan_part(int* __restrict__ part, int nb, int* __restrict__ rowstart) {
    if (threadIdx.x == 0 && blockIdx.x == 0) {
        int acc = 0;
        for (int i = 0; i < nb; i++) { int v = part[i]; part[i] = acc; acc += v; }
        rowstart[NNODES] = NEDGES;
    }
}

__global__ void k_scan_add(int* __restrict__ rowstart, const int* __restrict__ part,
                           int* __restrict__ cursor, int n) {
    int i = blockIdx.x * 1024 + threadIdx.x;
    if (i < n) {
        int v = rowstart[i] + part[blockIdx.x];
        rowstart[i] = v;
        cursor[i] = v;
    }
}

__global__ void k_scatter(const int* __restrict__ dst, int* __restrict__ cursor,
                          int* __restrict__ elist, int n) {
    int e = blockIdx.x * blockDim.x + threadIdx.x;
    if (e < n) {
        int d = dst[e];
        int p = atomicAdd(&cursor[d], 1);
        elist[p] = e;
    }
}

__global__ void k_eperm(const int* __restrict__ elist, const int* __restrict__ srcArr,
                        const int* __restrict__ ridArr, const int* __restrict__ nodeIds,
                        const int* __restrict__ batchArr,
                        int* __restrict__ esrc, int* __restrict__ erid,
                        int* __restrict__ eaidx, int n) {
    int i = blockIdx.x * blockDim.x + threadIdx.x;
    if (i < n) {
        int e = elist[i];
        int s = srcArr[e];
        esrc[i] = s;
        erid[i] = ridArr[e];
        eaidx[i] = batchArr[s] * NVOC + nodeIds[s];
    }
}

__global__ void k_bscan(const int* __restrict__ bcnt, int* __restrict__ bstart) {
    if (threadIdx.x == 0 && blockIdx.x == 0) {
        int acc = 0;
        for (int b = 0; b < NBATCH; b++) { bstart[b] = acc; acc += bcnt[b]; }
        bstart[NBATCH] = acc;
    }
}

__global__ void k_wrel(const float* __restrict__ Erel, const float* __restrict__ wr_w,
                       const float* __restrict__ wr_b, float* __restrict__ wrel) {
    int w = (blockIdx.x * blockDim.x + threadIdx.x) >> 5;
    int lane = threadIdx.x & 31;
    if (w >= NL * NREL) return;
    int l = w / NREL, r = w % NREL;
    float acc = 0.f;
#pragma unroll
    for (int h = lane; h < NH; h += 32) acc += Erel[r * NH + h] * wr_w[l * NH + h];
#pragma unroll
    for (int o = 16; o; o >>= 1) acc += __shfl_down_sync(0xffffffffu, acc, o);
    if (lane == 0) wrel[w] = acc + wr_b[l];
}

__global__ void k_gather(const float* __restrict__ Enode, const int* __restrict__ node_ids,
                         float* __restrict__ x, __half* __restrict__ xh) {
    int t = blockIdx.x * blockDim.x + threadIdx.x;
    if (t >= NNODES * 32) return;
    int i = t >> 5, q = t & 31;
    int nid = node_ids[i];
    float4 v = *(const float4*)(Enode + (size_t)nid * NH + q * 4);
    *(float4*)(x + (size_t)i * NH + q * 4) = v;
    __half2 h0 = __floats2half2_rn(v.x, v.y);
    __half2 h1 = __floats2half2_rn(v.z, v.w);
    uint2 raw;
    raw.x = *(uint32_t*)&h0; raw.y = *(uint32_t*)&h1;
    *(uint2*)(xh + (size_t)i * NH + q * 4) = raw;
}

__global__ void k_beta(const float* __restrict__ vn, const float* __restrict__ beta_w,
                       const float* __restrict__ beta_b, float* __restrict__ betaOut) {
    int w = (blockIdx.x * blockDim.x + threadIdx.x) >> 5;
    int lane = threadIdx.x & 31;
    if (w >= NL * NBATCH * NV) return;
    int l = w / (NBATCH * NV);
    int rem = w % (NBATCH * NV);
    int b = rem / NV, v = rem % NV;
    const float* row = vn + ((size_t)b * NV + v) * NVOC;
    const float* bw = beta_w + l * NVOC;
    float acc = 0.f;
    for (int n = lane; n < NVOC; n += 32) acc += row[n] * bw[n];
#pragma unroll
    for (int o = 16; o; o >>= 1) acc += __shfl_down_sync(0xffffffffu, acc, o);
    if (lane == 0)
        betaOut[w] = tanhf(acc + beta_b[l]) * expf(0.03f * (float)(NV - v));
}

__global__ void k_attn(const float* __restrict__ Z, const float* __restrict__ betaL,
                       float* __restrict__ attnL) {
    int m = blockIdx.x * blockDim.x + threadIdx.x;
    int b = blockIdx.y;
    if (m >= NVOC) return;
    float z[NV];
    float mx = -1e30f;
#pragma unroll
    for (int v = 0; v < NV; v++) {
        z[v] = Z[((size_t)(b * NV + v)) * NVOC + m];
        mx = fmaxf(mx, z[v]);
    }
    float s = 0.f, num = 0.f;
#pragma unroll
    for (int v = 0; v < NV; v++) {
        float e = expf(z[v] - mx);
        s += e;
        num += e * betaL[b * NV + v];
    }
    attnL[(size_t)b * NVOC + m] = num / s;
}

__global__ void k_aggregate(const __half* __restrict__ xh, const float* __restrict__ Erel,
                            const float* __restrict__ attnL, const float* __restrict__ wrelL,
                            const int* __restrict__ esrc, const int* __restrict__ erid,
                            const int* __restrict__ eaidx, const int* __restrict__ rowstart,
                            float* __restrict__ agg) {
    int warp = (blockIdx.x * blockDim.x + threadIdx.x) >> 5;
    int lane = threadIdx.x & 31;
    if (warp >= NNODES) return;
    int s0 = rowstart[warp], s1 = rowstart[warp + 1];
    float4 acc = {0.f, 0.f, 0.f, 0.f};
    for (int idx = s0; idx < s1; idx++) {
        int s = esrc[idx];
        int r = erid[idx];
        float ea = attnL[eaidx[idx]];
        float w = wrelL[r];
        uint2 raw = *(const uint2*)(xh + (size_t)s * NH + lane * 4);
        __half2 h0 = *(__half2*)&raw.x;
        __half2 h1 = *(__half2*)&raw.y;
        float2 f0 = __half22float2(h0);
        float2 f1 = __half22float2(h1);
        float4 ev = *(const float4*)(Erel + (size_t)r * NH + lane * 4);
        acc.x += fmaxf(fmaf(f0.x, ea, w * ev.x), 0.f);
        acc.y += fmaxf(fmaf(f0.y, ea, w * ev.y), 0.f);
        acc.z += fmaxf(fmaf(f1.x, ea, w * ev.z), 0.f);
        acc.w += fmaxf(fmaf(f1.y, ea, w * ev.w), 0.f);
    }
    *(float4*)(agg + (size_t)warp * NH + lane * 4) = acc;
}

__global__ void k_pool_partial(const float* __restrict__ x, const int* __restrict__ bstart,
                               float* __restrict__ xg) {
    int b = blockIdx.y, chunk = blockIdx.x, h = threadIdx.x;
    int s0 = bstart[b], s1 = bstart[b + 1];
    int len = s1 - s0;
    int r0 = s0 + (int)((long long)len * chunk / 8);
    int r1 = s0 + (int)((long long)len * (chunk + 1) / 8);
    float acc = 0.f;
    for (int i = r0; i < r1; i++) acc += x[(size_t)i * NH + h];
    atomicAdd(&xg[b * NH + h], acc);
}

__global__ void k_pool_finish(float* __restrict__ xg, const int* __restrict__ bcnt) {
    int b = blockIdx.x, h = threadIdx.x;
    float c = (float)bcnt[b];
    xg[b * NH + h] /= fmaxf(c, 1.f);
}

__global__ void k_ehrsum(const float* __restrict__ ehr, float* __restrict__ den) {
    int b = blockIdx.x, t = threadIdx.x;
    __shared__ float s[256];
    float acc = 0.f;
    for (int n = t; n < NVOC; n += 256) acc += ehr[(size_t)b * NVOC + n];
    s[t] = acc;
    __syncthreads();
    for (int o = 128; o; o >>= 1) {
        if (t < o) s[t] += s[t + o];
        __syncthreads();
    }
    if (t == 0) den[b] = s[0];
}

__global__ void k_xnode_partial(const float* __restrict__ ehr,
                                const float* __restrict__ node_emb,
                                float* __restrict__ xacc) {
    int b = blockIdx.y, slice = blockIdx.x, h = threadIdx.x;
    int n0 = slice * (NVOC / 16), n1 = n0 + (NVOC / 16);
    float acc = 0.f;
    for (int n = n0; n < n1; n++)
        acc += ehr[(size_t)b * NVOC + n] * node_emb[(size_t)n * NH + h];
    atomicAdd(&xacc[b * NH + h], acc);
}

__global__ void k_xnode_finish(const float* __restrict__ xacc, const float* __restrict__ den,
                               const float* __restrict__ lin_w, const float* __restrict__ lin_b,
                               float* __restrict__ xnode) {
    int b = blockIdx.x, h = threadIdx.x;
    __shared__ float t[NH];
    t[h] = xacc[b * NH + h] / den[b];
    __syncthreads();
    float s = 0.f;
#pragma unroll 8
    for (int hh = 0; hh < NH; hh++) s += t[hh] * lin_w[h * NH + hh];
    xnode[b * NH + h] = s + lin_b[h];
}

__global__ void k_final(const float* __restrict__ xg, const float* __restrict__ xn,
                        const float* __restrict__ mlp_w, const float* __restrict__ mlp_b,
                        float* __restrict__ out) {
    int b = blockIdx.x, t = threadIdx.x;
    __shared__ float s[2 * NH];
    s[t] = xg[b * NH + t];
    s[NH + t] = xn[b * NH + t];
    __syncthreads();
    if (t < NOUT) {
        float acc = mlp_b[t];
        const float* w = mlp_w + t * (2 * NH);
#pragma unroll 8
        for (int k = 0; k < 2 * NH; k++) acc += s[k] * w[k];
        out[b * NOUT + t] = acc;
    }
}

// ---------------- launch ----------------
extern "C" void kernel_launch(void* const* d_in, const int* in_sizes, int n_in,
                              void* d_out, int out_size) {
    const float* node_emb = (const float*)d_in[0];
    const float* rel_emb  = (const float*)d_in[1];
    const float* lin_w    = (const float*)d_in[2];
    const float* lin_b    = (const float*)d_in[3];
    const float* alpha_w  = (const float*)d_in[4];
    const float* alpha_b  = (const float*)d_in[5];
    const float* beta_w   = (const float*)d_in[6];
    const float* beta_b   = (const float*)d_in[7];
    const float* wr_w     = (const float*)d_in[8];
    const float* wr_b     = (const float*)d_in[9];
    const float* conv_w   = (const float*)d_in[10];
    const float* conv_b   = (const float*)d_in[11];
    const float* mlp_w    = (const float*)d_in[12];
    const float* mlp_b    = (const float*)d_in[13];
    const float* visit    = (const float*)d_in[14];
    const float* ehr      = (const float*)d_in[15];
    const int* node_ids   = (const int*)d_in[16];
    const int* rel_ids    = (const int*)d_in[17];
    const int* eidx       = (const int*)d_in[18];
    const int* batch      = (const int*)d_in[19];
    float* out = (float*)d_out;

    const int* srcArr = eidx;
    const int* dstArr = eidx + NEDGES;

    float *Zp, *Enodep, *Erelp, *wrelp, *attnp, *betap, *xp, *x2p, *aggp;
    float *xgp, *xaccp, *denp, *xnodep;
    __half *xhp, *xh2p, *vhp, *whp;
    int *degp, *rowstartp, *cursorp, *elistp, *esrcp, *eridp, *eaidxp;
    int *partp, *bcntp, *bstartp;
    cudaGetSymbolAddress((void**)&Zp, g_Z);
    cudaGetSymbolAddress((void**)&vhp, g_vh);
    cudaGetSymbolAddress((void**)&whp, g_wh);
    cudaGetSymbolAddress((void**)&Enodep, g_Enode);
    cudaGetSymbolAddress((void**)&Erelp, g_Erel);
    cudaGetSymbolAddress((void**)&wrelp, g_wrel);
    cudaGetSymbolAddress((void**)&attnp, g_attn);
    cudaGetSymbolAddress((void**)&betap, g_beta);
    cudaGetSymbolAddress((void**)&xp, g_x);
    cudaGetSymbolAddress((void**)&x2p, g_x2);
    cudaGetSymbolAddress((void**)&xhp, g_xh);
    cudaGetSymbolAddress((void**)&xh2p, g_xh2);
    cudaGetSymbolAddress((void**)&aggp, g_agg);
    cudaGetSymbolAddress((void**)&xgp, g_xg);
    cudaGetSymbolAddress((void**)&xaccp, g_xacc);
    cudaGetSymbolAddress((void**)&denp, g_den);
    cudaGetSymbolAddress((void**)&xnodep, g_xnode);
    cudaGetSymbolAddress((void**)&degp, g_deg);
    cudaGetSymbolAddress((void**)&rowstartp, g_rowstart);
    cudaGetSymbolAddress((void**)&cursorp, g_cursor);
    cudaGetSymbolAddress((void**)&elistp, g_elist);
    cudaGetSymbolAddress((void**)&esrcp, g_esrc);
    cudaGetSymbolAddress((void**)&eridp, g_erid);
    cudaGetSymbolAddress((void**)&eaidxp, g_eaidx);
    cudaGetSymbolAddress((void**)&partp, g_part);
    cudaGetSymbolAddress((void**)&bcntp, g_bcnt);
    cudaGetSymbolAddress((void**)&bstartp, g_bstart);

    static cudaStream_t sMain = nullptr, sSide = nullptr;
    static cudaEvent_t evFork = nullptr, evJoin = nullptr;
    static cudaEvent_t evZ[NL] = {nullptr, nullptr, nullptr};
    if (sMain == nullptr) {
        int prLo, prHi;
        cudaDeviceGetStreamPriorityRange(&prLo, &prHi);
        cudaStreamCreateWithPriority(&sMain, cudaStreamNonBlocking, prHi);
        cudaStreamCreateWithPriority(&sSide, cudaStreamNonBlocking, prLo);
        cudaEventCreateWithFlags(&evFork, cudaEventDisableTiming);
        cudaEventCreateWithFlags(&evJoin, cudaEventDisableTiming);
        for (int l = 0; l < NL; l++)
            cudaEventCreateWithFlags(&evZ[l], cudaEventDisableTiming);
    }

    const int SCAN_BLOCKS = (NNODES + 1023) / 1024;
    const size_t ZL = (size_t)NBATCH * NV * NVOC;
    const size_t WL = (size_t)NVOC * NVOC;

    // ---- fork ----
    cudaEventRecord(evFork, 0);
    cudaStreamWaitEvent(sMain, evFork, 0);
    cudaStreamWaitEvent(sSide, evFork, 0);

    // sMain: convert + alpha, W_{l+1} conversion interleaved behind alpha_l
    k_f2h<<<(unsigned)((ZL / 8 + 255) / 256), 256, 0, sMain>>>(visit, vhp, ZL);
    k_f2h<<<(unsigned)((WL / 8 + 255) / 256), 256, 0, sMain>>>(alpha_w, whp, WL);
    for (int l = 0; l < NL; l++) {
        alpha_gemm_fp16<<<dim3((NVOC + TBN - 1) / TBN, (NBATCH * NV) / TBM), 128, 0,
                          sMain>>>(
            vhp, whp + (size_t)l * WL, alpha_b + (size_t)l * NVOC, Zp + l * ZL);
        cudaEventRecord(evZ[l], sMain);
        if (l + 1 < NL)
            k_f2h<<<(unsigned)((WL / 8 + 255) / 256), 256, 0, sMain>>>(
                alpha_w + (size_t)(l + 1) * WL, whp + (size_t)(l + 1) * WL, WL);
    }

    // sSide: alpha-independent pre-work
    gemm128_3xtf32<<<(NVOC + 127) / 128, 256, 0, sSide>>>(
        node_emb, lin_w, lin_b, Enodep, NVOC);
    gemm128_3xtf32<<<(NREL + 127) / 128, 256, 0, sSide>>>(
        rel_emb, lin_w, lin_b, Erelp, NREL);
    k_wrel<<<(NL * NREL * 32 + 255) / 256, 256, 0, sSide>>>(Erelp, wr_w, wr_b, wrelp);
    k_gather<<<(NNODES * 32 + 255) / 256, 256, 0, sSide>>>(Enodep, node_ids, xp, xhp);
    k_beta<<<(NL * NBATCH * NV * 32 + 255) / 256, 256, 0, sSide>>>(
        visit, beta_w, beta_b, betap);
    k_zero_int<<<(NNODES + 255) / 256, 256, 0, sSide>>>(degp, NNODES);
    k_zero_int<<<1, 64, 0, sSide>>>(bcntp, NBATCH);
    k_hist<<<(NEDGES + 255) / 256, 256, 0, sSide>>>(dstArr, degp, NEDGES);
    k_hist_batch<<<(NNODES + 255) / 256, 256, 0, sSide>>>(batch, bcntp);
    k_scan_block<<<SCAN_BLOCKS, 1024, 0, sSide>>>(degp, rowstartp, partp, NNODES);
    k_scan_part<<<1, 1, 0, sSide>>>(partp, SCAN_BLOCKS, rowstartp);
    k_scan_add<<<SCAN_BLOCKS, 1024, 0, sSide>>>(rowstartp, partp, cursorp, NNODES);
    k_scatter<<<(NEDGES + 255) / 256, 256, 0, sSide>>>(dstArr, cursorp, elistp, NEDGES);
    k_eperm<<<(NEDGES + 255) / 256, 256, 0, sSide>>>(
        elistp, srcArr, rel_ids, node_ids, batch, esrcp, eridp, eaidxp, NEDGES);
    k_bscan<<<1, 1, 0, sSide>>>(bcntp, bstartp);
    k_zero_float<<<(NBATCH * NH + 255) / 256, 256, 0, sSide>>>(xgp, NBATCH * NH);
    k_zero_float<<<(NBATCH * NH + 255) / 256, 256, 0, sSide>>>(xaccp, NBATCH * NH);
    k_ehrsum<<<NBATCH, 256, 0, sSide>>>(ehr, denp);
    k_xnode_partial<<<dim3(16, NBATCH), NH, 0, sSide>>>(ehr, node_emb, xaccp);
    k_xnode_finish<<<NBATCH, NH, 0, sSide>>>(xaccp, denp, lin_w, lin_b, xnodep);

    // sSide: per-layer pipeline
    float* xcur = xp;
    float* xalt = x2p;
    __half* xhcur = xhp;
    __half* xhalt = xh2p;
    for (int l = 0; l < NL; l++) {
        cudaStreamWaitEvent(sSide, evZ[l], 0);
        k_attn<<<dim3((NVOC + 255) / 256, NBATCH), 256, 0, sSide>>>(
            Zp + l * ZL, betap + l * NBATCH * NV, attnp + (size_t)l * NBATCH * NVOC);
        k_aggregate<<<(NNODES * 32 + 255) / 256, 256, 0, sSide>>>(
            xhcur, Erelp, attnp + (size_t)l * NBATCH * NVOC, wrelp + l * NREL,
            esrcp, eridp, eaidxp, rowstartp, aggp);
        conv_fp16split<<<(NNODES + 127) / 128, 128, 0, sSide>>>(
            aggp, xcur, conv_w + (size_t)l * NH * NH, conv_b + (size_t)l * NH,
            xalt, xhalt, NNODES);
        float* tf = xcur; xcur = xalt; xalt = tf;
        __half* th = xhcur; xhcur = xhalt; xhalt = th;
    }

    // sSide: pooling
    k_pool_partial<<<dim3(8, NBATCH), NH, 0, sSide>>>(xcur, bstartp, xgp);
    k_pool_finish<<<NBATCH, NH, 0, sSide>>>(xgp, bcntp);

    // ---- join ----
    cudaEventRecord(evJoin, sSide);
    cudaStreamWaitEvent(0, evJoin, 0);

    k_final<<<NBATCH, NH>>>(xgp, xnodep, mlp_w, mlp_b, out);
}